// round 4
// baseline (speedup 1.0000x reference)
#include <cuda_runtime.h>
#include <cuda_bf16.h>
#include <math.h>

#define T_SEQ 4096
#define DM    2048
#define NH    8
#define NKV   4
#define HD    256
#define WIN   1024

// Scratch (static __device__ arrays — allocation-free per harness rules)
__device__ float g_q[T_SEQ * DM];          // 32 MB
__device__ float g_k[T_SEQ * NKV * HD];    // 16 MB
__device__ float g_v[T_SEQ * NKV * HD];    // 16 MB
__device__ float g_y[T_SEQ * DM];          // 32 MB

// ---------------------------------------------------------------------------
// SGEMM: C[M,N] = A[M,K] @ B[N,K]^T   (A,B,C row-major; M%128==0, N%128==0, K%16==0)
// 128x128 block tile, BK=16, 256 threads, 8x8 per thread (split 4+4 for
// conflict-free float4 smem reads).
// ---------------------------------------------------------------------------
__global__ __launch_bounds__(256) void sgemm_nt(
    const float* __restrict__ A, const float* __restrict__ B,
    float* __restrict__ C, int M, int N, int K)
{
    __shared__ float As[16][132];
    __shared__ float Bs[16][132];
    const int tid  = threadIdx.x;
    const int brow = blockIdx.y * 128;
    const int bcol = blockIdx.x * 128;
    const int ty = tid >> 4, tx = tid & 15;

    float acc[8][8];
#pragma unroll
    for (int i = 0; i < 8; i++)
#pragma unroll
        for (int j = 0; j < 8; j++) acc[i][j] = 0.f;

    for (int k0 = 0; k0 < K; k0 += 16) {
        __syncthreads();  // protect previous tile's compute
#pragma unroll
        for (int ldi = 0; ldi < 2; ldi++) {
            int id  = tid + ldi * 256;
            int row = id >> 2;
            int c4  = (id & 3) << 2;
            float4 av = *(const float4*)(A + (size_t)(brow + row) * K + k0 + c4);
            As[c4 + 0][row] = av.x; As[c4 + 1][row] = av.y;
            As[c4 + 2][row] = av.z; As[c4 + 3][row] = av.w;
            float4 bv = *(const float4*)(B + (size_t)(bcol + row) * K + k0 + c4);
            Bs[c4 + 0][row] = bv.x; Bs[c4 + 1][row] = bv.y;
            Bs[c4 + 2][row] = bv.z; Bs[c4 + 3][row] = bv.w;
        }
        __syncthreads();
#pragma unroll
        for (int kk = 0; kk < 16; kk++) {
            float4 a0 = *(const float4*)&As[kk][ty * 4];
            float4 a1 = *(const float4*)&As[kk][64 + ty * 4];
            float4 b0 = *(const float4*)&Bs[kk][tx * 4];
            float4 b1 = *(const float4*)&Bs[kk][64 + tx * 4];
            float a[8] = {a0.x, a0.y, a0.z, a0.w, a1.x, a1.y, a1.z, a1.w};
            float b[8] = {b0.x, b0.y, b0.z, b0.w, b1.x, b1.y, b1.z, b1.w};
#pragma unroll
            for (int i = 0; i < 8; i++)
#pragma unroll
                for (int j = 0; j < 8; j++)
                    acc[i][j] = fmaf(a[i], b[j], acc[i][j]);
        }
    }

#pragma unroll
    for (int i = 0; i < 8; i++) {
        int row = brow + ((i < 4) ? (ty * 4 + i) : (64 + ty * 4 + i - 4));
#pragma unroll
        for (int jb = 0; jb < 2; jb++) {
            int col = bcol + ((jb == 0) ? (tx * 4) : (64 + tx * 4));
            float4 o;
            o.x = acc[i][jb * 4 + 0]; o.y = acc[i][jb * 4 + 1];
            o.z = acc[i][jb * 4 + 2]; o.w = acc[i][jb * 4 + 3];
            *(float4*)(C + (size_t)row * N + col) = o;
        }
    }
}

// ---------------------------------------------------------------------------
// Fused per-head RMSNorm + RoPE (in-place on g_q / g_k).
// Reference semantics: norm first, then rotary with
//   rot[2i] = -x[2i+1], rot[2i+1] = x[2i],  cos/sin index = d mod 128,
//   inv_freq[f] = 10000^(-f/128).
// grid = (T, 12): hi<8 -> q head hi, hi>=8 -> k head hi-8. 256 threads.
// ---------------------------------------------------------------------------
__global__ __launch_bounds__(256) void rmsnorm_rope_kernel(
    float* __restrict__ q, float* __restrict__ kbuf,
    const float* __restrict__ qw, const float* __restrict__ kw,
    const int* __restrict__ pos)
{
    const int t  = blockIdx.x;
    const int hi = blockIdx.y;
    const int d  = threadIdx.x;

    float* row;
    const float* w;
    if (hi < NH) { row = q    + (size_t)t * DM + hi * HD;              w = qw; }
    else         { row = kbuf + (size_t)t * (NKV * HD) + (hi - NH) * HD; w = kw; }

    float v  = row[d];
    float ss = v * v;
#pragma unroll
    for (int o = 16; o; o >>= 1) ss += __shfl_xor_sync(0xffffffffu, ss, o);

    __shared__ float red[8];
    __shared__ float s_scale;
    __shared__ float sn[256];
    if ((d & 31) == 0) red[d >> 5] = ss;
    __syncthreads();
    if (d == 0) {
        float tot = 0.f;
#pragma unroll
        for (int i = 0; i < 8; i++) tot += red[i];
        s_scale = rsqrtf(tot * (1.0f / HD) + 1e-6f);
    }
    __syncthreads();

    float nrm = v * s_scale * w[d];
    sn[d] = nrm;
    __syncthreads();

    float rot = (d & 1) ? sn[d - 1] : -sn[d + 1];
    int   fi  = d & 127;
    float inv_freq = expf(-(float)fi * (logf(10000.0f) / 128.0f));
    float ang = (float)pos[t] * inv_freq;
    float sv, cv;
    sincosf(ang, &sv, &cv);
    row[d] = nrm * cv + rot * sv;
}

// ---------------------------------------------------------------------------
// Flash attention, fp32, sliding window 1024, causal.
// Block: 64 queries x 1 head. 256 threads (16x16). D=256.
// Smem: Qs[D][64] (transposed), Ks[D][64] (transposed), Vs[64][D],
//       Ps[64][68], row stats. Total 214784 B.
// ---------------------------------------------------------------------------
#define ATTN_SMEM_FLOATS (256*64 + 256*64 + 64*256 + 64*68 + 64*3)
#define ATTN_SMEM_BYTES  (ATTN_SMEM_FLOATS * 4)

__global__ __launch_bounds__(256) void attn_kernel(
    const float* __restrict__ q, const float* __restrict__ k,
    const float* __restrict__ v, float* __restrict__ y)
{
    extern __shared__ float smf[];
    float* Qs   = smf;                 // [256][64]
    float* Ks   = Qs + 256 * 64;       // [256][64]
    float* Vs   = Ks + 256 * 64;       // [64][256]
    float* Ps   = Vs + 64 * 256;       // [64][68]
    float* m_s  = Ps + 64 * 68;        // [64]
    float* l_s  = m_s + 64;            // [64]
    float* sc_s = l_s + 64;            // [64]

    const int tid = threadIdx.x;
    const int qb  = blockIdx.x;
    const int h   = blockIdx.y;
    const int kvh = h >> 1;            // repeat factor 2: heads (0,1)->kv0 etc.
    const int ty  = tid >> 4, tx = tid & 15;

    if (tid < 64) { m_s[tid] = -INFINITY; l_s[tid] = 0.f; }

    // Load Q tile transposed: Qs[d][r]
    for (int idx = tid; idx < 64 * 64; idx += 256) {
        int r = idx & 63, d4 = idx >> 6;
        float4 qv = *(const float4*)(q + (size_t)(qb * 64 + r) * DM + h * HD + d4 * 4);
        Qs[(d4 * 4 + 0) * 64 + r] = qv.x;
        Qs[(d4 * 4 + 1) * 64 + r] = qv.y;
        Qs[(d4 * 4 + 2) * 64 + r] = qv.z;
        Qs[(d4 * 4 + 3) * 64 + r] = qv.w;
    }

    float acc[4][16];
#pragma unroll
    for (int i = 0; i < 4; i++)
#pragma unroll
        for (int c = 0; c < 16; c++) acc[i][c] = 0.f;

    int s0 = qb * 64 - (WIN - 1);
    if (s0 < 0) s0 = 0;
    const int kt0 = s0 >> 6;

    for (int kt = kt0; kt <= qb; kt++) {
        __syncthreads();  // previous PV done (and Q load on first iter)

        // K tile transposed: Ks[d][r]
        for (int idx = tid; idx < 64 * 64; idx += 256) {
            int r = idx & 63, d4 = idx >> 6;
            float4 kv4 = *(const float4*)(k + (size_t)(kt * 64 + r) * (NKV * HD) + kvh * HD + d4 * 4);
            Ks[(d4 * 4 + 0) * 64 + r] = kv4.x;
            Ks[(d4 * 4 + 1) * 64 + r] = kv4.y;
            Ks[(d4 * 4 + 2) * 64 + r] = kv4.z;
            Ks[(d4 * 4 + 3) * 64 + r] = kv4.w;
        }
        // V tile row-major: Vs[r][d]
        for (int idx = tid; idx < 64 * 64; idx += 256) {
            int d4 = idx & 63, r = idx >> 6;
            float4 vv = *(const float4*)(v + (size_t)(kt * 64 + r) * (NKV * HD) + kvh * HD + d4 * 4);
            *(float4*)&Vs[r * 256 + d4 * 4] = vv;
        }
        __syncthreads();

        // S = Q @ K^T  (4x4 per thread)
        float s[4][4];
#pragma unroll
        for (int i = 0; i < 4; i++)
#pragma unroll
            for (int j = 0; j < 4; j++) s[i][j] = 0.f;
#pragma unroll 4
        for (int d = 0; d < 256; d++) {
            float4 qv = *(const float4*)&Qs[d * 64 + ty * 4];
            float4 kv = *(const float4*)&Ks[d * 64 + tx * 4];
            s[0][0] = fmaf(qv.x, kv.x, s[0][0]); s[0][1] = fmaf(qv.x, kv.y, s[0][1]);
            s[0][2] = fmaf(qv.x, kv.z, s[0][2]); s[0][3] = fmaf(qv.x, kv.w, s[0][3]);
            s[1][0] = fmaf(qv.y, kv.x, s[1][0]); s[1][1] = fmaf(qv.y, kv.y, s[1][1]);
            s[1][2] = fmaf(qv.y, kv.z, s[1][2]); s[1][3] = fmaf(qv.y, kv.w, s[1][3]);
            s[2][0] = fmaf(qv.z, kv.x, s[2][0]); s[2][1] = fmaf(qv.z, kv.y, s[2][1]);
            s[2][2] = fmaf(qv.z, kv.z, s[2][2]); s[2][3] = fmaf(qv.z, kv.w, s[2][3]);
            s[3][0] = fmaf(qv.w, kv.x, s[3][0]); s[3][1] = fmaf(qv.w, kv.y, s[3][1]);
            s[3][2] = fmaf(qv.w, kv.z, s[3][2]); s[3][3] = fmaf(qv.w, kv.w, s[3][3]);
        }

        // Mask + online softmax update (rows of a group live in one warp half)
#pragma unroll
        for (int i = 0; i < 4; i++) {
            int   row = ty * 4 + i;
            int   qi  = qb * 64 + row;
            float rmax = -INFINITY;
#pragma unroll
            for (int j = 0; j < 4; j++) {
                int   kj = kt * 64 + tx * 4 + j;
                float sv = s[i][j] * 0.0625f;  // 1/sqrt(256)
                sv = (kj <= qi && kj > qi - WIN) ? sv : -INFINITY;
                s[i][j] = sv;
                rmax = fmaxf(rmax, sv);
            }
#pragma unroll
            for (int o = 8; o; o >>= 1)
                rmax = fmaxf(rmax, __shfl_xor_sync(0xffffffffu, rmax, o));
            float mold = m_s[row];
            float mn   = fmaxf(mold, rmax);
            float rsum = 0.f;
#pragma unroll
            for (int j = 0; j < 4; j++) {
                float p = (s[i][j] == -INFINITY) ? 0.f : __expf(s[i][j] - mn);
                s[i][j] = p;
                rsum += p;
            }
#pragma unroll
            for (int o = 8; o; o >>= 1)
                rsum += __shfl_xor_sync(0xffffffffu, rsum, o);
            if (tx == 0) {
                float corr = (mn == -INFINITY) ? 1.f
                           : ((mold == -INFINITY) ? 0.f : __expf(mold - mn));
                sc_s[row] = corr;
                m_s[row]  = mn;
                l_s[row]  = l_s[row] * corr + rsum;
            }
            *(float4*)&Ps[row * 68 + tx * 4] =
                make_float4(s[i][0], s[i][1], s[i][2], s[i][3]);
        }
        __syncthreads();

        // O = O*corr + P @ V   (4 rows x 16 cols per thread; cols tx*4 + c*64)
#pragma unroll
        for (int i = 0; i < 4; i++) {
            float corr = sc_s[ty * 4 + i];
#pragma unroll
            for (int c = 0; c < 16; c++) acc[i][c] *= corr;
        }
#pragma unroll 2
        for (int kk = 0; kk < 64; kk++) {
            float4 v0 = *(const float4*)&Vs[kk * 256 +   0 + tx * 4];
            float4 v1 = *(const float4*)&Vs[kk * 256 +  64 + tx * 4];
            float4 v2 = *(const float4*)&Vs[kk * 256 + 128 + tx * 4];
            float4 v3 = *(const float4*)&Vs[kk * 256 + 192 + tx * 4];
#pragma unroll
            for (int i = 0; i < 4; i++) {
                float p = Ps[(ty * 4 + i) * 68 + kk];
                acc[i][ 0] = fmaf(p, v0.x, acc[i][ 0]);
                acc[i][ 1] = fmaf(p, v0.y, acc[i][ 1]);
                acc[i][ 2] = fmaf(p, v0.z, acc[i][ 2]);
                acc[i][ 3] = fmaf(p, v0.w, acc[i][ 3]);
                acc[i][ 4] = fmaf(p, v1.x, acc[i][ 4]);
                acc[i][ 5] = fmaf(p, v1.y, acc[i][ 5]);
                acc[i][ 6] = fmaf(p, v1.z, acc[i][ 6]);
                acc[i][ 7] = fmaf(p, v1.w, acc[i][ 7]);
                acc[i][ 8] = fmaf(p, v2.x, acc[i][ 8]);
                acc[i][ 9] = fmaf(p, v2.y, acc[i][ 9]);
                acc[i][10] = fmaf(p, v2.z, acc[i][10]);
                acc[i][11] = fmaf(p, v2.w, acc[i][11]);
                acc[i][12] = fmaf(p, v3.x, acc[i][12]);
                acc[i][13] = fmaf(p, v3.y, acc[i][13]);
                acc[i][14] = fmaf(p, v3.z, acc[i][14]);
                acc[i][15] = fmaf(p, v3.w, acc[i][15]);
            }
        }
    }

    // Epilogue: divide by l, write y[t][h*256 + col]
#pragma unroll
    for (int i = 0; i < 4; i++) {
        int   row = ty * 4 + i;
        float inv = 1.f / l_s[row];
        float* yr = y + (size_t)(qb * 64 + row) * DM + h * HD;
#pragma unroll
        for (int c = 0; c < 4; c++) {
            float4 o = make_float4(acc[i][c * 4 + 0] * inv, acc[i][c * 4 + 1] * inv,
                                   acc[i][c * 4 + 2] * inv, acc[i][c * 4 + 3] * inv);
            *(float4*)&yr[c * 64 + tx * 4] = o;
        }
    }
}

// ---------------------------------------------------------------------------
extern "C" void kernel_launch(void* const* d_in, const int* in_sizes, int n_in,
                              void* d_out, int out_size)
{
    const float* x  = (const float*)d_in[0];
    const int*   pos= (const int*)  d_in[1];
    const float* Wq = (const float*)d_in[2];
    const float* Wk = (const float*)d_in[3];
    const float* Wv = (const float*)d_in[4];
    const float* Wo = (const float*)d_in[5];
    const float* qw = (const float*)d_in[6];
    const float* kw = (const float*)d_in[7];
    float* out = (float*)d_out;

    float *q_p, *k_p, *v_p, *y_p;
    cudaGetSymbolAddress((void**)&q_p, g_q);
    cudaGetSymbolAddress((void**)&k_p, g_k);
    cudaGetSymbolAddress((void**)&v_p, g_v);
    cudaGetSymbolAddress((void**)&y_p, g_y);

    // QKV projections
    sgemm_nt<<<dim3(DM / 128, T_SEQ / 128), 256>>>(x, Wq, q_p, T_SEQ, DM, DM);
    sgemm_nt<<<dim3((NKV * HD) / 128, T_SEQ / 128), 256>>>(x, Wk, k_p, T_SEQ, NKV * HD, DM);
    sgemm_nt<<<dim3((NKV * HD) / 128, T_SEQ / 128), 256>>>(x, Wv, v_p, T_SEQ, NKV * HD, DM);

    // RMSNorm + RoPE on q and k (12 head-rows per timestep)
    rmsnorm_rope_kernel<<<dim3(T_SEQ, NH + NKV), 256>>>(q_p, k_p, qw, kw, pos);

    // Flash attention (64-query tiles x 8 heads)
    cudaFuncSetAttribute(attn_kernel, cudaFuncAttributeMaxDynamicSharedMemorySize,
                         ATTN_SMEM_BYTES);
    attn_kernel<<<dim3(T_SEQ / 64, NH), 256, ATTN_SMEM_BYTES>>>(q_p, k_p, v_p, y_p);

    // Output projection (writes every element of d_out)
    sgemm_nt<<<dim3(DM / 128, T_SEQ / 128), 256>>>(y_p, Wo, out, T_SEQ, DM, DM);
}

// round 5
// speedup vs baseline: 1.7024x; 1.7024x over previous
#include <cuda_runtime.h>
#include <cuda_bf16.h>
#include <math.h>
#include <stdint.h>

#define T_SEQ 4096
#define DM    2048
#define NH    8
#define NKV   4
#define HD    256
#define WIN   1024

// Scratch (static __device__ arrays — allocation-free per harness rules)
__device__ float g_q[T_SEQ * DM];          // 32 MB
__device__ float g_k[T_SEQ * NKV * HD];    // 16 MB
__device__ float g_v[T_SEQ * NKV * HD];    // 16 MB
__device__ float g_y[T_SEQ * DM];          // 32 MB

__device__ __forceinline__ uint32_t f2tf32(float x) {
    uint32_t y;
    asm("cvt.rna.tf32.f32 %0, %1;" : "=r"(y) : "f"(x));
    return y;
}

// ---------------------------------------------------------------------------
// TF32 tensor-core GEMM: C[M,N] = A[M,K] @ B[N,K]^T  (row-major, fp32 in/out)
// 128x128 block tile, BK=32, 256 threads = 8 warps (4m x 2n), warp tile 32x64.
// mma.sync.aligned.m16n8k8.row.col.f32.tf32.tf32.f32, fp32 accumulate.
// Requires M%128==0, N%128==0, K%32==0.
// ---------------------------------------------------------------------------
__global__ __launch_bounds__(256, 2) void sgemm_tf32(
    const float* __restrict__ A, const float* __restrict__ B,
    float* __restrict__ C, int M, int N, int K)
{
    __shared__ uint32_t As[128][36];
    __shared__ uint32_t Bs[128][36];

    const int tid  = threadIdx.x;
    const int brow = blockIdx.y * 128;
    const int bcol = blockIdx.x * 128;
    const int warp = tid >> 5;
    const int lane = tid & 31;
    const int g    = lane >> 2;     // groupID 0..7
    const int tig  = lane & 3;      // thread-in-group 0..3
    const int warpM = (warp >> 1) * 32;
    const int warpN = (warp & 1) * 64;

    float acc[2][8][4];
#pragma unroll
    for (int mi = 0; mi < 2; mi++)
#pragma unroll
        for (int nj = 0; nj < 8; nj++)
#pragma unroll
            for (int c = 0; c < 4; c++) acc[mi][nj][c] = 0.f;

    for (int k0 = 0; k0 < K; k0 += 32) {
        __syncthreads();   // protect previous slab's fragment reads
        // Load 128x32 of A and B, convert to tf32, store to smem (pitch 36).
#pragma unroll
        for (int i = 0; i < 4; i++) {
            int id  = tid + i * 256;
            int row = id >> 3;
            int c4  = (id & 7) << 2;
            float4 av = *(const float4*)(A + (size_t)(brow + row) * K + k0 + c4);
            uint4 at;
            at.x = f2tf32(av.x); at.y = f2tf32(av.y);
            at.z = f2tf32(av.z); at.w = f2tf32(av.w);
            *(uint4*)&As[row][c4] = at;
            float4 bv = *(const float4*)(B + (size_t)(bcol + row) * K + k0 + c4);
            uint4 bt;
            bt.x = f2tf32(bv.x); bt.y = f2tf32(bv.y);
            bt.z = f2tf32(bv.z); bt.w = f2tf32(bv.w);
            *(uint4*)&Bs[row][c4] = bt;
        }
        __syncthreads();

#pragma unroll
        for (int ks = 0; ks < 32; ks += 8) {
            uint32_t af[2][4];
            uint32_t bf[8][2];
#pragma unroll
            for (int mi = 0; mi < 2; mi++) {
                int r = warpM + mi * 16 + g;
                af[mi][0] = As[r    ][ks + tig];
                af[mi][1] = As[r + 8][ks + tig];
                af[mi][2] = As[r    ][ks + tig + 4];
                af[mi][3] = As[r + 8][ks + tig + 4];
            }
#pragma unroll
            for (int nj = 0; nj < 8; nj++) {
                int c = warpN + nj * 8 + g;
                bf[nj][0] = Bs[c][ks + tig];
                bf[nj][1] = Bs[c][ks + tig + 4];
            }
#pragma unroll
            for (int mi = 0; mi < 2; mi++)
#pragma unroll
                for (int nj = 0; nj < 8; nj++) {
                    asm volatile(
                        "mma.sync.aligned.m16n8k8.row.col.f32.tf32.tf32.f32 "
                        "{%0,%1,%2,%3}, {%4,%5,%6,%7}, {%8,%9}, {%0,%1,%2,%3};"
                        : "+f"(acc[mi][nj][0]), "+f"(acc[mi][nj][1]),
                          "+f"(acc[mi][nj][2]), "+f"(acc[mi][nj][3])
                        : "r"(af[mi][0]), "r"(af[mi][1]),
                          "r"(af[mi][2]), "r"(af[mi][3]),
                          "r"(bf[nj][0]), "r"(bf[nj][1]));
                }
        }
    }

    // Epilogue: c0,c1 -> (row g, col 2*tig), c2,c3 -> (row g+8, col 2*tig)
#pragma unroll
    for (int mi = 0; mi < 2; mi++) {
        int row0 = brow + warpM + mi * 16 + g;
#pragma unroll
        for (int nj = 0; nj < 8; nj++) {
            int col = bcol + warpN + nj * 8 + tig * 2;
            float2 lo, hi;
            lo.x = acc[mi][nj][0]; lo.y = acc[mi][nj][1];
            hi.x = acc[mi][nj][2]; hi.y = acc[mi][nj][3];
            *(float2*)(C + (size_t)row0 * N + col)       = lo;
            *(float2*)(C + (size_t)(row0 + 8) * N + col) = hi;
        }
    }
}

// ---------------------------------------------------------------------------
// Fused per-head RMSNorm + RoPE (in-place on g_q / g_k).
// Reference semantics: norm first, then rotary with
//   rot[2i] = -x[2i+1], rot[2i+1] = x[2i],  cos/sin index = d mod 128,
//   inv_freq[f] = 10000^(-f/128).
// grid = (T, 12): hi<8 -> q head hi, hi>=8 -> k head hi-8. 256 threads.
// ---------------------------------------------------------------------------
__global__ __launch_bounds__(256) void rmsnorm_rope_kernel(
    float* __restrict__ q, float* __restrict__ kbuf,
    const float* __restrict__ qw, const float* __restrict__ kw,
    const int* __restrict__ pos)
{
    const int t  = blockIdx.x;
    const int hi = blockIdx.y;
    const int d  = threadIdx.x;

    float* row;
    const float* w;
    if (hi < NH) { row = q    + (size_t)t * DM + hi * HD;              w = qw; }
    else         { row = kbuf + (size_t)t * (NKV * HD) + (hi - NH) * HD; w = kw; }

    float v  = row[d];
    float ss = v * v;
#pragma unroll
    for (int o = 16; o; o >>= 1) ss += __shfl_xor_sync(0xffffffffu, ss, o);

    __shared__ float red[8];
    __shared__ float s_scale;
    __shared__ float sn[256];
    if ((d & 31) == 0) red[d >> 5] = ss;
    __syncthreads();
    if (d == 0) {
        float tot = 0.f;
#pragma unroll
        for (int i = 0; i < 8; i++) tot += red[i];
        s_scale = rsqrtf(tot * (1.0f / HD) + 1e-6f);
    }
    __syncthreads();

    float nrm = v * s_scale * w[d];
    sn[d] = nrm;
    __syncthreads();

    float rot = (d & 1) ? sn[d - 1] : -sn[d + 1];
    int   fi  = d & 127;
    float inv_freq = expf(-(float)fi * (logf(10000.0f) / 128.0f));
    float ang = (float)pos[t] * inv_freq;
    float sv, cv;
    sincosf(ang, &sv, &cv);
    row[d] = nrm * cv + rot * sv;
}

// ---------------------------------------------------------------------------
// Flash attention, fp32, sliding window 1024, causal.
// Block: 64 queries x 1 head. 256 threads (16x16). D=256.
// ---------------------------------------------------------------------------
#define ATTN_SMEM_FLOATS (256*64 + 256*64 + 64*256 + 64*68 + 64*3)
#define ATTN_SMEM_BYTES  (ATTN_SMEM_FLOATS * 4)

__global__ __launch_bounds__(256) void attn_kernel(
    const float* __restrict__ q, const float* __restrict__ k,
    const float* __restrict__ v, float* __restrict__ y)
{
    extern __shared__ float smf[];
    float* Qs   = smf;                 // [256][64]
    float* Ks   = Qs + 256 * 64;       // [256][64]
    float* Vs   = Ks + 256 * 64;       // [64][256]
    float* Ps   = Vs + 64 * 256;       // [64][68]
    float* m_s  = Ps + 64 * 68;        // [64]
    float* l_s  = m_s + 64;            // [64]
    float* sc_s = l_s + 64;            // [64]

    const int tid = threadIdx.x;
    const int qb  = blockIdx.x;
    const int h   = blockIdx.y;
    const int kvh = h >> 1;
    const int ty  = tid >> 4, tx = tid & 15;

    if (tid < 64) { m_s[tid] = -INFINITY; l_s[tid] = 0.f; }

    for (int idx = tid; idx < 64 * 64; idx += 256) {
        int r = idx & 63, d4 = idx >> 6;
        float4 qv = *(const float4*)(q + (size_t)(qb * 64 + r) * DM + h * HD + d4 * 4);
        Qs[(d4 * 4 + 0) * 64 + r] = qv.x;
        Qs[(d4 * 4 + 1) * 64 + r] = qv.y;
        Qs[(d4 * 4 + 2) * 64 + r] = qv.z;
        Qs[(d4 * 4 + 3) * 64 + r] = qv.w;
    }

    float acc[4][16];
#pragma unroll
    for (int i = 0; i < 4; i++)
#pragma unroll
        for (int c = 0; c < 16; c++) acc[i][c] = 0.f;

    int s0 = qb * 64 - (WIN - 1);
    if (s0 < 0) s0 = 0;
    const int kt0 = s0 >> 6;

    for (int kt = kt0; kt <= qb; kt++) {
        __syncthreads();

        for (int idx = tid; idx < 64 * 64; idx += 256) {
            int r = idx & 63, d4 = idx >> 6;
            float4 kv4 = *(const float4*)(k + (size_t)(kt * 64 + r) * (NKV * HD) + kvh * HD + d4 * 4);
            Ks[(d4 * 4 + 0) * 64 + r] = kv4.x;
            Ks[(d4 * 4 + 1) * 64 + r] = kv4.y;
            Ks[(d4 * 4 + 2) * 64 + r] = kv4.z;
            Ks[(d4 * 4 + 3) * 64 + r] = kv4.w;
        }
        for (int idx = tid; idx < 64 * 64; idx += 256) {
            int d4 = idx & 63, r = idx >> 6;
            float4 vv = *(const float4*)(v + (size_t)(kt * 64 + r) * (NKV * HD) + kvh * HD + d4 * 4);
            *(float4*)&Vs[r * 256 + d4 * 4] = vv;
        }
        __syncthreads();

        float s[4][4];
#pragma unroll
        for (int i = 0; i < 4; i++)
#pragma unroll
            for (int j = 0; j < 4; j++) s[i][j] = 0.f;
#pragma unroll 4
        for (int d = 0; d < 256; d++) {
            float4 qv = *(const float4*)&Qs[d * 64 + ty * 4];
            float4 kv = *(const float4*)&Ks[d * 64 + tx * 4];
            s[0][0] = fmaf(qv.x, kv.x, s[0][0]); s[0][1] = fmaf(qv.x, kv.y, s[0][1]);
            s[0][2] = fmaf(qv.x, kv.z, s[0][2]); s[0][3] = fmaf(qv.x, kv.w, s[0][3]);
            s[1][0] = fmaf(qv.y, kv.x, s[1][0]); s[1][1] = fmaf(qv.y, kv.y, s[1][1]);
            s[1][2] = fmaf(qv.y, kv.z, s[1][2]); s[1][3] = fmaf(qv.y, kv.w, s[1][3]);
            s[2][0] = fmaf(qv.z, kv.x, s[2][0]); s[2][1] = fmaf(qv.z, kv.y, s[2][1]);
            s[2][2] = fmaf(qv.z, kv.z, s[2][2]); s[2][3] = fmaf(qv.z, kv.w, s[2][3]);
            s[3][0] = fmaf(qv.w, kv.x, s[3][0]); s[3][1] = fmaf(qv.w, kv.y, s[3][1]);
            s[3][2] = fmaf(qv.w, kv.z, s[3][2]); s[3][3] = fmaf(qv.w, kv.w, s[3][3]);
        }

#pragma unroll
        for (int i = 0; i < 4; i++) {
            int   row = ty * 4 + i;
            int   qi  = qb * 64 + row;
            float rmax = -INFINITY;
#pragma unroll
            for (int j = 0; j < 4; j++) {
                int   kj = kt * 64 + tx * 4 + j;
                float sv = s[i][j] * 0.0625f;
                sv = (kj <= qi && kj > qi - WIN) ? sv : -INFINITY;
                s[i][j] = sv;
                rmax = fmaxf(rmax, sv);
            }
#pragma unroll
            for (int o = 8; o; o >>= 1)
                rmax = fmaxf(rmax, __shfl_xor_sync(0xffffffffu, rmax, o));
            float mold = m_s[row];
            float mn   = fmaxf(mold, rmax);
            float rsum = 0.f;
#pragma unroll
            for (int j = 0; j < 4; j++) {
                float p = (s[i][j] == -INFINITY) ? 0.f : __expf(s[i][j] - mn);
                s[i][j] = p;
                rsum += p;
            }
#pragma unroll
            for (int o = 8; o; o >>= 1)
                rsum += __shfl_xor_sync(0xffffffffu, rsum, o);
            if (tx == 0) {
                float corr = (mn == -INFINITY) ? 1.f
                           : ((mold == -INFINITY) ? 0.f : __expf(mold - mn));
                sc_s[row] = corr;
                m_s[row]  = mn;
                l_s[row]  = l_s[row] * corr + rsum;
            }
            *(float4*)&Ps[row * 68 + tx * 4] =
                make_float4(s[i][0], s[i][1], s[i][2], s[i][3]);
        }
        __syncthreads();

#pragma unroll
        for (int i = 0; i < 4; i++) {
            float corr = sc_s[ty * 4 + i];
#pragma unroll
            for (int c = 0; c < 16; c++) acc[i][c] *= corr;
        }
#pragma unroll 2
        for (int kk = 0; kk < 64; kk++) {
            float4 v0 = *(const float4*)&Vs[kk * 256 +   0 + tx * 4];
            float4 v1 = *(const float4*)&Vs[kk * 256 +  64 + tx * 4];
            float4 v2 = *(const float4*)&Vs[kk * 256 + 128 + tx * 4];
            float4 v3 = *(const float4*)&Vs[kk * 256 + 192 + tx * 4];
#pragma unroll
            for (int i = 0; i < 4; i++) {
                float p = Ps[(ty * 4 + i) * 68 + kk];
                acc[i][ 0] = fmaf(p, v0.x, acc[i][ 0]);
                acc[i][ 1] = fmaf(p, v0.y, acc[i][ 1]);
                acc[i][ 2] = fmaf(p, v0.z, acc[i][ 2]);
                acc[i][ 3] = fmaf(p, v0.w, acc[i][ 3]);
                acc[i][ 4] = fmaf(p, v1.x, acc[i][ 4]);
                acc[i][ 5] = fmaf(p, v1.y, acc[i][ 5]);
                acc[i][ 6] = fmaf(p, v1.z, acc[i][ 6]);
                acc[i][ 7] = fmaf(p, v1.w, acc[i][ 7]);
                acc[i][ 8] = fmaf(p, v2.x, acc[i][ 8]);
                acc[i][ 9] = fmaf(p, v2.y, acc[i][ 9]);
                acc[i][10] = fmaf(p, v2.z, acc[i][10]);
                acc[i][11] = fmaf(p, v2.w, acc[i][11]);
                acc[i][12] = fmaf(p, v3.x, acc[i][12]);
                acc[i][13] = fmaf(p, v3.y, acc[i][13]);
                acc[i][14] = fmaf(p, v3.z, acc[i][14]);
                acc[i][15] = fmaf(p, v3.w, acc[i][15]);
            }
        }
    }

#pragma unroll
    for (int i = 0; i < 4; i++) {
        int   row = ty * 4 + i;
        float inv = 1.f / l_s[row];
        float* yr = y + (size_t)(qb * 64 + row) * DM + h * HD;
#pragma unroll
        for (int c = 0; c < 4; c++) {
            float4 o = make_float4(acc[i][c * 4 + 0] * inv, acc[i][c * 4 + 1] * inv,
                                   acc[i][c * 4 + 2] * inv, acc[i][c * 4 + 3] * inv);
            *(float4*)&yr[c * 64 + tx * 4] = o;
        }
    }
}

// ---------------------------------------------------------------------------
extern "C" void kernel_launch(void* const* d_in, const int* in_sizes, int n_in,
                              void* d_out, int out_size)
{
    const float* x  = (const float*)d_in[0];
    const int*   pos= (const int*)  d_in[1];
    const float* Wq = (const float*)d_in[2];
    const float* Wk = (const float*)d_in[3];
    const float* Wv = (const float*)d_in[4];
    const float* Wo = (const float*)d_in[5];
    const float* qw = (const float*)d_in[6];
    const float* kw = (const float*)d_in[7];
    float* out = (float*)d_out;

    float *q_p, *k_p, *v_p, *y_p;
    cudaGetSymbolAddress((void**)&q_p, g_q);
    cudaGetSymbolAddress((void**)&k_p, g_k);
    cudaGetSymbolAddress((void**)&v_p, g_v);
    cudaGetSymbolAddress((void**)&y_p, g_y);

    // QKV projections (tf32 tensor cores)
    sgemm_tf32<<<dim3(DM / 128, T_SEQ / 128), 256>>>(x, Wq, q_p, T_SEQ, DM, DM);
    sgemm_tf32<<<dim3((NKV * HD) / 128, T_SEQ / 128), 256>>>(x, Wk, k_p, T_SEQ, NKV * HD, DM);
    sgemm_tf32<<<dim3((NKV * HD) / 128, T_SEQ / 128), 256>>>(x, Wv, v_p, T_SEQ, NKV * HD, DM);

    // RMSNorm + RoPE on q and k
    rmsnorm_rope_kernel<<<dim3(T_SEQ, NH + NKV), 256>>>(q_p, k_p, qw, kw, pos);

    // Flash attention (64-query tiles x 8 heads)
    cudaFuncSetAttribute(attn_kernel, cudaFuncAttributeMaxDynamicSharedMemorySize,
                         ATTN_SMEM_BYTES);
    attn_kernel<<<dim3(T_SEQ / 64, NH), 256, ATTN_SMEM_BYTES>>>(q_p, k_p, v_p, y_p);

    // Output projection (tf32 tensor cores; writes every element of d_out)
    sgemm_tf32<<<dim3(DM / 128, T_SEQ / 128), 256>>>(y_p, Wo, out, T_SEQ, DM, DM);
}

// round 6
// speedup vs baseline: 2.7408x; 1.6100x over previous
#include <cuda_runtime.h>
#include <cuda_bf16.h>
#include <math.h>
#include <stdint.h>

#define T_SEQ 4096
#define DM    2048
#define NH    8
#define NKV   4
#define HD    256
#define WIN   1024

// Scratch (static __device__ arrays — allocation-free per harness rules)
__device__ float g_q[T_SEQ * DM];          // 32 MB
__device__ float g_k[T_SEQ * NKV * HD];    // 16 MB
__device__ float g_v[T_SEQ * NKV * HD];    // 16 MB
__device__ float g_y[T_SEQ * DM];          // 32 MB

__device__ __forceinline__ uint32_t f2tf32(float x) {
    uint32_t y;
    asm("cvt.rna.tf32.f32 %0, %1;" : "=r"(y) : "f"(x));
    return y;
}

#define MMA_TF32(d0,d1,d2,d3,a0,a1,a2,a3,b0,b1)                              \
    asm volatile(                                                            \
        "mma.sync.aligned.m16n8k8.row.col.f32.tf32.tf32.f32 "                \
        "{%0,%1,%2,%3}, {%4,%5,%6,%7}, {%8,%9}, {%0,%1,%2,%3};"              \
        : "+f"(d0), "+f"(d1), "+f"(d2), "+f"(d3)                             \
        : "r"(a0), "r"(a1), "r"(a2), "r"(a3), "r"(b0), "r"(b1))

// ---------------------------------------------------------------------------
// TF32 tensor-core GEMM: C[M,N] = A[M,K] @ B[N,K]^T  (row-major, fp32 in/out)
// 128x128 block tile, BK=32, 256 threads = 8 warps (4m x 2n), warp tile 32x64.
// ---------------------------------------------------------------------------
__global__ __launch_bounds__(256, 2) void sgemm_tf32(
    const float* __restrict__ A, const float* __restrict__ B,
    float* __restrict__ C, int M, int N, int K)
{
    __shared__ uint32_t As[128][36];
    __shared__ uint32_t Bs[128][36];

    const int tid  = threadIdx.x;
    const int brow = blockIdx.y * 128;
    const int bcol = blockIdx.x * 128;
    const int warp = tid >> 5;
    const int lane = tid & 31;
    const int g    = lane >> 2;
    const int tig  = lane & 3;
    const int warpM = (warp >> 1) * 32;
    const int warpN = (warp & 1) * 64;

    float acc[2][8][4];
#pragma unroll
    for (int mi = 0; mi < 2; mi++)
#pragma unroll
        for (int nj = 0; nj < 8; nj++)
#pragma unroll
            for (int c = 0; c < 4; c++) acc[mi][nj][c] = 0.f;

    for (int k0 = 0; k0 < K; k0 += 32) {
        __syncthreads();
#pragma unroll
        for (int i = 0; i < 4; i++) {
            int id  = tid + i * 256;
            int row = id >> 3;
            int c4  = (id & 7) << 2;
            float4 av = *(const float4*)(A + (size_t)(brow + row) * K + k0 + c4);
            uint4 at;
            at.x = f2tf32(av.x); at.y = f2tf32(av.y);
            at.z = f2tf32(av.z); at.w = f2tf32(av.w);
            *(uint4*)&As[row][c4] = at;
            float4 bv = *(const float4*)(B + (size_t)(bcol + row) * K + k0 + c4);
            uint4 bt;
            bt.x = f2tf32(bv.x); bt.y = f2tf32(bv.y);
            bt.z = f2tf32(bv.z); bt.w = f2tf32(bv.w);
            *(uint4*)&Bs[row][c4] = bt;
        }
        __syncthreads();

#pragma unroll
        for (int ks = 0; ks < 32; ks += 8) {
            uint32_t af[2][4];
            uint32_t bf[8][2];
#pragma unroll
            for (int mi = 0; mi < 2; mi++) {
                int r = warpM + mi * 16 + g;
                af[mi][0] = As[r    ][ks + tig];
                af[mi][1] = As[r + 8][ks + tig];
                af[mi][2] = As[r    ][ks + tig + 4];
                af[mi][3] = As[r + 8][ks + tig + 4];
            }
#pragma unroll
            for (int nj = 0; nj < 8; nj++) {
                int c = warpN + nj * 8 + g;
                bf[nj][0] = Bs[c][ks + tig];
                bf[nj][1] = Bs[c][ks + tig + 4];
            }
#pragma unroll
            for (int mi = 0; mi < 2; mi++)
#pragma unroll
                for (int nj = 0; nj < 8; nj++)
                    MMA_TF32(acc[mi][nj][0], acc[mi][nj][1],
                             acc[mi][nj][2], acc[mi][nj][3],
                             af[mi][0], af[mi][1], af[mi][2], af[mi][3],
                             bf[nj][0], bf[nj][1]);
        }
    }

#pragma unroll
    for (int mi = 0; mi < 2; mi++) {
        int row0 = brow + warpM + mi * 16 + g;
#pragma unroll
        for (int nj = 0; nj < 8; nj++) {
            int col = bcol + warpN + nj * 8 + tig * 2;
            float2 lo, hi;
            lo.x = acc[mi][nj][0]; lo.y = acc[mi][nj][1];
            hi.x = acc[mi][nj][2]; hi.y = acc[mi][nj][3];
            *(float2*)(C + (size_t)row0 * N + col)       = lo;
            *(float2*)(C + (size_t)(row0 + 8) * N + col) = hi;
        }
    }
}

// ---------------------------------------------------------------------------
// Fused per-head RMSNorm + RoPE (in-place on g_q / g_k). Same as R4.
// ---------------------------------------------------------------------------
__global__ __launch_bounds__(256) void rmsnorm_rope_kernel(
    float* __restrict__ q, float* __restrict__ kbuf,
    const float* __restrict__ qw, const float* __restrict__ kw,
    const int* __restrict__ pos)
{
    const int t  = blockIdx.x;
    const int hi = blockIdx.y;
    const int d  = threadIdx.x;

    float* row;
    const float* w;
    if (hi < NH) { row = q    + (size_t)t * DM + hi * HD;              w = qw; }
    else         { row = kbuf + (size_t)t * (NKV * HD) + (hi - NH) * HD; w = kw; }

    float v  = row[d];
    float ss = v * v;
#pragma unroll
    for (int o = 16; o; o >>= 1) ss += __shfl_xor_sync(0xffffffffu, ss, o);

    __shared__ float red[8];
    __shared__ float s_scale;
    __shared__ float sn[256];
    if ((d & 31) == 0) red[d >> 5] = ss;
    __syncthreads();
    if (d == 0) {
        float tot = 0.f;
#pragma unroll
        for (int i = 0; i < 8; i++) tot += red[i];
        s_scale = rsqrtf(tot * (1.0f / HD) + 1e-6f);
    }
    __syncthreads();

    float nrm = v * s_scale * w[d];
    sn[d] = nrm;
    __syncthreads();

    float rot = (d & 1) ? sn[d - 1] : -sn[d + 1];
    int   fi  = d & 127;
    float inv_freq = expf(-(float)fi * (logf(10000.0f) / 128.0f));
    float ang = (float)pos[t] * inv_freq;
    float sv, cv;
    sincosf(ang, &sv, &cv);
    row[d] = nrm * cv + rot * sv;
}

// ---------------------------------------------------------------------------
// Flash attention, tf32 tensor cores, fp32 softmax. Window 1024, causal.
// Block: 64 queries x 1 head, 256 threads = 8 warps (wm=warp>>1 in 0..3,
// wn=warp&1 in 0..1).
//  QK^T: S[64x64], warp tile 16x32 (4 n-frags), K-dim 256 (32 k-steps).
//  PV:   O[64x256], warp tile 16x128 (16 n-frags), K-dim 64 (8 k-steps).
// Q/K/V in smem row-major tf32, pitch 260 (banks 4g+tig -> conflict-free
// fragment loads). P in smem tf32, pitch 68.
// ---------------------------------------------------------------------------
#define AT_PITCH 260
#define P_PITCH  68
#define ATTN_SMEM_FLOATS (3*64*AT_PITCH + 64*P_PITCH + 128 + 128 + 64 + 64)
#define ATTN_SMEM_BYTES  (ATTN_SMEM_FLOATS * 4)

__global__ __launch_bounds__(256) void attn_tf32(
    const float* __restrict__ q, const float* __restrict__ k,
    const float* __restrict__ v, float* __restrict__ y)
{
    extern __shared__ float smf[];
    uint32_t* Qs   = (uint32_t*)smf;               // [64][260]
    uint32_t* Ks   = Qs + 64 * AT_PITCH;           // [64][260]
    uint32_t* Vs   = Ks + 64 * AT_PITCH;           // [64][260]
    uint32_t* Ps   = Vs + 64 * AT_PITCH;           // [64][68]
    float* pmax = (float*)(Ps + 64 * P_PITCH);     // [64][2]
    float* psum = pmax + 128;                      // [64][2]
    float* m_s  = psum + 128;                      // [64]
    float* l_s  = m_s + 64;                        // [64]

    const int tid  = threadIdx.x;
    const int qb   = blockIdx.x;
    const int h    = blockIdx.y;
    const int kvh  = h >> 1;
    const int warp = tid >> 5;
    const int lane = tid & 31;
    const int g    = lane >> 2;
    const int tig  = lane & 3;
    const int wm   = warp >> 1;
    const int wn   = warp & 1;
    const int r0   = wm * 16 + g;      // this thread's first row; second = r0+8

    if (tid < 64) { m_s[tid] = -INFINITY; l_s[tid] = 0.f; }

    // Load Q tile (tf32, row-major pitch 260)
    for (int idx = tid; idx < 64 * 64; idx += 256) {
        int r = idx >> 6, c4 = (idx & 63) << 2;
        float4 qv = *(const float4*)(q + (size_t)(qb * 64 + r) * DM + h * HD + c4);
        uint4 qt;
        qt.x = f2tf32(qv.x); qt.y = f2tf32(qv.y);
        qt.z = f2tf32(qv.z); qt.w = f2tf32(qv.w);
        *(uint4*)&Qs[r * AT_PITCH + c4] = qt;
    }

    float acc[16][4];
#pragma unroll
    for (int nj = 0; nj < 16; nj++)
#pragma unroll
        for (int c = 0; c < 4; c++) acc[nj][c] = 0.f;

    int s0 = qb * 64 - (WIN - 1);
    if (s0 < 0) s0 = 0;
    const int kt0 = s0 >> 6;
    const int qi0 = qb * 64 + r0;
    const int qi1 = qi0 + 8;

    for (int kt = kt0; kt <= qb; kt++) {
        __syncthreads();   // sync1: previous tile's PV reads done (also Q store / first iter)

        // Load K and V tiles (tf32, row-major)
        for (int idx = tid; idx < 64 * 64; idx += 256) {
            int r = idx >> 6, c4 = (idx & 63) << 2;
            size_t base = (size_t)(kt * 64 + r) * (NKV * HD) + kvh * HD + c4;
            float4 kv4 = *(const float4*)(k + base);
            uint4 kt4;
            kt4.x = f2tf32(kv4.x); kt4.y = f2tf32(kv4.y);
            kt4.z = f2tf32(kv4.z); kt4.w = f2tf32(kv4.w);
            *(uint4*)&Ks[r * AT_PITCH + c4] = kt4;
            float4 vv4 = *(const float4*)(v + base);
            uint4 vt4;
            vt4.x = f2tf32(vv4.x); vt4.y = f2tf32(vv4.y);
            vt4.z = f2tf32(vv4.z); vt4.w = f2tf32(vv4.w);
            *(uint4*)&Vs[r * AT_PITCH + c4] = vt4;
        }
        __syncthreads();   // sync2

        // ---- S = Q @ K^T (warp tile 16x32) ----
        float sf[4][4];
#pragma unroll
        for (int nj = 0; nj < 4; nj++)
#pragma unroll
            for (int c = 0; c < 4; c++) sf[nj][c] = 0.f;
#pragma unroll
        for (int ks = 0; ks < 256; ks += 8) {
            uint32_t a0 = Qs[r0 * AT_PITCH + ks + tig];
            uint32_t a1 = Qs[(r0 + 8) * AT_PITCH + ks + tig];
            uint32_t a2 = Qs[r0 * AT_PITCH + ks + tig + 4];
            uint32_t a3 = Qs[(r0 + 8) * AT_PITCH + ks + tig + 4];
#pragma unroll
            for (int nj = 0; nj < 4; nj++) {
                int c = wn * 32 + nj * 8 + g;
                uint32_t b0 = Ks[c * AT_PITCH + ks + tig];
                uint32_t b1 = Ks[c * AT_PITCH + ks + tig + 4];
                MMA_TF32(sf[nj][0], sf[nj][1], sf[nj][2], sf[nj][3],
                         a0, a1, a2, a3, b0, b1);
            }
        }

        // ---- mask + partial row max ----
        float mx0 = -INFINITY, mx1 = -INFINITY;
#pragma unroll
        for (int nj = 0; nj < 4; nj++) {
#pragma unroll
            for (int c = 0; c < 2; c++) {
                int col = kt * 64 + wn * 32 + nj * 8 + 2 * tig + c;
                float v0 = sf[nj][c] * 0.0625f;       // 1/sqrt(256)
                v0 = (col <= qi0 && col > qi0 - WIN) ? v0 : -INFINITY;
                sf[nj][c] = v0;
                mx0 = fmaxf(mx0, v0);
                float v1 = sf[nj][2 + c] * 0.0625f;
                v1 = (col <= qi1 && col > qi1 - WIN) ? v1 : -INFINITY;
                sf[nj][2 + c] = v1;
                mx1 = fmaxf(mx1, v1);
            }
        }
#pragma unroll
        for (int o = 1; o <= 2; o <<= 1) {
            mx0 = fmaxf(mx0, __shfl_xor_sync(0xffffffffu, mx0, o));
            mx1 = fmaxf(mx1, __shfl_xor_sync(0xffffffffu, mx1, o));
        }
        if (tig == 0) {
            pmax[r0 * 2 + wn]       = mx0;
            pmax[(r0 + 8) * 2 + wn] = mx1;
        }
        __syncthreads();   // sync3

        float mold0 = m_s[r0], mold1 = m_s[r0 + 8];
        float mn0 = fmaxf(mold0, fmaxf(pmax[r0 * 2], pmax[r0 * 2 + 1]));
        float mn1 = fmaxf(mold1, fmaxf(pmax[(r0 + 8) * 2], pmax[(r0 + 8) * 2 + 1]));

        // ---- exp, partial sums, store P (tf32) ----
        float sum0 = 0.f, sum1 = 0.f;
#pragma unroll
        for (int nj = 0; nj < 4; nj++) {
#pragma unroll
            for (int c = 0; c < 2; c++) {
                int cl = wn * 32 + nj * 8 + 2 * tig + c;
                float p0 = (sf[nj][c] == -INFINITY) ? 0.f : __expf(sf[nj][c] - mn0);
                sum0 += p0;
                Ps[r0 * P_PITCH + cl] = f2tf32(p0);
                float p1 = (sf[nj][2 + c] == -INFINITY) ? 0.f : __expf(sf[nj][2 + c] - mn1);
                sum1 += p1;
                Ps[(r0 + 8) * P_PITCH + cl] = f2tf32(p1);
            }
        }
#pragma unroll
        for (int o = 1; o <= 2; o <<= 1) {
            sum0 += __shfl_xor_sync(0xffffffffu, sum0, o);
            sum1 += __shfl_xor_sync(0xffffffffu, sum1, o);
        }
        if (tig == 0) {
            psum[r0 * 2 + wn]       = sum0;
            psum[(r0 + 8) * 2 + wn] = sum1;
        }
        float corr0 = (mn0 == -INFINITY) ? 1.f
                    : ((mold0 == -INFINITY) ? 0.f : __expf(mold0 - mn0));
        float corr1 = (mn1 == -INFINITY) ? 1.f
                    : ((mold1 == -INFINITY) ? 0.f : __expf(mold1 - mn1));
        __syncthreads();   // sync4: P + psum visible

        if (wn == 0 && tig == 0) {
            l_s[r0]     = l_s[r0]     * corr0 + psum[r0 * 2]       + psum[r0 * 2 + 1];
            l_s[r0 + 8] = l_s[r0 + 8] * corr1 + psum[(r0 + 8) * 2] + psum[(r0 + 8) * 2 + 1];
            m_s[r0]     = mn0;
            m_s[r0 + 8] = mn1;
        }

        // ---- O = O*corr + P @ V (warp tile 16x128) ----
#pragma unroll
        for (int nj = 0; nj < 16; nj++) {
            acc[nj][0] *= corr0; acc[nj][1] *= corr0;
            acc[nj][2] *= corr1; acc[nj][3] *= corr1;
        }
#pragma unroll
        for (int ks = 0; ks < 64; ks += 8) {
            uint32_t a0 = Ps[r0 * P_PITCH + ks + tig];
            uint32_t a1 = Ps[(r0 + 8) * P_PITCH + ks + tig];
            uint32_t a2 = Ps[r0 * P_PITCH + ks + tig + 4];
            uint32_t a3 = Ps[(r0 + 8) * P_PITCH + ks + tig + 4];
#pragma unroll
            for (int nj = 0; nj < 16; nj++) {
                int c = wn * 128 + nj * 8 + g;
                uint32_t b0 = Vs[(ks + tig) * AT_PITCH + c];
                uint32_t b1 = Vs[(ks + tig + 4) * AT_PITCH + c];
                MMA_TF32(acc[nj][0], acc[nj][1], acc[nj][2], acc[nj][3],
                         a0, a1, a2, a3, b0, b1);
            }
        }
    }

    __syncthreads();
    float inv0 = 1.f / l_s[r0];
    float inv1 = 1.f / l_s[r0 + 8];
    float* yr0 = y + (size_t)(qb * 64 + r0) * DM + h * HD;
    float* yr1 = y + (size_t)(qb * 64 + r0 + 8) * DM + h * HD;
#pragma unroll
    for (int nj = 0; nj < 16; nj++) {
        int col = wn * 128 + nj * 8 + 2 * tig;
        float2 o0, o1;
        o0.x = acc[nj][0] * inv0; o0.y = acc[nj][1] * inv0;
        o1.x = acc[nj][2] * inv1; o1.y = acc[nj][3] * inv1;
        *(float2*)(yr0 + col) = o0;
        *(float2*)(yr1 + col) = o1;
    }
}

// ---------------------------------------------------------------------------
extern "C" void kernel_launch(void* const* d_in, const int* in_sizes, int n_in,
                              void* d_out, int out_size)
{
    const float* x  = (const float*)d_in[0];
    const int*   pos= (const int*)  d_in[1];
    const float* Wq = (const float*)d_in[2];
    const float* Wk = (const float*)d_in[3];
    const float* Wv = (const float*)d_in[4];
    const float* Wo = (const float*)d_in[5];
    const float* qw = (const float*)d_in[6];
    const float* kw = (const float*)d_in[7];
    float* out = (float*)d_out;

    float *q_p, *k_p, *v_p, *y_p;
    cudaGetSymbolAddress((void**)&q_p, g_q);
    cudaGetSymbolAddress((void**)&k_p, g_k);
    cudaGetSymbolAddress((void**)&v_p, g_v);
    cudaGetSymbolAddress((void**)&y_p, g_y);

    // QKV projections (tf32 tensor cores)
    sgemm_tf32<<<dim3(DM / 128, T_SEQ / 128), 256>>>(x, Wq, q_p, T_SEQ, DM, DM);
    sgemm_tf32<<<dim3((NKV * HD) / 128, T_SEQ / 128), 256>>>(x, Wk, k_p, T_SEQ, NKV * HD, DM);
    sgemm_tf32<<<dim3((NKV * HD) / 128, T_SEQ / 128), 256>>>(x, Wv, v_p, T_SEQ, NKV * HD, DM);

    // RMSNorm + RoPE on q and k
    rmsnorm_rope_kernel<<<dim3(T_SEQ, NH + NKV), 256>>>(q_p, k_p, qw, kw, pos);

    // Flash attention (tf32 tensor cores)
    cudaFuncSetAttribute(attn_tf32, cudaFuncAttributeMaxDynamicSharedMemorySize,
                         ATTN_SMEM_BYTES);
    attn_tf32<<<dim3(T_SEQ / 64, NH), 256, ATTN_SMEM_BYTES>>>(q_p, k_p, v_p, y_p);

    // Output projection (tf32 tensor cores; writes every element of d_out)
    sgemm_tf32<<<dim3(DM / 128, T_SEQ / 128), 256>>>(y_p, Wo, out, T_SEQ, DM, DM);
}

// round 8
// speedup vs baseline: 3.6526x; 1.3327x over previous
#include <cuda_runtime.h>
#include <cuda_bf16.h>
#include <cuda_fp16.h>
#include <math.h>
#include <stdint.h>

#define T_SEQ 4096
#define DM    2048
#define NH    8
#define NKV   4
#define HD    256
#define WIN   1024

// Scratch (static __device__ arrays — allocation-free per harness rules)
__device__ float g_q[T_SEQ * DM];          // 32 MB
__device__ float g_k[T_SEQ * NKV * HD];    // 16 MB
__device__ float g_v[T_SEQ * NKV * HD];    // 16 MB
__device__ float g_y[T_SEQ * DM];          // 32 MB

__device__ __forceinline__ uint32_t f2tf32(float x) {
    uint32_t y;
    asm("cvt.rna.tf32.f32 %0, %1;" : "=r"(y) : "f"(x));
    return y;
}

__device__ __forceinline__ uint32_t pack_f16x2(float lo, float hi) {
    __half2 h = __floats2half2_rn(lo, hi);   // .x = lo (low 16 bits)
    return *reinterpret_cast<uint32_t*>(&h);
}

#define MMA_F16(d0,d1,d2,d3,a0,a1,a2,a3,b0,b1)                               \
    asm volatile(                                                            \
        "mma.sync.aligned.m16n8k16.row.col.f32.f16.f16.f32 "                 \
        "{%0,%1,%2,%3}, {%4,%5,%6,%7}, {%8,%9}, {%0,%1,%2,%3};"              \
        : "+f"(d0), "+f"(d1), "+f"(d2), "+f"(d3)                             \
        : "r"(a0), "r"(a1), "r"(a2), "r"(a3), "r"(b0), "r"(b1))

#define MMA_TF32(d0,d1,d2,d3,a0,a1,a2,a3,b0,b1)                              \
    asm volatile(                                                            \
        "mma.sync.aligned.m16n8k8.row.col.f32.tf32.tf32.f32 "                \
        "{%0,%1,%2,%3}, {%4,%5,%6,%7}, {%8,%9}, {%0,%1,%2,%3};"              \
        : "+f"(d0), "+f"(d1), "+f"(d2), "+f"(d3)                             \
        : "r"(a0), "r"(a1), "r"(a2), "r"(a3), "r"(b0), "r"(b1))

// ---------------------------------------------------------------------------
// FP16 tensor-core GEMM: C[M,N] = A[M,K] @ B[N,K]^T (fp32 in/out, fp16 mma,
// fp32 accumulate). 128x128 block tile, BK=64 elements (32 f16x2 words/row),
// 256 threads = 8 warps (4m x 2n), warp tile 32x64.
// Smem word layout: As[row][w] = halves (2w, 2w+1) of that row's K-slab.
// Fragment indexing identical to the proven tf32 kernel (pitch 36 words ->
// bank = 4g + tig + const, conflict-free).
// ---------------------------------------------------------------------------
__global__ __launch_bounds__(256, 2) void sgemm_f16(
    const float* __restrict__ A, const float* __restrict__ B,
    float* __restrict__ C, int M, int N, int K)
{
    __shared__ uint32_t As[128][36];
    __shared__ uint32_t Bs[128][36];

    const int tid  = threadIdx.x;
    const int brow = blockIdx.y * 128;
    const int bcol = blockIdx.x * 128;
    const int warp = tid >> 5;
    const int lane = tid & 31;
    const int g    = lane >> 2;
    const int tig  = lane & 3;
    const int warpM = (warp >> 1) * 32;
    const int warpN = (warp & 1) * 64;

    float acc[2][8][4];
#pragma unroll
    for (int mi = 0; mi < 2; mi++)
#pragma unroll
        for (int nj = 0; nj < 8; nj++)
#pragma unroll
            for (int c = 0; c < 4; c++) acc[mi][nj][c] = 0.f;

    for (int k0 = 0; k0 < K; k0 += 64) {
        __syncthreads();
        // Load 128x64 fp32 of A and B, convert to f16x2, store to smem.
#pragma unroll
        for (int i = 0; i < 8; i++) {
            int id  = tid + i * 256;        // 2048 float4-granules per matrix
            int row = id >> 4;
            int c4  = (id & 15) << 2;       // float index 0..60
            int w   = c4 >> 1;              // word index 0..30
            float4 av = *(const float4*)(A + (size_t)(brow + row) * K + k0 + c4);
            As[row][w]     = pack_f16x2(av.x, av.y);
            As[row][w + 1] = pack_f16x2(av.z, av.w);
            float4 bv = *(const float4*)(B + (size_t)(bcol + row) * K + k0 + c4);
            Bs[row][w]     = pack_f16x2(bv.x, bv.y);
            Bs[row][w + 1] = pack_f16x2(bv.z, bv.w);
        }
        __syncthreads();

#pragma unroll
        for (int ks = 0; ks < 32; ks += 8) {    // 4 k-steps of K=16 halves
            uint32_t af[2][4];
            uint32_t bf[8][2];
#pragma unroll
            for (int mi = 0; mi < 2; mi++) {
                int r = warpM + mi * 16 + g;
                af[mi][0] = As[r    ][ks + tig];
                af[mi][1] = As[r + 8][ks + tig];
                af[mi][2] = As[r    ][ks + tig + 4];
                af[mi][3] = As[r + 8][ks + tig + 4];
            }
#pragma unroll
            for (int nj = 0; nj < 8; nj++) {
                int c = warpN + nj * 8 + g;
                bf[nj][0] = Bs[c][ks + tig];
                bf[nj][1] = Bs[c][ks + tig + 4];
            }
#pragma unroll
            for (int mi = 0; mi < 2; mi++)
#pragma unroll
                for (int nj = 0; nj < 8; nj++)
                    MMA_F16(acc[mi][nj][0], acc[mi][nj][1],
                            acc[mi][nj][2], acc[mi][nj][3],
                            af[mi][0], af[mi][1], af[mi][2], af[mi][3],
                            bf[nj][0], bf[nj][1]);
        }
    }

    // Epilogue: c0,c1 -> (row g, col 2*tig), c2,c3 -> (row g+8, col 2*tig)
#pragma unroll
    for (int mi = 0; mi < 2; mi++) {
        int row0 = brow + warpM + mi * 16 + g;
#pragma unroll
        for (int nj = 0; nj < 8; nj++) {
            int col = bcol + warpN + nj * 8 + tig * 2;
            float2 lo, hi;
            lo.x = acc[mi][nj][0]; lo.y = acc[mi][nj][1];
            hi.x = acc[mi][nj][2]; hi.y = acc[mi][nj][3];
            *(float2*)(C + (size_t)row0 * N + col)       = lo;
            *(float2*)(C + (size_t)(row0 + 8) * N + col) = hi;
        }
    }
}

// ---------------------------------------------------------------------------
// Fused per-head RMSNorm + RoPE (in-place on g_q / g_k). Same as R4/R5.
// ---------------------------------------------------------------------------
__global__ __launch_bounds__(256) void rmsnorm_rope_kernel(
    float* __restrict__ q, float* __restrict__ kbuf,
    const float* __restrict__ qw, const float* __restrict__ kw,
    const int* __restrict__ pos)
{
    const int t  = blockIdx.x;
    const int hi = blockIdx.y;
    const int d  = threadIdx.x;

    float* row;
    const float* w;
    if (hi < NH) { row = q    + (size_t)t * DM + hi * HD;              w = qw; }
    else         { row = kbuf + (size_t)t * (NKV * HD) + (hi - NH) * HD; w = kw; }

    float v  = row[d];
    float ss = v * v;
#pragma unroll
    for (int o = 16; o; o >>= 1) ss += __shfl_xor_sync(0xffffffffu, ss, o);

    __shared__ float red[8];
    __shared__ float s_scale;
    __shared__ float sn[256];
    if ((d & 31) == 0) red[d >> 5] = ss;
    __syncthreads();
    if (d == 0) {
        float tot = 0.f;
#pragma unroll
        for (int i = 0; i < 8; i++) tot += red[i];
        s_scale = rsqrtf(tot * (1.0f / HD) + 1e-6f);
    }
    __syncthreads();

    float nrm = v * s_scale * w[d];
    sn[d] = nrm;
    __syncthreads();

    float rot = (d & 1) ? sn[d - 1] : -sn[d + 1];
    int   fi  = d & 127;
    float inv_freq = expf(-(float)fi * (logf(10000.0f) / 128.0f));
    float ang = (float)pos[t] * inv_freq;
    float sv, cv;
    sincosf(ang, &sv, &cv);
    row[d] = nrm * cv + rot * sv;
}

// ---------------------------------------------------------------------------
// Flash attention, tf32 mma.sync, fp32 softmax. Window 1024, causal.
// Identical to the R5 version that passed at 1300us / rel_err 6.8e-4.
// ---------------------------------------------------------------------------
#define AT_PITCH 260
#define P_PITCH  68
#define ATTN_SMEM_FLOATS (3*64*AT_PITCH + 64*P_PITCH + 128 + 128 + 64 + 64)
#define ATTN_SMEM_BYTES  (ATTN_SMEM_FLOATS * 4)

__global__ __launch_bounds__(256) void attn_tf32(
    const float* __restrict__ q, const float* __restrict__ k,
    const float* __restrict__ v, float* __restrict__ y)
{
    extern __shared__ float smf[];
    uint32_t* Qs   = (uint32_t*)smf;               // [64][260]
    uint32_t* Ks   = Qs + 64 * AT_PITCH;           // [64][260]
    uint32_t* Vs   = Ks + 64 * AT_PITCH;           // [64][260]
    uint32_t* Ps   = Vs + 64 * AT_PITCH;           // [64][68]
    float* pmax = (float*)(Ps + 64 * P_PITCH);     // [64][2]
    float* psum = pmax + 128;                      // [64][2]
    float* m_s  = psum + 128;                      // [64]
    float* l_s  = m_s + 64;                        // [64]

    const int tid  = threadIdx.x;
    const int qb   = blockIdx.x;
    const int h    = blockIdx.y;
    const int kvh  = h >> 1;
    const int warp = tid >> 5;
    const int lane = tid & 31;
    const int g    = lane >> 2;
    const int tig  = lane & 3;
    const int wn   = warp & 1;
    const int r0   = (warp >> 1) * 16 + g;

    if (tid < 64) { m_s[tid] = -INFINITY; l_s[tid] = 0.f; }

    for (int idx = tid; idx < 64 * 64; idx += 256) {
        int r = idx >> 6, c4 = (idx & 63) << 2;
        float4 qv = *(const float4*)(q + (size_t)(qb * 64 + r) * DM + h * HD + c4);
        uint4 qt;
        qt.x = f2tf32(qv.x); qt.y = f2tf32(qv.y);
        qt.z = f2tf32(qv.z); qt.w = f2tf32(qv.w);
        *(uint4*)&Qs[r * AT_PITCH + c4] = qt;
    }

    float acc[16][4];
#pragma unroll
    for (int nj = 0; nj < 16; nj++)
#pragma unroll
        for (int c = 0; c < 4; c++) acc[nj][c] = 0.f;

    int s0 = qb * 64 - (WIN - 1);
    if (s0 < 0) s0 = 0;
    const int kt0 = s0 >> 6;
    const int qi0 = qb * 64 + r0;
    const int qi1 = qi0 + 8;

    for (int kt = kt0; kt <= qb; kt++) {
        __syncthreads();

        for (int idx = tid; idx < 64 * 64; idx += 256) {
            int r = idx >> 6, c4 = (idx & 63) << 2;
            size_t base = (size_t)(kt * 64 + r) * (NKV * HD) + kvh * HD + c4;
            float4 kv4 = *(const float4*)(k + base);
            uint4 kt4;
            kt4.x = f2tf32(kv4.x); kt4.y = f2tf32(kv4.y);
            kt4.z = f2tf32(kv4.z); kt4.w = f2tf32(kv4.w);
            *(uint4*)&Ks[r * AT_PITCH + c4] = kt4;
            float4 vv4 = *(const float4*)(v + base);
            uint4 vt4;
            vt4.x = f2tf32(vv4.x); vt4.y = f2tf32(vv4.y);
            vt4.z = f2tf32(vv4.z); vt4.w = f2tf32(vv4.w);
            *(uint4*)&Vs[r * AT_PITCH + c4] = vt4;
        }
        __syncthreads();

        float sf[4][4];
#pragma unroll
        for (int nj = 0; nj < 4; nj++)
#pragma unroll
            for (int c = 0; c < 4; c++) sf[nj][c] = 0.f;
#pragma unroll
        for (int ks = 0; ks < 256; ks += 8) {
            uint32_t a0 = Qs[r0 * AT_PITCH + ks + tig];
            uint32_t a1 = Qs[(r0 + 8) * AT_PITCH + ks + tig];
            uint32_t a2 = Qs[r0 * AT_PITCH + ks + tig + 4];
            uint32_t a3 = Qs[(r0 + 8) * AT_PITCH + ks + tig + 4];
#pragma unroll
            for (int nj = 0; nj < 4; nj++) {
                int c = wn * 32 + nj * 8 + g;
                uint32_t b0 = Ks[c * AT_PITCH + ks + tig];
                uint32_t b1 = Ks[c * AT_PITCH + ks + tig + 4];
                MMA_TF32(sf[nj][0], sf[nj][1], sf[nj][2], sf[nj][3],
                         a0, a1, a2, a3, b0, b1);
            }
        }

        float mx0 = -INFINITY, mx1 = -INFINITY;
#pragma unroll
        for (int nj = 0; nj < 4; nj++) {
#pragma unroll
            for (int c = 0; c < 2; c++) {
                int col = kt * 64 + wn * 32 + nj * 8 + 2 * tig + c;
                float v0 = sf[nj][c] * 0.0625f;
                v0 = (col <= qi0 && col > qi0 - WIN) ? v0 : -INFINITY;
                sf[nj][c] = v0;
                mx0 = fmaxf(mx0, v0);
                float v1 = sf[nj][2 + c] * 0.0625f;
                v1 = (col <= qi1 && col > qi1 - WIN) ? v1 : -INFINITY;
                sf[nj][2 + c] = v1;
                mx1 = fmaxf(mx1, v1);
            }
        }
#pragma unroll
        for (int o = 1; o <= 2; o <<= 1) {
            mx0 = fmaxf(mx0, __shfl_xor_sync(0xffffffffu, mx0, o));
            mx1 = fmaxf(mx1, __shfl_xor_sync(0xffffffffu, mx1, o));
        }
        if (tig == 0) {
            pmax[r0 * 2 + wn]       = mx0;
            pmax[(r0 + 8) * 2 + wn] = mx1;
        }
        __syncthreads();

        float mold0 = m_s[r0], mold1 = m_s[r0 + 8];
        float mn0 = fmaxf(mold0, fmaxf(pmax[r0 * 2], pmax[r0 * 2 + 1]));
        float mn1 = fmaxf(mold1, fmaxf(pmax[(r0 + 8) * 2], pmax[(r0 + 8) * 2 + 1]));

        float sum0 = 0.f, sum1 = 0.f;
#pragma unroll
        for (int nj = 0; nj < 4; nj++) {
#pragma unroll
            for (int c = 0; c < 2; c++) {
                int cl = wn * 32 + nj * 8 + 2 * tig + c;
                float p0 = (sf[nj][c] == -INFINITY) ? 0.f : __expf(sf[nj][c] - mn0);
                sum0 += p0;
                Ps[r0 * P_PITCH + cl] = f2tf32(p0);
                float p1 = (sf[nj][2 + c] == -INFINITY) ? 0.f : __expf(sf[nj][2 + c] - mn1);
                sum1 += p1;
                Ps[(r0 + 8) * P_PITCH + cl] = f2tf32(p1);
            }
        }
#pragma unroll
        for (int o = 1; o <= 2; o <<= 1) {
            sum0 += __shfl_xor_sync(0xffffffffu, sum0, o);
            sum1 += __shfl_xor_sync(0xffffffffu, sum1, o);
        }
        if (tig == 0) {
            psum[r0 * 2 + wn]       = sum0;
            psum[(r0 + 8) * 2 + wn] = sum1;
        }
        float corr0 = (mn0 == -INFINITY) ? 1.f
                    : ((mold0 == -INFINITY) ? 0.f : __expf(mold0 - mn0));
        float corr1 = (mn1 == -INFINITY) ? 1.f
                    : ((mold1 == -INFINITY) ? 0.f : __expf(mold1 - mn1));
        __syncthreads();

        if (wn == 0 && tig == 0) {
            l_s[r0]     = l_s[r0]     * corr0 + psum[r0 * 2]       + psum[r0 * 2 + 1];
            l_s[r0 + 8] = l_s[r0 + 8] * corr1 + psum[(r0 + 8) * 2] + psum[(r0 + 8) * 2 + 1];
            m_s[r0]     = mn0;
            m_s[r0 + 8] = mn1;
        }

#pragma unroll
        for (int nj = 0; nj < 16; nj++) {
            acc[nj][0] *= corr0; acc[nj][1] *= corr0;
            acc[nj][2] *= corr1; acc[nj][3] *= corr1;
        }
#pragma unroll
        for (int ks = 0; ks < 64; ks += 8) {
            uint32_t a0 = Ps[r0 * P_PITCH + ks + tig];
            uint32_t a1 = Ps[(r0 + 8) * P_PITCH + ks + tig];
            uint32_t a2 = Ps[r0 * P_PITCH + ks + tig + 4];
            uint32_t a3 = Ps[(r0 + 8) * P_PITCH + ks + tig + 4];
#pragma unroll
            for (int nj = 0; nj < 16; nj++) {
                int c = wn * 128 + nj * 8 + g;
                uint32_t b0 = Vs[(ks + tig) * AT_PITCH + c];
                uint32_t b1 = Vs[(ks + tig + 4) * AT_PITCH + c];
                MMA_TF32(acc[nj][0], acc[nj][1], acc[nj][2], acc[nj][3],
                         a0, a1, a2, a3, b0, b1);
            }
        }
    }

    __syncthreads();
    float inv0 = 1.f / l_s[r0];
    float inv1 = 1.f / l_s[r0 + 8];
    float* yr0 = y + (size_t)(qb * 64 + r0) * DM + h * HD;
    float* yr1 = y + (size_t)(qb * 64 + r0 + 8) * DM + h * HD;
#pragma unroll
    for (int nj = 0; nj < 16; nj++) {
        int col = wn * 128 + nj * 8 + 2 * tig;
        float2 o0, o1;
        o0.x = acc[nj][0] * inv0; o0.y = acc[nj][1] * inv0;
        o1.x = acc[nj][2] * inv1; o1.y = acc[nj][3] * inv1;
        *(float2*)(yr0 + col) = o0;
        *(float2*)(yr1 + col) = o1;
    }
}

// ---------------------------------------------------------------------------
extern "C" void kernel_launch(void* const* d_in, const int* in_sizes, int n_in,
                              void* d_out, int out_size)
{
    const float* x  = (const float*)d_in[0];
    const int*   pos= (const int*)  d_in[1];
    const float* Wq = (const float*)d_in[2];
    const float* Wk = (const float*)d_in[3];
    const float* Wv = (const float*)d_in[4];
    const float* Wo = (const float*)d_in[5];
    const float* qw = (const float*)d_in[6];
    const float* kw = (const float*)d_in[7];
    float* out = (float*)d_out;

    float *q_p, *k_p, *v_p, *y_p;
    cudaGetSymbolAddress((void**)&q_p, g_q);
    cudaGetSymbolAddress((void**)&k_p, g_k);
    cudaGetSymbolAddress((void**)&v_p, g_v);
    cudaGetSymbolAddress((void**)&y_p, g_y);

    // QKV projections (fp16 tensor cores, fp32 accumulate)
    sgemm_f16<<<dim3(DM / 128, T_SEQ / 128), 256>>>(x, Wq, q_p, T_SEQ, DM, DM);
    sgemm_f16<<<dim3((NKV * HD) / 128, T_SEQ / 128), 256>>>(x, Wk, k_p, T_SEQ, NKV * HD, DM);
    sgemm_f16<<<dim3((NKV * HD) / 128, T_SEQ / 128), 256>>>(x, Wv, v_p, T_SEQ, NKV * HD, DM);

    // RMSNorm + RoPE on q and k
    rmsnorm_rope_kernel<<<dim3(T_SEQ, NH + NKV), 256>>>(q_p, k_p, qw, kw, pos);

    // Flash attention (tf32 tensor cores)
    cudaFuncSetAttribute(attn_tf32, cudaFuncAttributeMaxDynamicSharedMemorySize,
                         ATTN_SMEM_BYTES);
    attn_tf32<<<dim3(T_SEQ / 64, NH), 256, ATTN_SMEM_BYTES>>>(q_p, k_p, v_p, y_p);

    // Output projection (fp16 tensor cores; writes every element of d_out)
    sgemm_f16<<<dim3(DM / 128, T_SEQ / 128), 256>>>(y_p, Wo, out, T_SEQ, DM, DM);
}

// round 9
// speedup vs baseline: 4.9623x; 1.3586x over previous
#include <cuda_runtime.h>
#include <cuda_bf16.h>
#include <cuda_fp16.h>
#include <math.h>
#include <stdint.h>

#define T_SEQ 4096
#define DM    2048
#define NH    8
#define NKV   4
#define HD    256
#define WIN   1024

// Scratch (static __device__ arrays — allocation-free per harness rules)
__device__ float  g_q[T_SEQ * DM];            // 32 MB (fp32, rmsnorm in-place)
__device__ float  g_k[T_SEQ * NKV * HD];      // 16 MB
__device__ float  g_v[T_SEQ * NKV * HD];      // 16 MB
__device__ __half g_xh[T_SEQ * DM];           // 16 MB
__device__ __half g_wqh[DM * DM];             // 8 MB
__device__ __half g_wkh[NKV * HD * DM];       // 4 MB
__device__ __half g_wvh[NKV * HD * DM];       // 4 MB
__device__ __half g_woh[DM * DM];             // 8 MB
__device__ __half g_yh[T_SEQ * DM];           // 16 MB (attention out, fp16)

__device__ __forceinline__ uint32_t pack_f16x2(float lo, float hi) {
    __half2 h = __floats2half2_rn(lo, hi);    // .x = lo (low 16 bits)
    return *reinterpret_cast<uint32_t*>(&h);
}

__device__ __forceinline__ uint32_t smem_u32(const void* p) {
    uint32_t a;
    asm("{ .reg .u64 t; cvta.to.shared.u64 t, %1; cvt.u32.u64 %0, t; }"
        : "=r"(a) : "l"(p));
    return a;
}
__device__ __forceinline__ void cp_async16(uint32_t dst, const void* src) {
    asm volatile("cp.async.cg.shared.global [%0], [%1], 16;" :: "r"(dst), "l"(src));
}
__device__ __forceinline__ void cp_commit() {
    asm volatile("cp.async.commit_group;" ::: "memory");
}
__device__ __forceinline__ void cp_wait1() {
    asm volatile("cp.async.wait_group 1;" ::: "memory");
}

#define MMA_F16(d0,d1,d2,d3,a0,a1,a2,a3,b0,b1)                               \
    asm volatile(                                                            \
        "mma.sync.aligned.m16n8k16.row.col.f32.f16.f16.f32 "                 \
        "{%0,%1,%2,%3}, {%4,%5,%6,%7}, {%8,%9}, {%0,%1,%2,%3};"              \
        : "+f"(d0), "+f"(d1), "+f"(d2), "+f"(d3)                             \
        : "r"(a0), "r"(a1), "r"(a2), "r"(a3), "r"(b0), "r"(b1))

// ---------------------------------------------------------------------------
// fp32 -> fp16 conversion pass (n % 1024 == 0)
// ---------------------------------------------------------------------------
__global__ __launch_bounds__(256) void to_half_kernel(
    const float* __restrict__ in, __half* __restrict__ out, int n)
{
    int i = (blockIdx.x * 256 + threadIdx.x) * 4;
    if (i < n) {
        float4 v = *(const float4*)(in + i);
        uint2 o;
        o.x = pack_f16x2(v.x, v.y);
        o.y = pack_f16x2(v.z, v.w);
        *(uint2*)((char*)out + (size_t)i * 2) = o;
    }
}

// ---------------------------------------------------------------------------
// FP16 tensor-core GEMM, fp16 inputs, fp32 out: C[M,N] = A[M,K] @ B[N,K]^T.
// 128x128 tile, BK=64 halves (32 words/row, pitch 36), cp.async double
// buffered, 256 threads = 8 warps (4m x 2n), warp tile 32x64.
// ---------------------------------------------------------------------------
#define HG_STAGE_WORDS (128 * 36)
#define HG_SMEM_BYTES  (4 * HG_STAGE_WORDS * 4 * 2)   // 2 stages x (A+B) = 73728

__global__ __launch_bounds__(256, 2) void hgemm(
    const __half* __restrict__ A, const __half* __restrict__ B,
    float* __restrict__ C, int M, int N, int K)
{
    extern __shared__ uint32_t sm[];
    // layout: [stage][A/B][128][36]
    const int tid  = threadIdx.x;
    const int brow = blockIdx.y * 128;
    const int bcol = blockIdx.x * 128;
    const int warp = tid >> 5;
    const int lane = tid & 31;
    const int g    = lane >> 2;
    const int tig  = lane & 3;
    const int warpM = (warp >> 1) * 32;
    const int warpN = (warp & 1) * 64;
    const int nslab = K >> 6;

    auto As = [&](int st, int r, int w) -> uint32_t& {
        return sm[st * 2 * HG_STAGE_WORDS + r * 36 + w];
    };
    auto Bs = [&](int st, int r, int w) -> uint32_t& {
        return sm[st * 2 * HG_STAGE_WORDS + HG_STAGE_WORDS + r * 36 + w];
    };

    auto load_slab = [&](int j, int st) {
        const int k0 = j << 6;
#pragma unroll
        for (int i = 0; i < 4; i++) {
            int id  = tid + i * 256;          // 1024 granules per matrix
            int row = id >> 3;
            int g8  = (id & 7) * 8;           // half offset, 16B granule
            cp_async16(smem_u32(&As(st, row, g8 >> 1)),
                       A + (size_t)(brow + row) * K + k0 + g8);
            cp_async16(smem_u32(&Bs(st, row, g8 >> 1)),
                       B + (size_t)(bcol + row) * K + k0 + g8);
        }
    };

    float acc[2][8][4];
#pragma unroll
    for (int mi = 0; mi < 2; mi++)
#pragma unroll
        for (int nj = 0; nj < 8; nj++)
#pragma unroll
            for (int c = 0; c < 4; c++) acc[mi][nj][c] = 0.f;

    load_slab(0, 0);
    cp_commit();

    for (int j = 0; j < nslab; j++) {
        const int st = j & 1;
        if (j + 1 < nslab) load_slab(j + 1, st ^ 1);
        cp_commit();
        cp_wait1();                            // slab j resident
        __syncthreads();

#pragma unroll
        for (int ks = 0; ks < 32; ks += 8) {   // 4 k-steps of K=16 halves
            uint32_t af[2][4];
            uint32_t bf[8][2];
#pragma unroll
            for (int mi = 0; mi < 2; mi++) {
                int r = warpM + mi * 16 + g;
                af[mi][0] = As(st, r,     ks + tig);
                af[mi][1] = As(st, r + 8, ks + tig);
                af[mi][2] = As(st, r,     ks + tig + 4);
                af[mi][3] = As(st, r + 8, ks + tig + 4);
            }
#pragma unroll
            for (int nj = 0; nj < 8; nj++) {
                int c = warpN + nj * 8 + g;
                bf[nj][0] = Bs(st, c, ks + tig);
                bf[nj][1] = Bs(st, c, ks + tig + 4);
            }
#pragma unroll
            for (int mi = 0; mi < 2; mi++)
#pragma unroll
                for (int nj = 0; nj < 8; nj++)
                    MMA_F16(acc[mi][nj][0], acc[mi][nj][1],
                            acc[mi][nj][2], acc[mi][nj][3],
                            af[mi][0], af[mi][1], af[mi][2], af[mi][3],
                            bf[nj][0], bf[nj][1]);
        }
        __syncthreads();                       // stage may be overwritten next iter
    }

#pragma unroll
    for (int mi = 0; mi < 2; mi++) {
        int row0 = brow + warpM + mi * 16 + g;
#pragma unroll
        for (int nj = 0; nj < 8; nj++) {
            int col = bcol + warpN + nj * 8 + tig * 2;
            float2 lo, hi;
            lo.x = acc[mi][nj][0]; lo.y = acc[mi][nj][1];
            hi.x = acc[mi][nj][2]; hi.y = acc[mi][nj][3];
            *(float2*)(C + (size_t)row0 * N + col)       = lo;
            *(float2*)(C + (size_t)(row0 + 8) * N + col) = hi;
        }
    }
}

// ---------------------------------------------------------------------------
// Fused per-head RMSNorm + RoPE (in-place on g_q / g_k). Unchanged.
// ---------------------------------------------------------------------------
__global__ __launch_bounds__(256) void rmsnorm_rope_kernel(
    float* __restrict__ q, float* __restrict__ kbuf,
    const float* __restrict__ qw, const float* __restrict__ kw,
    const int* __restrict__ pos)
{
    const int t  = blockIdx.x;
    const int hi = blockIdx.y;
    const int d  = threadIdx.x;

    float* row;
    const float* w;
    if (hi < NH) { row = q    + (size_t)t * DM + hi * HD;              w = qw; }
    else         { row = kbuf + (size_t)t * (NKV * HD) + (hi - NH) * HD; w = kw; }

    float v  = row[d];
    float ss = v * v;
#pragma unroll
    for (int o = 16; o; o >>= 1) ss += __shfl_xor_sync(0xffffffffu, ss, o);

    __shared__ float red[8];
    __shared__ float s_scale;
    __shared__ float sn[256];
    if ((d & 31) == 0) red[d >> 5] = ss;
    __syncthreads();
    if (d == 0) {
        float tot = 0.f;
#pragma unroll
        for (int i = 0; i < 8; i++) tot += red[i];
        s_scale = rsqrtf(tot * (1.0f / HD) + 1e-6f);
    }
    __syncthreads();

    float nrm = v * s_scale * w[d];
    sn[d] = nrm;
    __syncthreads();

    float rot = (d & 1) ? sn[d - 1] : -sn[d + 1];
    int   fi  = d & 127;
    float inv_freq = expf(-(float)fi * (logf(10000.0f) / 128.0f));
    float ang = (float)pos[t] * inv_freq;
    float sv, cv;
    sincosf(ang, &sv, &cv);
    row[d] = nrm * cv + rot * sv;
}

// ---------------------------------------------------------------------------
// Flash attention, fp16 mma.sync (m16n8k16), fp32 softmax. Window 1024.
// 64 queries x 1 head per block, 256 threads = 8 warps.
//  Qs/Ks: [64 rows][132 words]  (256 halves packed pairwise along K)
//  Vt:    [32 kpairs][264 words] (word = (V[2kp][d], V[2kp+1][d]))
//  Ps:    [64 rows][36 words]   (64 probs packed pairwise along cols)
// Epilogue writes fp16 y (feeds hgemm out-projection).
// ---------------------------------------------------------------------------
#define QK_PW 132
#define VT_PW 264
#define P_PW  36
#define ATTN_SMEM_WORDS (2*64*QK_PW + 32*VT_PW + 64*P_PW + 128 + 128 + 64 + 64)
#define ATTN_SMEM_BYTES (ATTN_SMEM_WORDS * 4)

__global__ __launch_bounds__(256) void attn_f16(
    const float* __restrict__ q, const float* __restrict__ k,
    const float* __restrict__ v, __half* __restrict__ yh)
{
    extern __shared__ uint32_t smw[];
    uint32_t* Qs = smw;                       // [64][132]
    uint32_t* Ks = Qs + 64 * QK_PW;           // [64][132]
    uint32_t* Vt = Ks + 64 * QK_PW;           // [32][264]
    uint32_t* Ps = Vt + 32 * VT_PW;           // [64][36]
    float* pmax = (float*)(Ps + 64 * P_PW);   // [64][2]
    float* psum = pmax + 128;                 // [64][2]
    float* m_s  = psum + 128;                 // [64]
    float* l_s  = m_s + 64;                   // [64]

    const int tid  = threadIdx.x;
    const int qb   = blockIdx.x;
    const int h    = blockIdx.y;
    const int kvh  = h >> 1;
    const int warp = tid >> 5;
    const int lane = tid & 31;
    const int g    = lane >> 2;
    const int tig  = lane & 3;
    const int wn   = warp & 1;
    const int r0   = (warp >> 1) * 16 + g;

    if (tid < 64) { m_s[tid] = -INFINITY; l_s[tid] = 0.f; }

    // Q tile: fp32 -> f16x2 words, row-major
    for (int idx = tid; idx < 64 * 64; idx += 256) {
        int r = idx >> 6, c4 = (idx & 63) << 2;
        float4 qv = *(const float4*)(q + (size_t)(qb * 64 + r) * DM + h * HD + c4);
        uint2 o;
        o.x = pack_f16x2(qv.x, qv.y);
        o.y = pack_f16x2(qv.z, qv.w);
        *(uint2*)&Qs[r * QK_PW + (c4 >> 1)] = o;
    }

    float acc[16][4];
#pragma unroll
    for (int nj = 0; nj < 16; nj++)
#pragma unroll
        for (int c = 0; c < 4; c++) acc[nj][c] = 0.f;

    int s0 = qb * 64 - (WIN - 1);
    if (s0 < 0) s0 = 0;
    const int kt0 = s0 >> 6;
    const int qi0 = qb * 64 + r0;
    const int qi1 = qi0 + 8;

    for (int kt = kt0; kt <= qb; kt++) {
        __syncthreads();

        // K tile (row-major, K-dim pairs packed)
        for (int idx = tid; idx < 64 * 64; idx += 256) {
            int r = idx >> 6, c4 = (idx & 63) << 2;
            float4 kv4 = *(const float4*)(k + (size_t)(kt * 64 + r) * (NKV * HD) + kvh * HD + c4);
            uint2 o;
            o.x = pack_f16x2(kv4.x, kv4.y);
            o.y = pack_f16x2(kv4.z, kv4.w);
            *(uint2*)&Ks[r * QK_PW + (c4 >> 1)] = o;
        }
        // V tile row-pair packed: Vt[kp][d] = (V[2kp][d], V[2kp+1][d])
        for (int idx = tid; idx < 32 * 64; idx += 256) {
            int kp = idx >> 6, c4 = (idx & 63) << 2;
            size_t b0 = (size_t)(kt * 64 + 2 * kp)     * (NKV * HD) + kvh * HD + c4;
            size_t b1 = (size_t)(kt * 64 + 2 * kp + 1) * (NKV * HD) + kvh * HD + c4;
            float4 lo = *(const float4*)(v + b0);
            float4 hi = *(const float4*)(v + b1);
            uint4 o;
            o.x = pack_f16x2(lo.x, hi.x);
            o.y = pack_f16x2(lo.y, hi.y);
            o.z = pack_f16x2(lo.z, hi.z);
            o.w = pack_f16x2(lo.w, hi.w);
            *(uint4*)&Vt[kp * VT_PW + c4] = o;
        }
        __syncthreads();

        // ---- S = Q @ K^T (fp16 mma, 16 k-steps) ----
        float sf[4][4];
#pragma unroll
        for (int nj = 0; nj < 4; nj++)
#pragma unroll
            for (int c = 0; c < 4; c++) sf[nj][c] = 0.f;
#pragma unroll
        for (int ks = 0; ks < 128; ks += 8) {
            uint32_t a0 = Qs[r0 * QK_PW + ks + tig];
            uint32_t a1 = Qs[(r0 + 8) * QK_PW + ks + tig];
            uint32_t a2 = Qs[r0 * QK_PW + ks + tig + 4];
            uint32_t a3 = Qs[(r0 + 8) * QK_PW + ks + tig + 4];
#pragma unroll
            for (int nj = 0; nj < 4; nj++) {
                int c = wn * 32 + nj * 8 + g;
                uint32_t b0 = Ks[c * QK_PW + ks + tig];
                uint32_t b1 = Ks[c * QK_PW + ks + tig + 4];
                MMA_F16(sf[nj][0], sf[nj][1], sf[nj][2], sf[nj][3],
                        a0, a1, a2, a3, b0, b1);
            }
        }

        // ---- mask + partial row max ----
        float mx0 = -INFINITY, mx1 = -INFINITY;
#pragma unroll
        for (int nj = 0; nj < 4; nj++) {
#pragma unroll
            for (int c = 0; c < 2; c++) {
                int col = kt * 64 + wn * 32 + nj * 8 + 2 * tig + c;
                float v0 = sf[nj][c] * 0.0625f;       // 1/sqrt(256)
                v0 = (col <= qi0 && col > qi0 - WIN) ? v0 : -INFINITY;
                sf[nj][c] = v0;
                mx0 = fmaxf(mx0, v0);
                float v1 = sf[nj][2 + c] * 0.0625f;
                v1 = (col <= qi1 && col > qi1 - WIN) ? v1 : -INFINITY;
                sf[nj][2 + c] = v1;
                mx1 = fmaxf(mx1, v1);
            }
        }
#pragma unroll
        for (int o = 1; o <= 2; o <<= 1) {
            mx0 = fmaxf(mx0, __shfl_xor_sync(0xffffffffu, mx0, o));
            mx1 = fmaxf(mx1, __shfl_xor_sync(0xffffffffu, mx1, o));
        }
        if (tig == 0) {
            pmax[r0 * 2 + wn]       = mx0;
            pmax[(r0 + 8) * 2 + wn] = mx1;
        }
        __syncthreads();

        float mold0 = m_s[r0], mold1 = m_s[r0 + 8];
        float mn0 = fmaxf(mold0, fmaxf(pmax[r0 * 2], pmax[r0 * 2 + 1]));
        float mn1 = fmaxf(mold1, fmaxf(pmax[(r0 + 8) * 2], pmax[(r0 + 8) * 2 + 1]));

        // ---- exp, partial sums, store P packed fp16 ----
        float sum0 = 0.f, sum1 = 0.f;
#pragma unroll
        for (int nj = 0; nj < 4; nj++) {
            float p00 = (sf[nj][0] == -INFINITY) ? 0.f : __expf(sf[nj][0] - mn0);
            float p01 = (sf[nj][1] == -INFINITY) ? 0.f : __expf(sf[nj][1] - mn0);
            float p10 = (sf[nj][2] == -INFINITY) ? 0.f : __expf(sf[nj][2] - mn1);
            float p11 = (sf[nj][3] == -INFINITY) ? 0.f : __expf(sf[nj][3] - mn1);
            sum0 += p00 + p01;
            sum1 += p10 + p11;
            int wd = wn * 16 + nj * 4 + tig;          // cols (2wd, 2wd+1)
            Ps[r0 * P_PW + wd]       = pack_f16x2(p00, p01);
            Ps[(r0 + 8) * P_PW + wd] = pack_f16x2(p10, p11);
        }
#pragma unroll
        for (int o = 1; o <= 2; o <<= 1) {
            sum0 += __shfl_xor_sync(0xffffffffu, sum0, o);
            sum1 += __shfl_xor_sync(0xffffffffu, sum1, o);
        }
        if (tig == 0) {
            psum[r0 * 2 + wn]       = sum0;
            psum[(r0 + 8) * 2 + wn] = sum1;
        }
        float corr0 = (mn0 == -INFINITY) ? 1.f
                    : ((mold0 == -INFINITY) ? 0.f : __expf(mold0 - mn0));
        float corr1 = (mn1 == -INFINITY) ? 1.f
                    : ((mold1 == -INFINITY) ? 0.f : __expf(mold1 - mn1));
        __syncthreads();

        if (wn == 0 && tig == 0) {
            l_s[r0]     = l_s[r0]     * corr0 + psum[r0 * 2]       + psum[r0 * 2 + 1];
            l_s[r0 + 8] = l_s[r0 + 8] * corr1 + psum[(r0 + 8) * 2] + psum[(r0 + 8) * 2 + 1];
            m_s[r0]     = mn0;
            m_s[r0 + 8] = mn1;
        }

        // ---- O = O*corr + P @ V (fp16 mma, 4 k-steps) ----
#pragma unroll
        for (int nj = 0; nj < 16; nj++) {
            acc[nj][0] *= corr0; acc[nj][1] *= corr0;
            acc[nj][2] *= corr1; acc[nj][3] *= corr1;
        }
#pragma unroll
        for (int ks = 0; ks < 32; ks += 8) {
            uint32_t a0 = Ps[r0 * P_PW + ks + tig];
            uint32_t a1 = Ps[(r0 + 8) * P_PW + ks + tig];
            uint32_t a2 = Ps[r0 * P_PW + ks + tig + 4];
            uint32_t a3 = Ps[(r0 + 8) * P_PW + ks + tig + 4];
#pragma unroll
            for (int nj = 0; nj < 16; nj++) {
                int c = wn * 128 + nj * 8 + g;
                uint32_t b0 = Vt[(ks + tig) * VT_PW + c];
                uint32_t b1 = Vt[(ks + tig + 4) * VT_PW + c];
                MMA_F16(acc[nj][0], acc[nj][1], acc[nj][2], acc[nj][3],
                        a0, a1, a2, a3, b0, b1);
            }
        }
    }

    __syncthreads();
    float inv0 = 1.f / l_s[r0];
    float inv1 = 1.f / l_s[r0 + 8];
    __half* yr0 = yh + (size_t)(qb * 64 + r0) * DM + h * HD;
    __half* yr1 = yh + (size_t)(qb * 64 + r0 + 8) * DM + h * HD;
#pragma unroll
    for (int nj = 0; nj < 16; nj++) {
        int col = wn * 128 + nj * 8 + 2 * tig;
        *(uint32_t*)(yr0 + col) = pack_f16x2(acc[nj][0] * inv0, acc[nj][1] * inv0);
        *(uint32_t*)(yr1 + col) = pack_f16x2(acc[nj][2] * inv1, acc[nj][3] * inv1);
    }
}

// ---------------------------------------------------------------------------
extern "C" void kernel_launch(void* const* d_in, const int* in_sizes, int n_in,
                              void* d_out, int out_size)
{
    const float* x  = (const float*)d_in[0];
    const int*   pos= (const int*)  d_in[1];
    const float* Wq = (const float*)d_in[2];
    const float* Wk = (const float*)d_in[3];
    const float* Wv = (const float*)d_in[4];
    const float* Wo = (const float*)d_in[5];
    const float* qw = (const float*)d_in[6];
    const float* kw = (const float*)d_in[7];
    float* out = (float*)d_out;

    float  *q_p, *k_p, *v_p;
    __half *xh_p, *wqh_p, *wkh_p, *wvh_p, *woh_p, *yh_p;
    cudaGetSymbolAddress((void**)&q_p,   g_q);
    cudaGetSymbolAddress((void**)&k_p,   g_k);
    cudaGetSymbolAddress((void**)&v_p,   g_v);
    cudaGetSymbolAddress((void**)&xh_p,  g_xh);
    cudaGetSymbolAddress((void**)&wqh_p, g_wqh);
    cudaGetSymbolAddress((void**)&wkh_p, g_wkh);
    cudaGetSymbolAddress((void**)&wvh_p, g_wvh);
    cudaGetSymbolAddress((void**)&woh_p, g_woh);
    cudaGetSymbolAddress((void**)&yh_p,  g_yh);

    // fp32 -> fp16 conversion passes (same rounding the R7 GEMM did in-loop)
    to_half_kernel<<<(T_SEQ * DM) / 1024, 256>>>(x, xh_p, T_SEQ * DM);
    to_half_kernel<<<(DM * DM) / 1024, 256>>>(Wq, wqh_p, DM * DM);
    to_half_kernel<<<(NKV * HD * DM) / 1024, 256>>>(Wk, wkh_p, NKV * HD * DM);
    to_half_kernel<<<(NKV * HD * DM) / 1024, 256>>>(Wv, wvh_p, NKV * HD * DM);
    to_half_kernel<<<(DM * DM) / 1024, 256>>>(Wo, woh_p, DM * DM);

    cudaFuncSetAttribute(hgemm, cudaFuncAttributeMaxDynamicSharedMemorySize,
                         HG_SMEM_BYTES);

    // QKV projections (fp16 tensor cores, cp.async double-buffered)
    hgemm<<<dim3(DM / 128, T_SEQ / 128), 256, HG_SMEM_BYTES>>>(
        xh_p, wqh_p, q_p, T_SEQ, DM, DM);
    hgemm<<<dim3((NKV * HD) / 128, T_SEQ / 128), 256, HG_SMEM_BYTES>>>(
        xh_p, wkh_p, k_p, T_SEQ, NKV * HD, DM);
    hgemm<<<dim3((NKV * HD) / 128, T_SEQ / 128), 256, HG_SMEM_BYTES>>>(
        xh_p, wvh_p, v_p, T_SEQ, NKV * HD, DM);

    // RMSNorm + RoPE on q and k (fp32, in-place)
    rmsnorm_rope_kernel<<<dim3(T_SEQ, NH + NKV), 256>>>(q_p, k_p, qw, kw, pos);

    // Flash attention (fp16 tensor cores); writes fp16 y
    cudaFuncSetAttribute(attn_f16, cudaFuncAttributeMaxDynamicSharedMemorySize,
                         ATTN_SMEM_BYTES);
    attn_f16<<<dim3(T_SEQ / 64, NH), 256, ATTN_SMEM_BYTES>>>(q_p, k_p, v_p, yh_p);

    // Output projection (writes every element of d_out)
    hgemm<<<dim3(DM / 128, T_SEQ / 128), 256, HG_SMEM_BYTES>>>(
        yh_p, woh_p, out, T_SEQ, DM, DM);
}

// round 10
// speedup vs baseline: 5.1870x; 1.0453x over previous
#include <cuda_runtime.h>
#include <cuda_bf16.h>
#include <cuda_fp16.h>
#include <math.h>
#include <stdint.h>

#define T_SEQ 4096
#define DM    2048
#define NH    8
#define NKV   4
#define HD    256
#define WIN   1024

// Scratch (static __device__ arrays — allocation-free per harness rules)
__device__ float  g_q[T_SEQ * DM];            // 32 MB (fp32, rmsnorm in-place)
__device__ float  g_k[T_SEQ * NKV * HD];      // 16 MB
__device__ float  g_v[T_SEQ * NKV * HD];      // 16 MB
__device__ __half g_xh[T_SEQ * DM];           // 16 MB
__device__ __half g_wqh[DM * DM];             // 8 MB
__device__ __half g_wkh[NKV * HD * DM];       // 4 MB
__device__ __half g_wvh[NKV * HD * DM];       // 4 MB
__device__ __half g_woh[DM * DM];             // 8 MB
__device__ __half g_yh[T_SEQ * DM];           // 16 MB (attention out, fp16)
__device__ float  g_cs[T_SEQ * 128];          // 2 MB rope cos table
__device__ float  g_sn[T_SEQ * 128];          // 2 MB rope sin table

__device__ __forceinline__ uint32_t pack_f16x2(float lo, float hi) {
    __half2 h = __floats2half2_rn(lo, hi);    // .x = lo (low 16 bits)
    return *reinterpret_cast<uint32_t*>(&h);
}

__device__ __forceinline__ uint32_t smem_u32(const void* p) {
    uint32_t a;
    asm("{ .reg .u64 t; cvta.to.shared.u64 t, %1; cvt.u32.u64 %0, t; }"
        : "=r"(a) : "l"(p));
    return a;
}
__device__ __forceinline__ void cp_async16(uint32_t dst, const void* src) {
    asm volatile("cp.async.cg.shared.global [%0], [%1], 16;" :: "r"(dst), "l"(src));
}
__device__ __forceinline__ void cp_commit() {
    asm volatile("cp.async.commit_group;" ::: "memory");
}
__device__ __forceinline__ void cp_wait1() {
    asm volatile("cp.async.wait_group 1;" ::: "memory");
}

#define MMA_F16(d0,d1,d2,d3,a0,a1,a2,a3,b0,b1)                               \
    asm volatile(                                                            \
        "mma.sync.aligned.m16n8k16.row.col.f32.f16.f16.f32 "                 \
        "{%0,%1,%2,%3}, {%4,%5,%6,%7}, {%8,%9}, {%0,%1,%2,%3};"              \
        : "+f"(d0), "+f"(d1), "+f"(d2), "+f"(d3)                             \
        : "r"(a0), "r"(a1), "r"(a2), "r"(a3), "r"(b0), "r"(b1))

#define LDSM_X4(r0,r1,r2,r3,addr)                                            \
    asm volatile("ldmatrix.sync.aligned.m8n8.x4.shared.b16 {%0,%1,%2,%3}, [%4];" \
        : "=r"(r0), "=r"(r1), "=r"(r2), "=r"(r3) : "r"(addr))

// ---------------------------------------------------------------------------
// fp32 -> fp16 conversion pass, 8 elements/thread, grid-stride.
// ---------------------------------------------------------------------------
__global__ __launch_bounds__(256) void to_half_kernel(
    const float* __restrict__ in, __half* __restrict__ out, int n)
{
    for (int i = (blockIdx.x * 256 + threadIdx.x) * 8; i < n;
         i += gridDim.x * 256 * 8) {
        float4 v0 = *(const float4*)(in + i);
        float4 v1 = *(const float4*)(in + i + 4);
        uint4 o;
        o.x = pack_f16x2(v0.x, v0.y);
        o.y = pack_f16x2(v0.z, v0.w);
        o.z = pack_f16x2(v1.x, v1.y);
        o.w = pack_f16x2(v1.z, v1.w);
        *(uint4*)((char*)out + (size_t)i * 2) = o;
    }
}

// ---------------------------------------------------------------------------
// RoPE table: cos/sin[t][fi], same expf/sincosf math as before (bit-identical)
// ---------------------------------------------------------------------------
__global__ __launch_bounds__(128) void rope_table_kernel(
    const int* __restrict__ pos, float* __restrict__ cs, float* __restrict__ sn)
{
    int t = blockIdx.x, f = threadIdx.x;
    float inv_freq = expf(-(float)f * (logf(10000.0f) / 128.0f));
    float ang = (float)pos[t] * inv_freq;
    float sv, cv;
    sincosf(ang, &sv, &cv);
    cs[t * 128 + f] = cv;
    sn[t * 128 + f] = sv;
}

// ---------------------------------------------------------------------------
// FP16 tensor-core GEMM with ldmatrix fragment loads.
// 128x128 tile, BK=64 halves (32 words/row, pitch 36), cp.async double
// buffered, 256 threads = 8 warps (4m x 2n), warp tile 32x64.
// ---------------------------------------------------------------------------
#define HG_STAGE_WORDS (128 * 36)
#define HG_SMEM_BYTES  (4 * HG_STAGE_WORDS * 4 * 2)   // 73728

__global__ __launch_bounds__(256, 2) void hgemm(
    const __half* __restrict__ A, const __half* __restrict__ B,
    float* __restrict__ C, int M, int N, int K)
{
    extern __shared__ uint32_t sm[];
    const int tid  = threadIdx.x;
    const int brow = blockIdx.y * 128;
    const int bcol = blockIdx.x * 128;
    const int warp = tid >> 5;
    const int lane = tid & 31;
    const int g    = lane >> 2;
    const int tig  = lane & 3;
    const int warpM = (warp >> 1) * 32;
    const int warpN = (warp & 1) * 64;
    const int nslab = K >> 6;

    const uint32_t sa = smem_u32(sm);
    // ldmatrix per-lane byte addresses (within stage 0)
    const uint32_t aab = sa + 4u * ((warpM + (lane & 15)) * 36 + ((lane >> 4) << 2));
    const uint32_t bbb = sa + 4u * (HG_STAGE_WORDS
                       + (warpN + (lane & 7) + ((lane >> 4) << 3)) * 36
                       + (((lane >> 3) & 1) << 2));

    auto As_w = [&](int st, int r, int w) -> uint32_t& {
        return sm[st * 2 * HG_STAGE_WORDS + r * 36 + w];
    };
    auto Bs_w = [&](int st, int r, int w) -> uint32_t& {
        return sm[st * 2 * HG_STAGE_WORDS + HG_STAGE_WORDS + r * 36 + w];
    };

    auto load_slab = [&](int j, int st) {
        const int k0 = j << 6;
#pragma unroll
        for (int i = 0; i < 4; i++) {
            int id  = tid + i * 256;
            int row = id >> 3;
            int g8  = (id & 7) * 8;
            cp_async16(smem_u32(&As_w(st, row, g8 >> 1)),
                       A + (size_t)(brow + row) * K + k0 + g8);
            cp_async16(smem_u32(&Bs_w(st, row, g8 >> 1)),
                       B + (size_t)(bcol + row) * K + k0 + g8);
        }
    };

    float acc[2][8][4];
#pragma unroll
    for (int mi = 0; mi < 2; mi++)
#pragma unroll
        for (int nj = 0; nj < 8; nj++)
#pragma unroll
            for (int c = 0; c < 4; c++) acc[mi][nj][c] = 0.f;

    load_slab(0, 0);
    cp_commit();

    for (int j = 0; j < nslab; j++) {
        const int st = j & 1;
        if (j + 1 < nslab) load_slab(j + 1, st ^ 1);
        cp_commit();
        cp_wait1();
        __syncthreads();

        const uint32_t stoff = (uint32_t)st * (2 * HG_STAGE_WORDS * 4);
#pragma unroll
        for (int ks = 0; ks < 32; ks += 8) {
            uint32_t af[2][4];
            uint32_t bf[8][2];
            LDSM_X4(af[0][0], af[0][1], af[0][2], af[0][3],
                    aab + stoff + 4u * ks);
            LDSM_X4(af[1][0], af[1][1], af[1][2], af[1][3],
                    aab + stoff + 4u * (16 * 36) + 4u * ks);
#pragma unroll
            for (int njp = 0; njp < 4; njp++)
                LDSM_X4(bf[2 * njp][0], bf[2 * njp][1],
                        bf[2 * njp + 1][0], bf[2 * njp + 1][1],
                        bbb + stoff + (uint32_t)njp * (16 * 36 * 4) + 4u * ks);
#pragma unroll
            for (int mi = 0; mi < 2; mi++)
#pragma unroll
                for (int nj = 0; nj < 8; nj++)
                    MMA_F16(acc[mi][nj][0], acc[mi][nj][1],
                            acc[mi][nj][2], acc[mi][nj][3],
                            af[mi][0], af[mi][1], af[mi][2], af[mi][3],
                            bf[nj][0], bf[nj][1]);
        }
        __syncthreads();
    }

#pragma unroll
    for (int mi = 0; mi < 2; mi++) {
        int row0 = brow + warpM + mi * 16 + g;
#pragma unroll
        for (int nj = 0; nj < 8; nj++) {
            int col = bcol + warpN + nj * 8 + tig * 2;
            float2 lo, hi;
            lo.x = acc[mi][nj][0]; lo.y = acc[mi][nj][1];
            hi.x = acc[mi][nj][2]; hi.y = acc[mi][nj][3];
            *(float2*)(C + (size_t)row0 * N + col)       = lo;
            *(float2*)(C + (size_t)(row0 + 8) * N + col) = hi;
        }
    }
}

// ---------------------------------------------------------------------------
// Fused per-head RMSNorm + RoPE, cos/sin from precomputed table.
// ---------------------------------------------------------------------------
__global__ __launch_bounds__(256) void rmsnorm_rope_kernel(
    float* __restrict__ q, float* __restrict__ kbuf,
    const float* __restrict__ qw, const float* __restrict__ kw,
    const float* __restrict__ cs, const float* __restrict__ sn_t)
{
    const int t  = blockIdx.x;
    const int hi = blockIdx.y;
    const int d  = threadIdx.x;

    float* row;
    const float* w;
    if (hi < NH) { row = q    + (size_t)t * DM + hi * HD;              w = qw; }
    else         { row = kbuf + (size_t)t * (NKV * HD) + (hi - NH) * HD; w = kw; }

    float v  = row[d];
    float ss = v * v;
#pragma unroll
    for (int o = 16; o; o >>= 1) ss += __shfl_xor_sync(0xffffffffu, ss, o);

    __shared__ float red[8];
    __shared__ float s_scale;
    __shared__ float snm[256];
    if ((d & 31) == 0) red[d >> 5] = ss;
    __syncthreads();
    if (d == 0) {
        float tot = 0.f;
#pragma unroll
        for (int i = 0; i < 8; i++) tot += red[i];
        s_scale = rsqrtf(tot * (1.0f / HD) + 1e-6f);
    }
    __syncthreads();

    float nrm = v * s_scale * w[d];
    snm[d] = nrm;
    __syncthreads();

    float rot = (d & 1) ? snm[d - 1] : -snm[d + 1];
    int   fi  = d & 127;
    float cv = cs[t * 128 + fi];
    float sv = sn_t[t * 128 + fi];
    row[d] = nrm * cv + rot * sv;
}

// ---------------------------------------------------------------------------
// Flash attention, fp16 mma.sync, fp32 softmax, ldmatrix on Q/K/P loads,
// edge-only masking. Window 1024, causal. 64 queries x 1 head, 256 threads.
// ---------------------------------------------------------------------------
#define QK_PW 132
#define VT_PW 264
#define P_PW  36
#define ATTN_SMEM_WORDS (2*64*QK_PW + 32*VT_PW + 64*P_PW + 128 + 128 + 64 + 64)
#define ATTN_SMEM_BYTES (ATTN_SMEM_WORDS * 4)

__global__ __launch_bounds__(256) void attn_f16(
    const float* __restrict__ q, const float* __restrict__ k,
    const float* __restrict__ v, __half* __restrict__ yh)
{
    extern __shared__ uint32_t smw[];
    uint32_t* Qs = smw;                       // [64][132]
    uint32_t* Ks = Qs + 64 * QK_PW;           // [64][132]
    uint32_t* Vt = Ks + 64 * QK_PW;           // [32][264]
    uint32_t* Ps = Vt + 32 * VT_PW;           // [64][36]
    float* pmax = (float*)(Ps + 64 * P_PW);   // [64][2]
    float* psum = pmax + 128;                 // [64][2]
    float* m_s  = psum + 128;                 // [64]
    float* l_s  = m_s + 64;                   // [64]

    const int tid  = threadIdx.x;
    const int qb   = blockIdx.x;
    const int h    = blockIdx.y;
    const int kvh  = h >> 1;
    const int warp = tid >> 5;
    const int lane = tid & 31;
    const int g    = lane >> 2;
    const int tig  = lane & 3;
    const int wn   = warp & 1;
    const int r0   = (warp >> 1) * 16 + g;

    // ldmatrix per-lane byte addresses
    const uint32_t q_lb = smem_u32(Qs) +
        4u * (((warp >> 1) * 16 + (lane & 15)) * QK_PW + ((lane >> 4) << 2));
    const uint32_t k_lb = smem_u32(Ks) +
        4u * ((wn * 32 + (lane & 7) + ((lane >> 4) << 3)) * QK_PW
              + (((lane >> 3) & 1) << 2));
    const uint32_t p_lb = smem_u32(Ps) +
        4u * (((warp >> 1) * 16 + (lane & 15)) * P_PW + ((lane >> 4) << 2));

    if (tid < 64) { m_s[tid] = -INFINITY; l_s[tid] = 0.f; }

    for (int idx = tid; idx < 64 * 64; idx += 256) {
        int r = idx >> 6, c4 = (idx & 63) << 2;
        float4 qv = *(const float4*)(q + (size_t)(qb * 64 + r) * DM + h * HD + c4);
        uint2 o;
        o.x = pack_f16x2(qv.x, qv.y);
        o.y = pack_f16x2(qv.z, qv.w);
        *(uint2*)&Qs[r * QK_PW + (c4 >> 1)] = o;
    }

    float acc[16][4];
#pragma unroll
    for (int nj = 0; nj < 16; nj++)
#pragma unroll
        for (int c = 0; c < 4; c++) acc[nj][c] = 0.f;

    int s0 = qb * 64 - (WIN - 1);
    if (s0 < 0) s0 = 0;
    const int kt0 = s0 >> 6;
    const int qi0 = qb * 64 + r0;
    const int qi1 = qi0 + 8;

    for (int kt = kt0; kt <= qb; kt++) {
        const bool edge = (kt == qb) || (kt == kt0);
        __syncthreads();

        for (int idx = tid; idx < 64 * 64; idx += 256) {
            int r = idx >> 6, c4 = (idx & 63) << 2;
            float4 kv4 = *(const float4*)(k + (size_t)(kt * 64 + r) * (NKV * HD) + kvh * HD + c4);
            uint2 o;
            o.x = pack_f16x2(kv4.x, kv4.y);
            o.y = pack_f16x2(kv4.z, kv4.w);
            *(uint2*)&Ks[r * QK_PW + (c4 >> 1)] = o;
        }
        for (int idx = tid; idx < 32 * 64; idx += 256) {
            int kp = idx >> 6, c4 = (idx & 63) << 2;
            size_t b0 = (size_t)(kt * 64 + 2 * kp)     * (NKV * HD) + kvh * HD + c4;
            size_t b1 = (size_t)(kt * 64 + 2 * kp + 1) * (NKV * HD) + kvh * HD + c4;
            float4 lo = *(const float4*)(v + b0);
            float4 hi = *(const float4*)(v + b1);
            uint4 o;
            o.x = pack_f16x2(lo.x, hi.x);
            o.y = pack_f16x2(lo.y, hi.y);
            o.z = pack_f16x2(lo.z, hi.z);
            o.w = pack_f16x2(lo.w, hi.w);
            *(uint4*)&Vt[kp * VT_PW + c4] = o;
        }
        __syncthreads();

        // ---- S = Q @ K^T (ldmatrix + fp16 mma) ----
        float sf[4][4];
#pragma unroll
        for (int nj = 0; nj < 4; nj++)
#pragma unroll
            for (int c = 0; c < 4; c++) sf[nj][c] = 0.f;
#pragma unroll
        for (int ks = 0; ks < 128; ks += 8) {
            uint32_t a0, a1, a2, a3;
            LDSM_X4(a0, a1, a2, a3, q_lb + 4u * ks);
#pragma unroll
            for (int njp = 0; njp < 2; njp++) {
                uint32_t b00, b01, b10, b11;
                LDSM_X4(b00, b01, b10, b11,
                        k_lb + (uint32_t)njp * (16 * QK_PW * 4) + 4u * ks);
                MMA_F16(sf[2*njp][0], sf[2*njp][1], sf[2*njp][2], sf[2*njp][3],
                        a0, a1, a2, a3, b00, b01);
                MMA_F16(sf[2*njp+1][0], sf[2*njp+1][1], sf[2*njp+1][2], sf[2*njp+1][3],
                        a0, a1, a2, a3, b10, b11);
            }
        }

        // ---- scale (+ mask on edge tiles) + partial row max ----
        float mx0 = -INFINITY, mx1 = -INFINITY;
        if (edge) {
#pragma unroll
            for (int nj = 0; nj < 4; nj++) {
#pragma unroll
                for (int c = 0; c < 2; c++) {
                    int col = kt * 64 + wn * 32 + nj * 8 + 2 * tig + c;
                    float v0 = sf[nj][c] * 0.0625f;
                    v0 = (col <= qi0 && col > qi0 - WIN) ? v0 : -INFINITY;
                    sf[nj][c] = v0;
                    mx0 = fmaxf(mx0, v0);
                    float v1 = sf[nj][2 + c] * 0.0625f;
                    v1 = (col <= qi1 && col > qi1 - WIN) ? v1 : -INFINITY;
                    sf[nj][2 + c] = v1;
                    mx1 = fmaxf(mx1, v1);
                }
            }
        } else {
#pragma unroll
            for (int nj = 0; nj < 4; nj++) {
#pragma unroll
                for (int c = 0; c < 2; c++) {
                    float v0 = sf[nj][c] * 0.0625f;
                    sf[nj][c] = v0;
                    mx0 = fmaxf(mx0, v0);
                    float v1 = sf[nj][2 + c] * 0.0625f;
                    sf[nj][2 + c] = v1;
                    mx1 = fmaxf(mx1, v1);
                }
            }
        }
#pragma unroll
        for (int o = 1; o <= 2; o <<= 1) {
            mx0 = fmaxf(mx0, __shfl_xor_sync(0xffffffffu, mx0, o));
            mx1 = fmaxf(mx1, __shfl_xor_sync(0xffffffffu, mx1, o));
        }
        if (tig == 0) {
            pmax[r0 * 2 + wn]       = mx0;
            pmax[(r0 + 8) * 2 + wn] = mx1;
        }
        __syncthreads();

        float mold0 = m_s[r0], mold1 = m_s[r0 + 8];
        float mn0 = fmaxf(mold0, fmaxf(pmax[r0 * 2], pmax[r0 * 2 + 1]));
        float mn1 = fmaxf(mold1, fmaxf(pmax[(r0 + 8) * 2], pmax[(r0 + 8) * 2 + 1]));

        // ---- exp, partial sums, store P packed fp16 ----
        float sum0 = 0.f, sum1 = 0.f;
#pragma unroll
        for (int nj = 0; nj < 4; nj++) {
            float p00, p01, p10, p11;
            if (edge) {
                p00 = (sf[nj][0] == -INFINITY) ? 0.f : __expf(sf[nj][0] - mn0);
                p01 = (sf[nj][1] == -INFINITY) ? 0.f : __expf(sf[nj][1] - mn0);
                p10 = (sf[nj][2] == -INFINITY) ? 0.f : __expf(sf[nj][2] - mn1);
                p11 = (sf[nj][3] == -INFINITY) ? 0.f : __expf(sf[nj][3] - mn1);
            } else {
                p00 = __expf(sf[nj][0] - mn0);
                p01 = __expf(sf[nj][1] - mn0);
                p10 = __expf(sf[nj][2] - mn1);
                p11 = __expf(sf[nj][3] - mn1);
            }
            sum0 += p00 + p01;
            sum1 += p10 + p11;
            int wd = wn * 16 + nj * 4 + tig;
            Ps[r0 * P_PW + wd]       = pack_f16x2(p00, p01);
            Ps[(r0 + 8) * P_PW + wd] = pack_f16x2(p10, p11);
        }
#pragma unroll
        for (int o = 1; o <= 2; o <<= 1) {
            sum0 += __shfl_xor_sync(0xffffffffu, sum0, o);
            sum1 += __shfl_xor_sync(0xffffffffu, sum1, o);
        }
        if (tig == 0) {
            psum[r0 * 2 + wn]       = sum0;
            psum[(r0 + 8) * 2 + wn] = sum1;
        }
        float corr0 = (mn0 == -INFINITY) ? 1.f
                    : ((mold0 == -INFINITY) ? 0.f : __expf(mold0 - mn0));
        float corr1 = (mn1 == -INFINITY) ? 1.f
                    : ((mold1 == -INFINITY) ? 0.f : __expf(mold1 - mn1));
        __syncthreads();

        if (wn == 0 && tig == 0) {
            l_s[r0]     = l_s[r0]     * corr0 + psum[r0 * 2]       + psum[r0 * 2 + 1];
            l_s[r0 + 8] = l_s[r0 + 8] * corr1 + psum[(r0 + 8) * 2] + psum[(r0 + 8) * 2 + 1];
            m_s[r0]     = mn0;
            m_s[r0 + 8] = mn1;
        }

        // ---- O = O*corr + P @ V (ldmatrix A, scalar B) ----
#pragma unroll
        for (int nj = 0; nj < 16; nj++) {
            acc[nj][0] *= corr0; acc[nj][1] *= corr0;
            acc[nj][2] *= corr1; acc[nj][3] *= corr1;
        }
#pragma unroll
        for (int ks = 0; ks < 32; ks += 8) {
            uint32_t a0, a1, a2, a3;
            LDSM_X4(a0, a1, a2, a3, p_lb + 4u * ks);
#pragma unroll
            for (int nj = 0; nj < 16; nj++) {
                int c = wn * 128 + nj * 8 + g;
                uint32_t b0 = Vt[(ks + tig) * VT_PW + c];
                uint32_t b1 = Vt[(ks + tig + 4) * VT_PW + c];
                MMA_F16(acc[nj][0], acc[nj][1], acc[nj][2], acc[nj][3],
                        a0, a1, a2, a3, b0, b1);
            }
        }
    }

    __syncthreads();
    float inv0 = 1.f / l_s[r0];
    float inv1 = 1.f / l_s[r0 + 8];
    __half* yr0 = yh + (size_t)(qb * 64 + r0) * DM + h * HD;
    __half* yr1 = yh + (size_t)(qb * 64 + r0 + 8) * DM + h * HD;
#pragma unroll
    for (int nj = 0; nj < 16; nj++) {
        int col = wn * 128 + nj * 8 + 2 * tig;
        *(uint32_t*)(yr0 + col) = pack_f16x2(acc[nj][0] * inv0, acc[nj][1] * inv0);
        *(uint32_t*)(yr1 + col) = pack_f16x2(acc[nj][2] * inv1, acc[nj][3] * inv1);
    }
}

// ---------------------------------------------------------------------------
extern "C" void kernel_launch(void* const* d_in, const int* in_sizes, int n_in,
                              void* d_out, int out_size)
{
    const float* x  = (const float*)d_in[0];
    const int*   pos= (const int*)  d_in[1];
    const float* Wq = (const float*)d_in[2];
    const float* Wk = (const float*)d_in[3];
    const float* Wv = (const float*)d_in[4];
    const float* Wo = (const float*)d_in[5];
    const float* qw = (const float*)d_in[6];
    const float* kw = (const float*)d_in[7];
    float* out = (float*)d_out;

    float  *q_p, *k_p, *v_p, *cs_p, *sn_p;
    __half *xh_p, *wqh_p, *wkh_p, *wvh_p, *woh_p, *yh_p;
    cudaGetSymbolAddress((void**)&q_p,   g_q);
    cudaGetSymbolAddress((void**)&k_p,   g_k);
    cudaGetSymbolAddress((void**)&v_p,   g_v);
    cudaGetSymbolAddress((void**)&cs_p,  g_cs);
    cudaGetSymbolAddress((void**)&sn_p,  g_sn);
    cudaGetSymbolAddress((void**)&xh_p,  g_xh);
    cudaGetSymbolAddress((void**)&wqh_p, g_wqh);
    cudaGetSymbolAddress((void**)&wkh_p, g_wkh);
    cudaGetSymbolAddress((void**)&wvh_p, g_wvh);
    cudaGetSymbolAddress((void**)&woh_p, g_woh);
    cudaGetSymbolAddress((void**)&yh_p,  g_yh);

    // fp32 -> fp16 conversion passes + rope table
    to_half_kernel<<<(T_SEQ * DM) / 2048, 256>>>(x, xh_p, T_SEQ * DM);
    to_half_kernel<<<(DM * DM) / 2048, 256>>>(Wq, wqh_p, DM * DM);
    to_half_kernel<<<(NKV * HD * DM) / 2048, 256>>>(Wk, wkh_p, NKV * HD * DM);
    to_half_kernel<<<(NKV * HD * DM) / 2048, 256>>>(Wv, wvh_p, NKV * HD * DM);
    to_half_kernel<<<(DM * DM) / 2048, 256>>>(Wo, woh_p, DM * DM);
    rope_table_kernel<<<T_SEQ, 128>>>(pos, cs_p, sn_p);

    cudaFuncSetAttribute(hgemm, cudaFuncAttributeMaxDynamicSharedMemorySize,
                         HG_SMEM_BYTES);

    // QKV projections
    hgemm<<<dim3(DM / 128, T_SEQ / 128), 256, HG_SMEM_BYTES>>>(
        xh_p, wqh_p, q_p, T_SEQ, DM, DM);
    hgemm<<<dim3((NKV * HD) / 128, T_SEQ / 128), 256, HG_SMEM_BYTES>>>(
        xh_p, wkh_p, k_p, T_SEQ, NKV * HD, DM);
    hgemm<<<dim3((NKV * HD) / 128, T_SEQ / 128), 256, HG_SMEM_BYTES>>>(
        xh_p, wvh_p, v_p, T_SEQ, NKV * HD, DM);

    // RMSNorm + RoPE (table-driven)
    rmsnorm_rope_kernel<<<dim3(T_SEQ, NH + NKV), 256>>>(q_p, k_p, qw, kw, cs_p, sn_p);

    // Flash attention
    cudaFuncSetAttribute(attn_f16, cudaFuncAttributeMaxDynamicSharedMemorySize,
                         ATTN_SMEM_BYTES);
    attn_f16<<<dim3(T_SEQ / 64, NH), 256, ATTN_SMEM_BYTES>>>(q_p, k_p, v_p, yh_p);

    // Output projection
    hgemm<<<dim3(DM / 128, T_SEQ / 128), 256, HG_SMEM_BYTES>>>(
        yh_p, woh_p, out, T_SEQ, DM, DM);
}

// round 11
// speedup vs baseline: 5.4322x; 1.0473x over previous
#include <cuda_runtime.h>
#include <cuda_bf16.h>
#include <cuda_fp16.h>
#include <math.h>
#include <stdint.h>

#define T_SEQ 4096
#define DM    2048
#define NH    8
#define NKV   4
#define HD    256
#define WIN   1024
#define KVS   2048     // row stride of fused KV buffer (K cols 0-1023, V cols 1024-2047)

// Scratch (static __device__ arrays — allocation-free per harness rules)
__device__ float  g_q[T_SEQ * DM];            // 32 MB (Q projection, fp32 for rmsnorm)
__device__ __half g_qh[T_SEQ * DM];           // 16 MB (Q post norm+rope, fp16)
__device__ __half g_kvh[T_SEQ * KVS];         // 16 MB (K | V, fp16)
__device__ __half g_xh[T_SEQ * DM];           // 16 MB
__device__ __half g_wqh[DM * DM];             // 8 MB
__device__ __half g_wkvh[KVS * DM];           // 8 MB ([Wk; Wv] rows)
__device__ __half g_woh[DM * DM];             // 8 MB
__device__ __half g_yh[T_SEQ * DM];           // 16 MB (attention out, fp16)
__device__ float  g_cs[T_SEQ * 128];          // rope cos table
__device__ float  g_sn[T_SEQ * 128];          // rope sin table

__device__ __forceinline__ uint32_t pack_f16x2(float lo, float hi) {
    __half2 h = __floats2half2_rn(lo, hi);    // .x = lo (low 16 bits)
    return *reinterpret_cast<uint32_t*>(&h);
}

__device__ __forceinline__ uint32_t smem_u32(const void* p) {
    uint32_t a;
    asm("{ .reg .u64 t; cvta.to.shared.u64 t, %1; cvt.u32.u64 %0, t; }"
        : "=r"(a) : "l"(p));
    return a;
}
__device__ __forceinline__ void cp_async16(uint32_t dst, const void* src) {
    asm volatile("cp.async.cg.shared.global [%0], [%1], 16;" :: "r"(dst), "l"(src));
}
__device__ __forceinline__ void cp_commit() {
    asm volatile("cp.async.commit_group;" ::: "memory");
}
__device__ __forceinline__ void cp_wait1() {
    asm volatile("cp.async.wait_group 1;" ::: "memory");
}

#define MMA_F16(d0,d1,d2,d3,a0,a1,a2,a3,b0,b1)                               \
    asm volatile(                                                            \
        "mma.sync.aligned.m16n8k16.row.col.f32.f16.f16.f32 "                 \
        "{%0,%1,%2,%3}, {%4,%5,%6,%7}, {%8,%9}, {%0,%1,%2,%3};"              \
        : "+f"(d0), "+f"(d1), "+f"(d2), "+f"(d3)                             \
        : "r"(a0), "r"(a1), "r"(a2), "r"(a3), "r"(b0), "r"(b1))

#define LDSM_X4(r0,r1,r2,r3,addr)                                            \
    asm volatile("ldmatrix.sync.aligned.m8n8.x4.shared.b16 {%0,%1,%2,%3}, [%4];" \
        : "=r"(r0), "=r"(r1), "=r"(r2), "=r"(r3) : "r"(addr))

// ---------------------------------------------------------------------------
// fp32 -> fp16 conversion pass, 8 elements/thread, grid-stride.
// ---------------------------------------------------------------------------
__global__ __launch_bounds__(256) void to_half_kernel(
    const float* __restrict__ in, __half* __restrict__ out, int n)
{
    for (int i = (blockIdx.x * 256 + threadIdx.x) * 8; i < n;
         i += gridDim.x * 256 * 8) {
        float4 v0 = *(const float4*)(in + i);
        float4 v1 = *(const float4*)(in + i + 4);
        uint4 o;
        o.x = pack_f16x2(v0.x, v0.y);
        o.y = pack_f16x2(v0.z, v0.w);
        o.z = pack_f16x2(v1.x, v1.y);
        o.w = pack_f16x2(v1.z, v1.w);
        *(uint4*)((char*)out + (size_t)i * 2) = o;
    }
}

// ---------------------------------------------------------------------------
// RoPE table (bit-identical math to the original in-kernel version)
// ---------------------------------------------------------------------------
__global__ __launch_bounds__(128) void rope_table_kernel(
    const int* __restrict__ pos, float* __restrict__ cs, float* __restrict__ sn)
{
    int t = blockIdx.x, f = threadIdx.x;
    float inv_freq = expf(-(float)f * (logf(10000.0f) / 128.0f));
    float ang = (float)pos[t] * inv_freq;
    float sv, cv;
    sincosf(ang, &sv, &cv);
    cs[t * 128 + f] = cv;
    sn[t * 128 + f] = sv;
}

// ---------------------------------------------------------------------------
// FP16 tensor-core GEMM core (fp32 accum), shared by fp32-out and fp16-out
// variants. 128x128 tile, BK=64 halves, cp.async double buffered, 8 warps.
// ---------------------------------------------------------------------------
#define HG_STAGE_WORDS (128 * 36)
#define HG_SMEM_BYTES  (4 * HG_STAGE_WORDS * 4 * 2)   // 73728

template <bool HalfOut>
__device__ __forceinline__ void hgemm_body(
    const __half* __restrict__ A, const __half* __restrict__ B,
    void* __restrict__ C, int M, int N, int K)
{
    extern __shared__ uint32_t sm[];
    const int tid  = threadIdx.x;
    const int brow = blockIdx.y * 128;
    const int bcol = blockIdx.x * 128;
    const int warp = tid >> 5;
    const int lane = tid & 31;
    const int g    = lane >> 2;
    const int tig  = lane & 3;
    const int warpM = (warp >> 1) * 32;
    const int warpN = (warp & 1) * 64;
    const int nslab = K >> 6;

    const uint32_t sa = smem_u32(sm);
    const uint32_t aab = sa + 4u * ((warpM + (lane & 15)) * 36 + ((lane >> 4) << 2));
    const uint32_t bbb = sa + 4u * (HG_STAGE_WORDS
                       + (warpN + (lane & 7) + ((lane >> 4) << 3)) * 36
                       + (((lane >> 3) & 1) << 2));

    auto As_w = [&](int st, int r, int w) -> uint32_t& {
        return sm[st * 2 * HG_STAGE_WORDS + r * 36 + w];
    };
    auto Bs_w = [&](int st, int r, int w) -> uint32_t& {
        return sm[st * 2 * HG_STAGE_WORDS + HG_STAGE_WORDS + r * 36 + w];
    };

    auto load_slab = [&](int j, int st) {
        const int k0 = j << 6;
#pragma unroll
        for (int i = 0; i < 4; i++) {
            int id  = tid + i * 256;
            int row = id >> 3;
            int g8  = (id & 7) * 8;
            cp_async16(smem_u32(&As_w(st, row, g8 >> 1)),
                       A + (size_t)(brow + row) * K + k0 + g8);
            cp_async16(smem_u32(&Bs_w(st, row, g8 >> 1)),
                       B + (size_t)(bcol + row) * K + k0 + g8);
        }
    };

    float acc[2][8][4];
#pragma unroll
    for (int mi = 0; mi < 2; mi++)
#pragma unroll
        for (int nj = 0; nj < 8; nj++)
#pragma unroll
            for (int c = 0; c < 4; c++) acc[mi][nj][c] = 0.f;

    load_slab(0, 0);
    cp_commit();

    for (int j = 0; j < nslab; j++) {
        const int st = j & 1;
        if (j + 1 < nslab) load_slab(j + 1, st ^ 1);
        cp_commit();
        cp_wait1();
        __syncthreads();

        const uint32_t stoff = (uint32_t)st * (2 * HG_STAGE_WORDS * 4);
#pragma unroll
        for (int ks = 0; ks < 32; ks += 8) {
            uint32_t af[2][4];
            uint32_t bf[8][2];
            LDSM_X4(af[0][0], af[0][1], af[0][2], af[0][3],
                    aab + stoff + 4u * ks);
            LDSM_X4(af[1][0], af[1][1], af[1][2], af[1][3],
                    aab + stoff + 4u * (16 * 36) + 4u * ks);
#pragma unroll
            for (int njp = 0; njp < 4; njp++)
                LDSM_X4(bf[2 * njp][0], bf[2 * njp][1],
                        bf[2 * njp + 1][0], bf[2 * njp + 1][1],
                        bbb + stoff + (uint32_t)njp * (16 * 36 * 4) + 4u * ks);
#pragma unroll
            for (int mi = 0; mi < 2; mi++)
#pragma unroll
                for (int nj = 0; nj < 8; nj++)
                    MMA_F16(acc[mi][nj][0], acc[mi][nj][1],
                            acc[mi][nj][2], acc[mi][nj][3],
                            af[mi][0], af[mi][1], af[mi][2], af[mi][3],
                            bf[nj][0], bf[nj][1]);
        }
        __syncthreads();
    }

#pragma unroll
    for (int mi = 0; mi < 2; mi++) {
        int row0 = brow + warpM + mi * 16 + g;
#pragma unroll
        for (int nj = 0; nj < 8; nj++) {
            int col = bcol + warpN + nj * 8 + tig * 2;
            if (HalfOut) {
                __half* Ch = (__half*)C;
                *(uint32_t*)(Ch + (size_t)row0 * N + col) =
                    pack_f16x2(acc[mi][nj][0], acc[mi][nj][1]);
                *(uint32_t*)(Ch + (size_t)(row0 + 8) * N + col) =
                    pack_f16x2(acc[mi][nj][2], acc[mi][nj][3]);
            } else {
                float* Cf = (float*)C;
                float2 lo, hi;
                lo.x = acc[mi][nj][0]; lo.y = acc[mi][nj][1];
                hi.x = acc[mi][nj][2]; hi.y = acc[mi][nj][3];
                *(float2*)(Cf + (size_t)row0 * N + col)       = lo;
                *(float2*)(Cf + (size_t)(row0 + 8) * N + col) = hi;
            }
        }
    }
}

__global__ __launch_bounds__(256, 2) void hgemm_f32(
    const __half* __restrict__ A, const __half* __restrict__ B,
    float* __restrict__ C, int M, int N, int K)
{
    hgemm_body<false>(A, B, C, M, N, K);
}

__global__ __launch_bounds__(256, 2) void hgemm_f16(
    const __half* __restrict__ A, const __half* __restrict__ B,
    __half* __restrict__ C, int M, int N, int K)
{
    hgemm_body<true>(A, B, C, M, N, K);
}

// ---------------------------------------------------------------------------
// Fused per-head RMSNorm + RoPE.
// hi < NH : read fp32 g_q, write fp16 g_qh (same rounding attention used to do)
// hi >= NH: in-place on fp16 K columns of g_kvh
// ---------------------------------------------------------------------------
__global__ __launch_bounds__(256) void rmsnorm_rope_kernel(
    const float* __restrict__ q, __half* __restrict__ qh,
    __half* __restrict__ kv,
    const float* __restrict__ qw, const float* __restrict__ kw,
    const float* __restrict__ cs, const float* __restrict__ sn_t)
{
    const int t  = blockIdx.x;
    const int hi = blockIdx.y;
    const int d  = threadIdx.x;

    float v;
    const float* w;
    __half* krow = 0;
    if (hi < NH) {
        v = q[(size_t)t * DM + hi * HD + d];
        w = qw;
    } else {
        krow = kv + (size_t)t * KVS + (hi - NH) * HD;
        v = __half2float(krow[d]);
        w = kw;
    }

    float ss = v * v;
#pragma unroll
    for (int o = 16; o; o >>= 1) ss += __shfl_xor_sync(0xffffffffu, ss, o);

    __shared__ float red[8];
    __shared__ float s_scale;
    __shared__ float snm[256];
    if ((d & 31) == 0) red[d >> 5] = ss;
    __syncthreads();
    if (d == 0) {
        float tot = 0.f;
#pragma unroll
        for (int i = 0; i < 8; i++) tot += red[i];
        s_scale = rsqrtf(tot * (1.0f / HD) + 1e-6f);
    }
    __syncthreads();

    float nrm = v * s_scale * w[d];
    snm[d] = nrm;
    __syncthreads();

    float rot = (d & 1) ? snm[d - 1] : -snm[d + 1];
    int   fi  = d & 127;
    float cv = cs[t * 128 + fi];
    float sv = sn_t[t * 128 + fi];
    float res = nrm * cv + rot * sv;

    if (hi < NH) qh[(size_t)t * DM + hi * HD + d] = __float2half(res);
    else         krow[d] = __float2half(res);
}

// ---------------------------------------------------------------------------
// Flash attention, fp16 in / fp16 mma / fp32 softmax / fp16 out.
// Q/K tiles: raw uint4 copies (fp16 row-major == packed K-pair layout).
// V tile: row-pair interleave via __byte_perm.
// ---------------------------------------------------------------------------
#define QK_PW 132
#define VT_PW 264
#define P_PW  36
#define ATTN_SMEM_WORDS (2*64*QK_PW + 32*VT_PW + 64*P_PW + 128 + 128 + 64 + 64)
#define ATTN_SMEM_BYTES (ATTN_SMEM_WORDS * 4)

__global__ __launch_bounds__(256) void attn_f16(
    const __half* __restrict__ qh, const __half* __restrict__ kv,
    __half* __restrict__ yh)
{
    extern __shared__ uint32_t smw[];
    uint32_t* Qs = smw;                       // [64][132]
    uint32_t* Ks = Qs + 64 * QK_PW;           // [64][132]
    uint32_t* Vt = Ks + 64 * QK_PW;           // [32][264]
    uint32_t* Ps = Vt + 32 * VT_PW;           // [64][36]
    float* pmax = (float*)(Ps + 64 * P_PW);   // [64][2]
    float* psum = pmax + 128;                 // [64][2]
    float* m_s  = psum + 128;                 // [64]
    float* l_s  = m_s + 64;                   // [64]

    const int tid  = threadIdx.x;
    const int qb   = blockIdx.x;
    const int h    = blockIdx.y;
    const int kvi  = h >> 1;
    const int warp = tid >> 5;
    const int lane = tid & 31;
    const int g    = lane >> 2;
    const int tig  = lane & 3;
    const int wn   = warp & 1;
    const int r0   = (warp >> 1) * 16 + g;

    const uint32_t q_lb = smem_u32(Qs) +
        4u * (((warp >> 1) * 16 + (lane & 15)) * QK_PW + ((lane >> 4) << 2));
    const uint32_t k_lb = smem_u32(Ks) +
        4u * ((wn * 32 + (lane & 7) + ((lane >> 4) << 3)) * QK_PW
              + (((lane >> 3) & 1) << 2));
    const uint32_t p_lb = smem_u32(Ps) +
        4u * (((warp >> 1) * 16 + (lane & 15)) * P_PW + ((lane >> 4) << 2));

    if (tid < 64) { m_s[tid] = -INFINITY; l_s[tid] = 0.f; }

    // Q tile: raw copy (64 rows x 32 uint4)
    for (int idx = tid; idx < 64 * 32; idx += 256) {
        int r = idx >> 5, c = (idx & 31);
        uint4 o = *(const uint4*)(qh + (size_t)(qb * 64 + r) * DM + h * HD + c * 8);
        *(uint4*)&Qs[r * QK_PW + c * 4] = o;
    }

    float acc[16][4];
#pragma unroll
    for (int nj = 0; nj < 16; nj++)
#pragma unroll
        for (int c = 0; c < 4; c++) acc[nj][c] = 0.f;

    int s0 = qb * 64 - (WIN - 1);
    if (s0 < 0) s0 = 0;
    const int kt0 = s0 >> 6;
    const int qi0 = qb * 64 + r0;
    const int qi1 = qi0 + 8;

    for (int kt = kt0; kt <= qb; kt++) {
        const bool edge = (kt == qb) || (kt == kt0);
        __syncthreads();

        // K tile: raw copy
        for (int idx = tid; idx < 64 * 32; idx += 256) {
            int r = idx >> 5, c = (idx & 31);
            uint4 o = *(const uint4*)(kv + (size_t)(kt * 64 + r) * KVS + kvi * HD + c * 8);
            *(uint4*)&Ks[r * QK_PW + c * 4] = o;
        }
        // V tile: row-pair interleave via prmt
        for (int idx = tid; idx < 32 * 32; idx += 256) {
            int kp = idx >> 5, dg = (idx & 31) * 8;   // 8 head-dims per chunk
            const __half* v0p = kv + (size_t)(kt * 64 + 2 * kp) * KVS + 1024 + kvi * HD + dg;
            uint4 A = *(const uint4*)v0p;
            uint4 B = *(const uint4*)(v0p + KVS);
            uint32_t* dst = &Vt[kp * VT_PW + dg];
            dst[0] = __byte_perm(A.x, B.x, 0x5410);
            dst[1] = __byte_perm(A.x, B.x, 0x7632);
            dst[2] = __byte_perm(A.y, B.y, 0x5410);
            dst[3] = __byte_perm(A.y, B.y, 0x7632);
            dst[4] = __byte_perm(A.z, B.z, 0x5410);
            dst[5] = __byte_perm(A.z, B.z, 0x7632);
            dst[6] = __byte_perm(A.w, B.w, 0x5410);
            dst[7] = __byte_perm(A.w, B.w, 0x7632);
        }
        __syncthreads();

        // ---- S = Q @ K^T ----
        float sf[4][4];
#pragma unroll
        for (int nj = 0; nj < 4; nj++)
#pragma unroll
            for (int c = 0; c < 4; c++) sf[nj][c] = 0.f;
#pragma unroll
        for (int ks = 0; ks < 128; ks += 8) {
            uint32_t a0, a1, a2, a3;
            LDSM_X4(a0, a1, a2, a3, q_lb + 4u * ks);
#pragma unroll
            for (int njp = 0; njp < 2; njp++) {
                uint32_t b00, b01, b10, b11;
                LDSM_X4(b00, b01, b10, b11,
                        k_lb + (uint32_t)njp * (16 * QK_PW * 4) + 4u * ks);
                MMA_F16(sf[2*njp][0], sf[2*njp][1], sf[2*njp][2], sf[2*njp][3],
                        a0, a1, a2, a3, b00, b01);
                MMA_F16(sf[2*njp+1][0], sf[2*njp+1][1], sf[2*njp+1][2], sf[2*njp+1][3],
                        a0, a1, a2, a3, b10, b11);
            }
        }

        // ---- scale (+ mask on edge tiles) + partial row max ----
        float mx0 = -INFINITY, mx1 = -INFINITY;
        if (edge) {
#pragma unroll
            for (int nj = 0; nj < 4; nj++) {
#pragma unroll
                for (int c = 0; c < 2; c++) {
                    int col = kt * 64 + wn * 32 + nj * 8 + 2 * tig + c;
                    float v0 = sf[nj][c] * 0.0625f;
                    v0 = (col <= qi0 && col > qi0 - WIN) ? v0 : -INFINITY;
                    sf[nj][c] = v0;
                    mx0 = fmaxf(mx0, v0);
                    float v1 = sf[nj][2 + c] * 0.0625f;
                    v1 = (col <= qi1 && col > qi1 - WIN) ? v1 : -INFINITY;
                    sf[nj][2 + c] = v1;
                    mx1 = fmaxf(mx1, v1);
                }
            }
        } else {
#pragma unroll
            for (int nj = 0; nj < 4; nj++) {
#pragma unroll
                for (int c = 0; c < 2; c++) {
                    float v0 = sf[nj][c] * 0.0625f;
                    sf[nj][c] = v0;
                    mx0 = fmaxf(mx0, v0);
                    float v1 = sf[nj][2 + c] * 0.0625f;
                    sf[nj][2 + c] = v1;
                    mx1 = fmaxf(mx1, v1);
                }
            }
        }
#pragma unroll
        for (int o = 1; o <= 2; o <<= 1) {
            mx0 = fmaxf(mx0, __shfl_xor_sync(0xffffffffu, mx0, o));
            mx1 = fmaxf(mx1, __shfl_xor_sync(0xffffffffu, mx1, o));
        }
        if (tig == 0) {
            pmax[r0 * 2 + wn]       = mx0;
            pmax[(r0 + 8) * 2 + wn] = mx1;
        }
        __syncthreads();

        float mold0 = m_s[r0], mold1 = m_s[r0 + 8];
        float mn0 = fmaxf(mold0, fmaxf(pmax[r0 * 2], pmax[r0 * 2 + 1]));
        float mn1 = fmaxf(mold1, fmaxf(pmax[(r0 + 8) * 2], pmax[(r0 + 8) * 2 + 1]));

        // ---- exp, partial sums, store P packed fp16 ----
        float sum0 = 0.f, sum1 = 0.f;
#pragma unroll
        for (int nj = 0; nj < 4; nj++) {
            float p00, p01, p10, p11;
            if (edge) {
                p00 = (sf[nj][0] == -INFINITY) ? 0.f : __expf(sf[nj][0] - mn0);
                p01 = (sf[nj][1] == -INFINITY) ? 0.f : __expf(sf[nj][1] - mn0);
                p10 = (sf[nj][2] == -INFINITY) ? 0.f : __expf(sf[nj][2] - mn1);
                p11 = (sf[nj][3] == -INFINITY) ? 0.f : __expf(sf[nj][3] - mn1);
            } else {
                p00 = __expf(sf[nj][0] - mn0);
                p01 = __expf(sf[nj][1] - mn0);
                p10 = __expf(sf[nj][2] - mn1);
                p11 = __expf(sf[nj][3] - mn1);
            }
            sum0 += p00 + p01;
            sum1 += p10 + p11;
            int wd = wn * 16 + nj * 4 + tig;
            Ps[r0 * P_PW + wd]       = pack_f16x2(p00, p01);
            Ps[(r0 + 8) * P_PW + wd] = pack_f16x2(p10, p11);
        }
#pragma unroll
        for (int o = 1; o <= 2; o <<= 1) {
            sum0 += __shfl_xor_sync(0xffffffffu, sum0, o);
            sum1 += __shfl_xor_sync(0xffffffffu, sum1, o);
        }
        if (tig == 0) {
            psum[r0 * 2 + wn]       = sum0;
            psum[(r0 + 8) * 2 + wn] = sum1;
        }
        float corr0 = (mn0 == -INFINITY) ? 1.f
                    : ((mold0 == -INFINITY) ? 0.f : __expf(mold0 - mn0));
        float corr1 = (mn1 == -INFINITY) ? 1.f
                    : ((mold1 == -INFINITY) ? 0.f : __expf(mold1 - mn1));
        __syncthreads();

        if (wn == 0 && tig == 0) {
            l_s[r0]     = l_s[r0]     * corr0 + psum[r0 * 2]       + psum[r0 * 2 + 1];
            l_s[r0 + 8] = l_s[r0 + 8] * corr1 + psum[(r0 + 8) * 2] + psum[(r0 + 8) * 2 + 1];
            m_s[r0]     = mn0;
            m_s[r0 + 8] = mn1;
        }

        // ---- O = O*corr + P @ V ----
#pragma unroll
        for (int nj = 0; nj < 16; nj++) {
            acc[nj][0] *= corr0; acc[nj][1] *= corr0;
            acc[nj][2] *= corr1; acc[nj][3] *= corr1;
        }
#pragma unroll
        for (int ks = 0; ks < 32; ks += 8) {
            uint32_t a0, a1, a2, a3;
            LDSM_X4(a0, a1, a2, a3, p_lb + 4u * ks);
#pragma unroll
            for (int nj = 0; nj < 16; nj++) {
                int c = wn * 128 + nj * 8 + g;
                uint32_t b0 = Vt[(ks + tig) * VT_PW + c];
                uint32_t b1 = Vt[(ks + tig + 4) * VT_PW + c];
                MMA_F16(acc[nj][0], acc[nj][1], acc[nj][2], acc[nj][3],
                        a0, a1, a2, a3, b0, b1);
            }
        }
    }

    __syncthreads();
    float inv0 = 1.f / l_s[r0];
    float inv1 = 1.f / l_s[r0 + 8];
    __half* yr0 = yh + (size_t)(qb * 64 + r0) * DM + h * HD;
    __half* yr1 = yh + (size_t)(qb * 64 + r0 + 8) * DM + h * HD;
#pragma unroll
    for (int nj = 0; nj < 16; nj++) {
        int col = wn * 128 + nj * 8 + 2 * tig;
        *(uint32_t*)(yr0 + col) = pack_f16x2(acc[nj][0] * inv0, acc[nj][1] * inv0);
        *(uint32_t*)(yr1 + col) = pack_f16x2(acc[nj][2] * inv1, acc[nj][3] * inv1);
    }
}

// ---------------------------------------------------------------------------
extern "C" void kernel_launch(void* const* d_in, const int* in_sizes, int n_in,
                              void* d_out, int out_size)
{
    const float* x  = (const float*)d_in[0];
    const int*   pos= (const int*)  d_in[1];
    const float* Wq = (const float*)d_in[2];
    const float* Wk = (const float*)d_in[3];
    const float* Wv = (const float*)d_in[4];
    const float* Wo = (const float*)d_in[5];
    const float* qw = (const float*)d_in[6];
    const float* kw = (const float*)d_in[7];
    float* out = (float*)d_out;

    float  *q_p, *cs_p, *sn_p;
    __half *qh_p, *kvh_p, *xh_p, *wqh_p, *wkvh_p, *woh_p, *yh_p;
    cudaGetSymbolAddress((void**)&q_p,    g_q);
    cudaGetSymbolAddress((void**)&qh_p,   g_qh);
    cudaGetSymbolAddress((void**)&kvh_p,  g_kvh);
    cudaGetSymbolAddress((void**)&cs_p,   g_cs);
    cudaGetSymbolAddress((void**)&sn_p,   g_sn);
    cudaGetSymbolAddress((void**)&xh_p,   g_xh);
    cudaGetSymbolAddress((void**)&wqh_p,  g_wqh);
    cudaGetSymbolAddress((void**)&wkvh_p, g_wkvh);
    cudaGetSymbolAddress((void**)&woh_p,  g_woh);
    cudaGetSymbolAddress((void**)&yh_p,   g_yh);

    // fp32 -> fp16 converts (Wk/Wv concatenated into one KV weight) + rope table
    to_half_kernel<<<(T_SEQ * DM) / 2048, 256>>>(x, xh_p, T_SEQ * DM);
    to_half_kernel<<<(DM * DM) / 2048, 256>>>(Wq, wqh_p, DM * DM);
    to_half_kernel<<<(NKV * HD * DM) / 2048, 256>>>(Wk, wkvh_p, NKV * HD * DM);
    to_half_kernel<<<(NKV * HD * DM) / 2048, 256>>>(Wv, wkvh_p + (size_t)NKV * HD * DM,
                                                    NKV * HD * DM);
    to_half_kernel<<<(DM * DM) / 2048, 256>>>(Wo, woh_p, DM * DM);
    rope_table_kernel<<<T_SEQ, 128>>>(pos, cs_p, sn_p);

    cudaFuncSetAttribute(hgemm_f32, cudaFuncAttributeMaxDynamicSharedMemorySize,
                         HG_SMEM_BYTES);
    cudaFuncSetAttribute(hgemm_f16, cudaFuncAttributeMaxDynamicSharedMemorySize,
                         HG_SMEM_BYTES);

    // Q projection (fp32 out, rmsnorm reads it) + fused KV projection (fp16 out)
    hgemm_f32<<<dim3(DM / 128, T_SEQ / 128), 256, HG_SMEM_BYTES>>>(
        xh_p, wqh_p, q_p, T_SEQ, DM, DM);
    hgemm_f16<<<dim3(KVS / 128, T_SEQ / 128), 256, HG_SMEM_BYTES>>>(
        xh_p, wkvh_p, kvh_p, T_SEQ, KVS, DM);

    // RMSNorm + RoPE: Q fp32->fp16, K in-place fp16
    rmsnorm_rope_kernel<<<dim3(T_SEQ, NH + NKV), 256>>>(
        q_p, qh_p, kvh_p, qw, kw, cs_p, sn_p);

    // Flash attention (all-fp16 data path)
    cudaFuncSetAttribute(attn_f16, cudaFuncAttributeMaxDynamicSharedMemorySize,
                         ATTN_SMEM_BYTES);
    attn_f16<<<dim3(T_SEQ / 64, NH), 256, ATTN_SMEM_BYTES>>>(qh_p, kvh_p, yh_p);

    // Output projection (fp32 out -> d_out)
    hgemm_f32<<<dim3(DM / 128, T_SEQ / 128), 256, HG_SMEM_BYTES>>>(
        yh_p, woh_p, out, T_SEQ, DM, DM);
}

// round 12
// speedup vs baseline: 5.7413x; 1.0569x over previous
#include <cuda_runtime.h>
#include <cuda_bf16.h>
#include <cuda_fp16.h>
#include <math.h>
#include <stdint.h>

#define T_SEQ 4096
#define DM    2048
#define NH    8
#define NKV   4
#define HD    256
#define WIN   1024
#define QKVS  4096     // fused row: Q[0,2048) | K[2048,3072) | V[3072,4096)

// Scratch (static __device__ arrays — allocation-free per harness rules)
__device__ __half g_qkvh[T_SEQ * QKVS];       // 32 MB fused QKV (fp16)
__device__ __half g_xh[T_SEQ * DM];           // 16 MB
__device__ __half g_wqkvh[QKVS * DM];         // 16 MB [Wq; Wk; Wv]
__device__ __half g_woh[DM * DM];             // 8 MB
__device__ __half g_yh[T_SEQ * DM];           // 16 MB (attention out, fp16)
__device__ float  g_cs[T_SEQ * 128];          // rope cos table
__device__ float  g_sn[T_SEQ * 128];          // rope sin table

__device__ __forceinline__ uint32_t pack_f16x2(float lo, float hi) {
    __half2 h = __floats2half2_rn(lo, hi);    // .x = lo (low 16 bits)
    return *reinterpret_cast<uint32_t*>(&h);
}

__device__ __forceinline__ uint32_t smem_u32(const void* p) {
    uint32_t a;
    asm("{ .reg .u64 t; cvta.to.shared.u64 t, %1; cvt.u32.u64 %0, t; }"
        : "=r"(a) : "l"(p));
    return a;
}
__device__ __forceinline__ void cp_async16(uint32_t dst, const void* src) {
    asm volatile("cp.async.cg.shared.global [%0], [%1], 16;" :: "r"(dst), "l"(src));
}
__device__ __forceinline__ void cp_commit() {
    asm volatile("cp.async.commit_group;" ::: "memory");
}
__device__ __forceinline__ void cp_wait1() {
    asm volatile("cp.async.wait_group 1;" ::: "memory");
}

#define MMA_F16(d0,d1,d2,d3,a0,a1,a2,a3,b0,b1)                               \
    asm volatile(                                                            \
        "mma.sync.aligned.m16n8k16.row.col.f32.f16.f16.f32 "                 \
        "{%0,%1,%2,%3}, {%4,%5,%6,%7}, {%8,%9}, {%0,%1,%2,%3};"              \
        : "+f"(d0), "+f"(d1), "+f"(d2), "+f"(d3)                             \
        : "r"(a0), "r"(a1), "r"(a2), "r"(a3), "r"(b0), "r"(b1))

#define LDSM_X4(r0,r1,r2,r3,addr)                                            \
    asm volatile("ldmatrix.sync.aligned.m8n8.x4.shared.b16 {%0,%1,%2,%3}, [%4];" \
        : "=r"(r0), "=r"(r1), "=r"(r2), "=r"(r3) : "r"(addr))

// ---------------------------------------------------------------------------
// fp32 -> fp16 conversion pass, 8 elements/thread, grid-stride.
// ---------------------------------------------------------------------------
__global__ __launch_bounds__(256) void to_half_kernel(
    const float* __restrict__ in, __half* __restrict__ out, int n)
{
    for (int i = (blockIdx.x * 256 + threadIdx.x) * 8; i < n;
         i += gridDim.x * 256 * 8) {
        float4 v0 = *(const float4*)(in + i);
        float4 v1 = *(const float4*)(in + i + 4);
        uint4 o;
        o.x = pack_f16x2(v0.x, v0.y);
        o.y = pack_f16x2(v0.z, v0.w);
        o.z = pack_f16x2(v1.x, v1.y);
        o.w = pack_f16x2(v1.z, v1.w);
        *(uint4*)((char*)out + (size_t)i * 2) = o;
    }
}

// ---------------------------------------------------------------------------
// RoPE table (bit-identical math to the original in-kernel version)
// ---------------------------------------------------------------------------
__global__ __launch_bounds__(128) void rope_table_kernel(
    const int* __restrict__ pos, float* __restrict__ cs, float* __restrict__ sn)
{
    int t = blockIdx.x, f = threadIdx.x;
    float inv_freq = expf(-(float)f * (logf(10000.0f) / 128.0f));
    float ang = (float)pos[t] * inv_freq;
    float sv, cv;
    sincosf(ang, &sv, &cv);
    cs[t * 128 + f] = cv;
    sn[t * 128 + f] = sv;
}

// ---------------------------------------------------------------------------
// FP16 tensor-core GEMM core (fp32 accum). 128x128 tile, BK=64 halves,
// cp.async double buffered, ldmatrix fragments, 8 warps (4m x 2n).
// ---------------------------------------------------------------------------
#define HG_STAGE_WORDS (128 * 36)
#define HG_SMEM_BYTES  (4 * HG_STAGE_WORDS * 4 * 2)   // 73728

template <bool HalfOut>
__device__ __forceinline__ void hgemm_body(
    const __half* __restrict__ A, const __half* __restrict__ B,
    void* __restrict__ C, int M, int N, int K)
{
    extern __shared__ uint32_t sm[];
    const int tid  = threadIdx.x;
    const int brow = blockIdx.y * 128;
    const int bcol = blockIdx.x * 128;
    const int warp = tid >> 5;
    const int lane = tid & 31;
    const int g    = lane >> 2;
    const int tig  = lane & 3;
    const int warpM = (warp >> 1) * 32;
    const int warpN = (warp & 1) * 64;
    const int nslab = K >> 6;

    const uint32_t sa = smem_u32(sm);
    const uint32_t aab = sa + 4u * ((warpM + (lane & 15)) * 36 + ((lane >> 4) << 2));
    const uint32_t bbb = sa + 4u * (HG_STAGE_WORDS
                       + (warpN + (lane & 7) + ((lane >> 4) << 3)) * 36
                       + (((lane >> 3) & 1) << 2));

    auto As_w = [&](int st, int r, int w) -> uint32_t& {
        return sm[st * 2 * HG_STAGE_WORDS + r * 36 + w];
    };
    auto Bs_w = [&](int st, int r, int w) -> uint32_t& {
        return sm[st * 2 * HG_STAGE_WORDS + HG_STAGE_WORDS + r * 36 + w];
    };

    auto load_slab = [&](int j, int st) {
        const int k0 = j << 6;
#pragma unroll
        for (int i = 0; i < 4; i++) {
            int id  = tid + i * 256;
            int row = id >> 3;
            int g8  = (id & 7) * 8;
            cp_async16(smem_u32(&As_w(st, row, g8 >> 1)),
                       A + (size_t)(brow + row) * K + k0 + g8);
            cp_async16(smem_u32(&Bs_w(st, row, g8 >> 1)),
                       B + (size_t)(bcol + row) * K + k0 + g8);
        }
    };

    float acc[2][8][4];
#pragma unroll
    for (int mi = 0; mi < 2; mi++)
#pragma unroll
        for (int nj = 0; nj < 8; nj++)
#pragma unroll
            for (int c = 0; c < 4; c++) acc[mi][nj][c] = 0.f;

    load_slab(0, 0);
    cp_commit();

    for (int j = 0; j < nslab; j++) {
        const int st = j & 1;
        if (j + 1 < nslab) load_slab(j + 1, st ^ 1);
        cp_commit();
        cp_wait1();
        __syncthreads();

        const uint32_t stoff = (uint32_t)st * (2 * HG_STAGE_WORDS * 4);
#pragma unroll
        for (int ks = 0; ks < 32; ks += 8) {
            uint32_t af[2][4];
            uint32_t bf[8][2];
            LDSM_X4(af[0][0], af[0][1], af[0][2], af[0][3],
                    aab + stoff + 4u * ks);
            LDSM_X4(af[1][0], af[1][1], af[1][2], af[1][3],
                    aab + stoff + 4u * (16 * 36) + 4u * ks);
#pragma unroll
            for (int njp = 0; njp < 4; njp++)
                LDSM_X4(bf[2 * njp][0], bf[2 * njp][1],
                        bf[2 * njp + 1][0], bf[2 * njp + 1][1],
                        bbb + stoff + (uint32_t)njp * (16 * 36 * 4) + 4u * ks);
#pragma unroll
            for (int mi = 0; mi < 2; mi++)
#pragma unroll
                for (int nj = 0; nj < 8; nj++)
                    MMA_F16(acc[mi][nj][0], acc[mi][nj][1],
                            acc[mi][nj][2], acc[mi][nj][3],
                            af[mi][0], af[mi][1], af[mi][2], af[mi][3],
                            bf[nj][0], bf[nj][1]);
        }
        __syncthreads();
    }

#pragma unroll
    for (int mi = 0; mi < 2; mi++) {
        int row0 = brow + warpM + mi * 16 + g;
#pragma unroll
        for (int nj = 0; nj < 8; nj++) {
            int col = bcol + warpN + nj * 8 + tig * 2;
            if (HalfOut) {
                __half* Ch = (__half*)C;
                *(uint32_t*)(Ch + (size_t)row0 * N + col) =
                    pack_f16x2(acc[mi][nj][0], acc[mi][nj][1]);
                *(uint32_t*)(Ch + (size_t)(row0 + 8) * N + col) =
                    pack_f16x2(acc[mi][nj][2], acc[mi][nj][3]);
            } else {
                float* Cf = (float*)C;
                float2 lo, hi;
                lo.x = acc[mi][nj][0]; lo.y = acc[mi][nj][1];
                hi.x = acc[mi][nj][2]; hi.y = acc[mi][nj][3];
                *(float2*)(Cf + (size_t)row0 * N + col)       = lo;
                *(float2*)(Cf + (size_t)(row0 + 8) * N + col) = hi;
            }
        }
    }
}

__global__ __launch_bounds__(256, 2) void hgemm_f32(
    const __half* __restrict__ A, const __half* __restrict__ B,
    float* __restrict__ C, int M, int N, int K)
{
    hgemm_body<false>(A, B, C, M, N, K);
}

__global__ __launch_bounds__(256, 2) void hgemm_f16(
    const __half* __restrict__ A, const __half* __restrict__ B,
    __half* __restrict__ C, int M, int N, int K)
{
    hgemm_body<true>(A, B, C, M, N, K);
}

// ---------------------------------------------------------------------------
// Fused per-head RMSNorm + RoPE, in place on fp16 fused QKV buffer.
// hi < NH: Q head hi (cols hi*256). hi >= NH: K head hi-NH (cols 2048+...).
// ---------------------------------------------------------------------------
__global__ __launch_bounds__(256) void rmsnorm_rope_kernel(
    __half* __restrict__ qkv,
    const float* __restrict__ qw, const float* __restrict__ kw,
    const float* __restrict__ cs, const float* __restrict__ sn_t)
{
    const int t  = blockIdx.x;
    const int hi = blockIdx.y;
    const int d  = threadIdx.x;

    __half* row;
    const float* w;
    if (hi < NH) { row = qkv + (size_t)t * QKVS + hi * HD;              w = qw; }
    else         { row = qkv + (size_t)t * QKVS + 2048 + (hi - NH) * HD; w = kw; }

    float v = __half2float(row[d]);
    float ss = v * v;
#pragma unroll
    for (int o = 16; o; o >>= 1) ss += __shfl_xor_sync(0xffffffffu, ss, o);

    __shared__ float red[8];
    __shared__ float s_scale;
    __shared__ float snm[256];
    if ((d & 31) == 0) red[d >> 5] = ss;
    __syncthreads();
    if (d == 0) {
        float tot = 0.f;
#pragma unroll
        for (int i = 0; i < 8; i++) tot += red[i];
        s_scale = rsqrtf(tot * (1.0f / HD) + 1e-6f);
    }
    __syncthreads();

    float nrm = v * s_scale * w[d];
    snm[d] = nrm;
    __syncthreads();

    float rot = (d & 1) ? snm[d - 1] : -snm[d + 1];
    int   fi  = d & 127;
    float cv = cs[t * 128 + fi];
    float sv = sn_t[t * 128 + fi];
    row[d] = __float2half(nrm * cv + rot * sv);
}

// ---------------------------------------------------------------------------
// Flash attention, fp16 end-to-end data path, fp32 softmax, 2 CTAs/SM.
// ---------------------------------------------------------------------------
#define QK_PW 132
#define VT_PW 264
#define P_PW  36
#define ATTN_SMEM_WORDS (2*64*QK_PW + 32*VT_PW + 64*P_PW + 128 + 128 + 64 + 64)
#define ATTN_SMEM_BYTES (ATTN_SMEM_WORDS * 4)

__global__ __launch_bounds__(256, 2) void attn_f16(
    const __half* __restrict__ qkv, __half* __restrict__ yh)
{
    extern __shared__ uint32_t smw[];
    uint32_t* Qs = smw;                       // [64][132]
    uint32_t* Ks = Qs + 64 * QK_PW;           // [64][132]
    uint32_t* Vt = Ks + 64 * QK_PW;           // [32][264]
    uint32_t* Ps = Vt + 32 * VT_PW;           // [64][36]
    float* pmax = (float*)(Ps + 64 * P_PW);   // [64][2]
    float* psum = pmax + 128;                 // [64][2]
    float* m_s  = psum + 128;                 // [64]
    float* l_s  = m_s + 64;                   // [64]

    const int tid  = threadIdx.x;
    const int qb   = blockIdx.x;
    const int h    = blockIdx.y;
    const int kvi  = h >> 1;
    const int warp = tid >> 5;
    const int lane = tid & 31;
    const int g    = lane >> 2;
    const int tig  = lane & 3;
    const int wn   = warp & 1;
    const int r0   = (warp >> 1) * 16 + g;

    const uint32_t q_lb = smem_u32(Qs) +
        4u * (((warp >> 1) * 16 + (lane & 15)) * QK_PW + ((lane >> 4) << 2));
    const uint32_t k_lb = smem_u32(Ks) +
        4u * ((wn * 32 + (lane & 7) + ((lane >> 4) << 3)) * QK_PW
              + (((lane >> 3) & 1) << 2));
    const uint32_t p_lb = smem_u32(Ps) +
        4u * (((warp >> 1) * 16 + (lane & 15)) * P_PW + ((lane >> 4) << 2));

    if (tid < 64) { m_s[tid] = -INFINITY; l_s[tid] = 0.f; }

    // Q tile: raw copy from fused buffer
    for (int idx = tid; idx < 64 * 32; idx += 256) {
        int r = idx >> 5, c = (idx & 31);
        uint4 o = *(const uint4*)(qkv + (size_t)(qb * 64 + r) * QKVS + h * HD + c * 8);
        *(uint4*)&Qs[r * QK_PW + c * 4] = o;
    }

    float acc[16][4];
#pragma unroll
    for (int nj = 0; nj < 16; nj++)
#pragma unroll
        for (int c = 0; c < 4; c++) acc[nj][c] = 0.f;

    int s0 = qb * 64 - (WIN - 1);
    if (s0 < 0) s0 = 0;
    const int kt0 = s0 >> 6;
    const int qi0 = qb * 64 + r0;
    const int qi1 = qi0 + 8;

    for (int kt = kt0; kt <= qb; kt++) {
        const bool edge = (kt == qb) || (kt == kt0);
        __syncthreads();

        // K tile: raw copy
        for (int idx = tid; idx < 64 * 32; idx += 256) {
            int r = idx >> 5, c = (idx & 31);
            uint4 o = *(const uint4*)(qkv + (size_t)(kt * 64 + r) * QKVS + 2048 + kvi * HD + c * 8);
            *(uint4*)&Ks[r * QK_PW + c * 4] = o;
        }
        // V tile: row-pair interleave via prmt
        for (int idx = tid; idx < 32 * 32; idx += 256) {
            int kp = idx >> 5, dg = (idx & 31) * 8;
            const __half* v0p = qkv + (size_t)(kt * 64 + 2 * kp) * QKVS + 3072 + kvi * HD + dg;
            uint4 A = *(const uint4*)v0p;
            uint4 B = *(const uint4*)(v0p + QKVS);
            uint32_t* dst = &Vt[kp * VT_PW + dg];
            dst[0] = __byte_perm(A.x, B.x, 0x5410);
            dst[1] = __byte_perm(A.x, B.x, 0x7632);
            dst[2] = __byte_perm(A.y, B.y, 0x5410);
            dst[3] = __byte_perm(A.y, B.y, 0x7632);
            dst[4] = __byte_perm(A.z, B.z, 0x5410);
            dst[5] = __byte_perm(A.z, B.z, 0x7632);
            dst[6] = __byte_perm(A.w, B.w, 0x5410);
            dst[7] = __byte_perm(A.w, B.w, 0x7632);
        }
        __syncthreads();

        // ---- S = Q @ K^T ----
        float sf[4][4];
#pragma unroll
        for (int nj = 0; nj < 4; nj++)
#pragma unroll
            for (int c = 0; c < 4; c++) sf[nj][c] = 0.f;
#pragma unroll
        for (int ks = 0; ks < 128; ks += 8) {
            uint32_t a0, a1, a2, a3;
            LDSM_X4(a0, a1, a2, a3, q_lb + 4u * ks);
#pragma unroll
            for (int njp = 0; njp < 2; njp++) {
                uint32_t b00, b01, b10, b11;
                LDSM_X4(b00, b01, b10, b11,
                        k_lb + (uint32_t)njp * (16 * QK_PW * 4) + 4u * ks);
                MMA_F16(sf[2*njp][0], sf[2*njp][1], sf[2*njp][2], sf[2*njp][3],
                        a0, a1, a2, a3, b00, b01);
                MMA_F16(sf[2*njp+1][0], sf[2*njp+1][1], sf[2*njp+1][2], sf[2*njp+1][3],
                        a0, a1, a2, a3, b10, b11);
            }
        }

        // ---- scale (+ mask on edge tiles) + partial row max ----
        float mx0 = -INFINITY, mx1 = -INFINITY;
        if (edge) {
#pragma unroll
            for (int nj = 0; nj < 4; nj++) {
#pragma unroll
                for (int c = 0; c < 2; c++) {
                    int col = kt * 64 + wn * 32 + nj * 8 + 2 * tig + c;
                    float v0 = sf[nj][c] * 0.0625f;
                    v0 = (col <= qi0 && col > qi0 - WIN) ? v0 : -INFINITY;
                    sf[nj][c] = v0;
                    mx0 = fmaxf(mx0, v0);
                    float v1 = sf[nj][2 + c] * 0.0625f;
                    v1 = (col <= qi1 && col > qi1 - WIN) ? v1 : -INFINITY;
                    sf[nj][2 + c] = v1;
                    mx1 = fmaxf(mx1, v1);
                }
            }
        } else {
#pragma unroll
            for (int nj = 0; nj < 4; nj++) {
#pragma unroll
                for (int c = 0; c < 2; c++) {
                    float v0 = sf[nj][c] * 0.0625f;
                    sf[nj][c] = v0;
                    mx0 = fmaxf(mx0, v0);
                    float v1 = sf[nj][2 + c] * 0.0625f;
                    sf[nj][2 + c] = v1;
                    mx1 = fmaxf(mx1, v1);
                }
            }
        }
#pragma unroll
        for (int o = 1; o <= 2; o <<= 1) {
            mx0 = fmaxf(mx0, __shfl_xor_sync(0xffffffffu, mx0, o));
            mx1 = fmaxf(mx1, __shfl_xor_sync(0xffffffffu, mx1, o));
        }
        if (tig == 0) {
            pmax[r0 * 2 + wn]       = mx0;
            pmax[(r0 + 8) * 2 + wn] = mx1;
        }
        __syncthreads();

        float mold0 = m_s[r0], mold1 = m_s[r0 + 8];
        float mn0 = fmaxf(mold0, fmaxf(pmax[r0 * 2], pmax[r0 * 2 + 1]));
        float mn1 = fmaxf(mold1, fmaxf(pmax[(r0 + 8) * 2], pmax[(r0 + 8) * 2 + 1]));

        // ---- exp, partial sums, store P packed fp16 ----
        float sum0 = 0.f, sum1 = 0.f;
#pragma unroll
        for (int nj = 0; nj < 4; nj++) {
            float p00, p01, p10, p11;
            if (edge) {
                p00 = (sf[nj][0] == -INFINITY) ? 0.f : __expf(sf[nj][0] - mn0);
                p01 = (sf[nj][1] == -INFINITY) ? 0.f : __expf(sf[nj][1] - mn0);
                p10 = (sf[nj][2] == -INFINITY) ? 0.f : __expf(sf[nj][2] - mn1);
                p11 = (sf[nj][3] == -INFINITY) ? 0.f : __expf(sf[nj][3] - mn1);
            } else {
                p00 = __expf(sf[nj][0] - mn0);
                p01 = __expf(sf[nj][1] - mn0);
                p10 = __expf(sf[nj][2] - mn1);
                p11 = __expf(sf[nj][3] - mn1);
            }
            sum0 += p00 + p01;
            sum1 += p10 + p11;
            int wd = wn * 16 + nj * 4 + tig;
            Ps[r0 * P_PW + wd]       = pack_f16x2(p00, p01);
            Ps[(r0 + 8) * P_PW + wd] = pack_f16x2(p10, p11);
        }
#pragma unroll
        for (int o = 1; o <= 2; o <<= 1) {
            sum0 += __shfl_xor_sync(0xffffffffu, sum0, o);
            sum1 += __shfl_xor_sync(0xffffffffu, sum1, o);
        }
        if (tig == 0) {
            psum[r0 * 2 + wn]       = sum0;
            psum[(r0 + 8) * 2 + wn] = sum1;
        }
        float corr0 = (mn0 == -INFINITY) ? 1.f
                    : ((mold0 == -INFINITY) ? 0.f : __expf(mold0 - mn0));
        float corr1 = (mn1 == -INFINITY) ? 1.f
                    : ((mold1 == -INFINITY) ? 0.f : __expf(mold1 - mn1));
        __syncthreads();

        if (wn == 0 && tig == 0) {
            l_s[r0]     = l_s[r0]     * corr0 + psum[r0 * 2]       + psum[r0 * 2 + 1];
            l_s[r0 + 8] = l_s[r0 + 8] * corr1 + psum[(r0 + 8) * 2] + psum[(r0 + 8) * 2 + 1];
            m_s[r0]     = mn0;
            m_s[r0 + 8] = mn1;
        }

        // ---- O = O*corr + P @ V ----
#pragma unroll
        for (int nj = 0; nj < 16; nj++) {
            acc[nj][0] *= corr0; acc[nj][1] *= corr0;
            acc[nj][2] *= corr1; acc[nj][3] *= corr1;
        }
#pragma unroll
        for (int ks = 0; ks < 32; ks += 8) {
            uint32_t a0, a1, a2, a3;
            LDSM_X4(a0, a1, a2, a3, p_lb + 4u * ks);
#pragma unroll
            for (int nj = 0; nj < 16; nj++) {
                int c = wn * 128 + nj * 8 + g;
                uint32_t b0 = Vt[(ks + tig) * VT_PW + c];
                uint32_t b1 = Vt[(ks + tig + 4) * VT_PW + c];
                MMA_F16(acc[nj][0], acc[nj][1], acc[nj][2], acc[nj][3],
                        a0, a1, a2, a3, b0, b1);
            }
        }
    }

    __syncthreads();
    float inv0 = 1.f / l_s[r0];
    float inv1 = 1.f / l_s[r0 + 8];
    __half* yr0 = yh + (size_t)(qb * 64 + r0) * DM + h * HD;
    __half* yr1 = yh + (size_t)(qb * 64 + r0 + 8) * DM + h * HD;
#pragma unroll
    for (int nj = 0; nj < 16; nj++) {
        int col = wn * 128 + nj * 8 + 2 * tig;
        *(uint32_t*)(yr0 + col) = pack_f16x2(acc[nj][0] * inv0, acc[nj][1] * inv0);
        *(uint32_t*)(yr1 + col) = pack_f16x2(acc[nj][2] * inv1, acc[nj][3] * inv1);
    }
}

// ---------------------------------------------------------------------------
extern "C" void kernel_launch(void* const* d_in, const int* in_sizes, int n_in,
                              void* d_out, int out_size)
{
    const float* x  = (const float*)d_in[0];
    const int*   pos= (const int*)  d_in[1];
    const float* Wq = (const float*)d_in[2];
    const float* Wk = (const float*)d_in[3];
    const float* Wv = (const float*)d_in[4];
    const float* Wo = (const float*)d_in[5];
    const float* qw = (const float*)d_in[6];
    const float* kw = (const float*)d_in[7];
    float* out = (float*)d_out;

    float  *cs_p, *sn_p;
    __half *qkvh_p, *xh_p, *wqkvh_p, *woh_p, *yh_p;
    cudaGetSymbolAddress((void**)&qkvh_p,  g_qkvh);
    cudaGetSymbolAddress((void**)&cs_p,    g_cs);
    cudaGetSymbolAddress((void**)&sn_p,    g_sn);
    cudaGetSymbolAddress((void**)&xh_p,    g_xh);
    cudaGetSymbolAddress((void**)&wqkvh_p, g_wqkvh);
    cudaGetSymbolAddress((void**)&woh_p,   g_woh);
    cudaGetSymbolAddress((void**)&yh_p,    g_yh);

    // fp32 -> fp16 converts ([Wq; Wk; Wv] concatenated) + rope table
    to_half_kernel<<<(T_SEQ * DM) / 2048, 256>>>(x, xh_p, T_SEQ * DM);
    to_half_kernel<<<(DM * DM) / 2048, 256>>>(Wq, wqkvh_p, DM * DM);
    to_half_kernel<<<(NKV * HD * DM) / 2048, 256>>>(
        Wk, wqkvh_p + (size_t)DM * DM, NKV * HD * DM);
    to_half_kernel<<<(NKV * HD * DM) / 2048, 256>>>(
        Wv, wqkvh_p + (size_t)DM * DM + (size_t)NKV * HD * DM, NKV * HD * DM);
    to_half_kernel<<<(DM * DM) / 2048, 256>>>(Wo, woh_p, DM * DM);
    rope_table_kernel<<<T_SEQ, 128>>>(pos, cs_p, sn_p);

    cudaFuncSetAttribute(hgemm_f32, cudaFuncAttributeMaxDynamicSharedMemorySize,
                         HG_SMEM_BYTES);
    cudaFuncSetAttribute(hgemm_f16, cudaFuncAttributeMaxDynamicSharedMemorySize,
                         HG_SMEM_BYTES);

    // Fused QKV projection: one launch, fp16 out
    hgemm_f16<<<dim3(QKVS / 128, T_SEQ / 128), 256, HG_SMEM_BYTES>>>(
        xh_p, wqkvh_p, qkvh_p, T_SEQ, QKVS, DM);

    // RMSNorm + RoPE in place on fp16 QKV (Q heads + K heads)
    rmsnorm_rope_kernel<<<dim3(T_SEQ, NH + NKV), 256>>>(
        qkvh_p, qw, kw, cs_p, sn_p);

    // Flash attention (2 CTAs/SM)
    cudaFuncSetAttribute(attn_f16, cudaFuncAttributeMaxDynamicSharedMemorySize,
                         ATTN_SMEM_BYTES);
    attn_f16<<<dim3(T_SEQ / 64, NH), 256, ATTN_SMEM_BYTES>>>(qkvh_p, yh_p);

    // Output projection (fp32 out -> d_out)
    hgemm_f32<<<dim3(DM / 128, T_SEQ / 128), 256, HG_SMEM_BYTES>>>(
        yh_p, woh_p, out, T_SEQ, DM, DM);
}

// round 13
// speedup vs baseline: 5.9992x; 1.0449x over previous
#include <cuda_runtime.h>
#include <cuda_bf16.h>
#include <cuda_fp16.h>
#include <math.h>
#include <stdint.h>

#define T_SEQ 4096
#define DM    2048
#define NH    8
#define NKV   4
#define HD    256
#define WIN   1024
#define QKVS  4096     // fused row: Q[0,2048) | K[2048,3072) | V[3072,4096)

// Scratch (static __device__ arrays — allocation-free per harness rules)
__device__ __half g_qkvh[T_SEQ * QKVS];       // 32 MB fused QKV (fp16)
__device__ __half g_xh[T_SEQ * DM];           // 16 MB
__device__ __half g_wqkvh[QKVS * DM];         // 16 MB [Wq; Wk; Wv]
__device__ __half g_woh[DM * DM];             // 8 MB
__device__ __half g_yh[T_SEQ * DM];           // 16 MB (attention out, fp16)
__device__ float  g_cs[T_SEQ * 128];          // rope cos table
__device__ float  g_sn[T_SEQ * 128];          // rope sin table

__device__ __forceinline__ uint32_t pack_f16x2(float lo, float hi) {
    __half2 h = __floats2half2_rn(lo, hi);    // .x = lo (low 16 bits)
    return *reinterpret_cast<uint32_t*>(&h);
}

__device__ __forceinline__ uint32_t smem_u32(const void* p) {
    uint32_t a;
    asm("{ .reg .u64 t; cvta.to.shared.u64 t, %1; cvt.u32.u64 %0, t; }"
        : "=r"(a) : "l"(p));
    return a;
}
__device__ __forceinline__ void cp_async16(uint32_t dst, const void* src) {
    asm volatile("cp.async.cg.shared.global [%0], [%1], 16;" :: "r"(dst), "l"(src));
}
__device__ __forceinline__ void cp_commit() {
    asm volatile("cp.async.commit_group;" ::: "memory");
}
__device__ __forceinline__ void cp_wait1() {
    asm volatile("cp.async.wait_group 1;" ::: "memory");
}

#define MMA_F16(d0,d1,d2,d3,a0,a1,a2,a3,b0,b1)                               \
    asm volatile(                                                            \
        "mma.sync.aligned.m16n8k16.row.col.f32.f16.f16.f32 "                 \
        "{%0,%1,%2,%3}, {%4,%5,%6,%7}, {%8,%9}, {%0,%1,%2,%3};"              \
        : "+f"(d0), "+f"(d1), "+f"(d2), "+f"(d3)                             \
        : "r"(a0), "r"(a1), "r"(a2), "r"(a3), "r"(b0), "r"(b1))

#define LDSM_X4(r0,r1,r2,r3,addr)                                            \
    asm volatile("ldmatrix.sync.aligned.m8n8.x4.shared.b16 {%0,%1,%2,%3}, [%4];" \
        : "=r"(r0), "=r"(r1), "=r"(r2), "=r"(r3) : "r"(addr))

// ---------------------------------------------------------------------------
// ONE fused fp32->fp16 conversion pass over x, Wq, Wk, Wv, Wo.
// Segment bounds are compile-time constants (all multiples of 8).
// ---------------------------------------------------------------------------
#define NX   (T_SEQ * DM)            // 8M  -> g_xh
#define NWQ  (DM * DM)               // 4M  -> g_wqkvh[0]
#define NWK  (NKV * HD * DM)         // 2M  -> g_wqkvh[NWQ]
#define NWV  (NKV * HD * DM)         // 2M  -> g_wqkvh[NWQ+NWK]
#define NWO  (DM * DM)               // 4M  -> g_woh
#define NTOT (NX + NWQ + NWK + NWV + NWO)

__global__ __launch_bounds__(256) void convert_all_kernel(
    const float* __restrict__ x,  const float* __restrict__ Wq,
    const float* __restrict__ Wk, const float* __restrict__ Wv,
    const float* __restrict__ Wo,
    __half* __restrict__ xh, __half* __restrict__ wqkvh,
    __half* __restrict__ woh)
{
    for (size_t i = ((size_t)blockIdx.x * 256 + threadIdx.x) * 8; i < NTOT;
         i += (size_t)gridDim.x * 256 * 8) {
        const float* src;
        __half* dst;
        size_t o = i;
        if (o < NX)                        { src = x;  dst = xh; }
        else if ((o -= NX)  < NWQ)         { src = Wq; dst = wqkvh; }
        else if ((o -= NWQ) < NWK)         { src = Wk; dst = wqkvh + NWQ; }
        else if ((o -= NWK) < NWV)         { src = Wv; dst = wqkvh + NWQ + NWK; }
        else { o -= NWV;                     src = Wo; dst = woh; }
        float4 v0 = *(const float4*)(src + o);
        float4 v1 = *(const float4*)(src + o + 4);
        uint4 ov;
        ov.x = pack_f16x2(v0.x, v0.y);
        ov.y = pack_f16x2(v0.z, v0.w);
        ov.z = pack_f16x2(v1.x, v1.y);
        ov.w = pack_f16x2(v1.z, v1.w);
        *(uint4*)((char*)dst + o * 2) = ov;
    }
}

// ---------------------------------------------------------------------------
// RoPE table (bit-identical math to the original in-kernel version)
// ---------------------------------------------------------------------------
__global__ __launch_bounds__(128) void rope_table_kernel(
    const int* __restrict__ pos, float* __restrict__ cs, float* __restrict__ sn)
{
    int t = blockIdx.x, f = threadIdx.x;
    float inv_freq = expf(-(float)f * (logf(10000.0f) / 128.0f));
    float ang = (float)pos[t] * inv_freq;
    float sv, cv;
    sincosf(ang, &sv, &cv);
    cs[t * 128 + f] = cv;
    sn[t * 128 + f] = sv;
}

// ---------------------------------------------------------------------------
// FP16 tensor-core GEMM core (fp32 accum). 128x128 tile, BK=64 halves,
// cp.async double buffered, ldmatrix fragments, 8 warps (4m x 2n).
// ---------------------------------------------------------------------------
#define HG_STAGE_WORDS (128 * 36)
#define HG_SMEM_BYTES  (4 * HG_STAGE_WORDS * 4 * 2)   // 73728

template <bool HalfOut>
__device__ __forceinline__ void hgemm_body(
    const __half* __restrict__ A, const __half* __restrict__ B,
    void* __restrict__ C, int M, int N, int K)
{
    extern __shared__ uint32_t sm[];
    const int tid  = threadIdx.x;
    const int brow = blockIdx.y * 128;
    const int bcol = blockIdx.x * 128;
    const int warp = tid >> 5;
    const int lane = tid & 31;
    const int g    = lane >> 2;
    const int tig  = lane & 3;
    const int warpM = (warp >> 1) * 32;
    const int warpN = (warp & 1) * 64;
    const int nslab = K >> 6;

    const uint32_t sa = smem_u32(sm);
    const uint32_t aab = sa + 4u * ((warpM + (lane & 15)) * 36 + ((lane >> 4) << 2));
    const uint32_t bbb = sa + 4u * (HG_STAGE_WORDS
                       + (warpN + (lane & 7) + ((lane >> 4) << 3)) * 36
                       + (((lane >> 3) & 1) << 2));

    auto As_w = [&](int st, int r, int w) -> uint32_t& {
        return sm[st * 2 * HG_STAGE_WORDS + r * 36 + w];
    };
    auto Bs_w = [&](int st, int r, int w) -> uint32_t& {
        return sm[st * 2 * HG_STAGE_WORDS + HG_STAGE_WORDS + r * 36 + w];
    };

    auto load_slab = [&](int j, int st) {
        const int k0 = j << 6;
#pragma unroll
        for (int i = 0; i < 4; i++) {
            int id  = tid + i * 256;
            int row = id >> 3;
            int g8  = (id & 7) * 8;
            cp_async16(smem_u32(&As_w(st, row, g8 >> 1)),
                       A + (size_t)(brow + row) * K + k0 + g8);
            cp_async16(smem_u32(&Bs_w(st, row, g8 >> 1)),
                       B + (size_t)(bcol + row) * K + k0 + g8);
        }
    };

    float acc[2][8][4];
#pragma unroll
    for (int mi = 0; mi < 2; mi++)
#pragma unroll
        for (int nj = 0; nj < 8; nj++)
#pragma unroll
            for (int c = 0; c < 4; c++) acc[mi][nj][c] = 0.f;

    load_slab(0, 0);
    cp_commit();

    for (int j = 0; j < nslab; j++) {
        const int st = j & 1;
        if (j + 1 < nslab) load_slab(j + 1, st ^ 1);
        cp_commit();
        cp_wait1();
        __syncthreads();

        const uint32_t stoff = (uint32_t)st * (2 * HG_STAGE_WORDS * 4);
#pragma unroll
        for (int ks = 0; ks < 32; ks += 8) {
            uint32_t af[2][4];
            uint32_t bf[8][2];
            LDSM_X4(af[0][0], af[0][1], af[0][2], af[0][3],
                    aab + stoff + 4u * ks);
            LDSM_X4(af[1][0], af[1][1], af[1][2], af[1][3],
                    aab + stoff + 4u * (16 * 36) + 4u * ks);
#pragma unroll
            for (int njp = 0; njp < 4; njp++)
                LDSM_X4(bf[2 * njp][0], bf[2 * njp][1],
                        bf[2 * njp + 1][0], bf[2 * njp + 1][1],
                        bbb + stoff + (uint32_t)njp * (16 * 36 * 4) + 4u * ks);
#pragma unroll
            for (int mi = 0; mi < 2; mi++)
#pragma unroll
                for (int nj = 0; nj < 8; nj++)
                    MMA_F16(acc[mi][nj][0], acc[mi][nj][1],
                            acc[mi][nj][2], acc[mi][nj][3],
                            af[mi][0], af[mi][1], af[mi][2], af[mi][3],
                            bf[nj][0], bf[nj][1]);
        }
        __syncthreads();
    }

#pragma unroll
    for (int mi = 0; mi < 2; mi++) {
        int row0 = brow + warpM + mi * 16 + g;
#pragma unroll
        for (int nj = 0; nj < 8; nj++) {
            int col = bcol + warpN + nj * 8 + tig * 2;
            if (HalfOut) {
                __half* Ch = (__half*)C;
                *(uint32_t*)(Ch + (size_t)row0 * N + col) =
                    pack_f16x2(acc[mi][nj][0], acc[mi][nj][1]);
                *(uint32_t*)(Ch + (size_t)(row0 + 8) * N + col) =
                    pack_f16x2(acc[mi][nj][2], acc[mi][nj][3]);
            } else {
                float* Cf = (float*)C;
                float2 lo, hi;
                lo.x = acc[mi][nj][0]; lo.y = acc[mi][nj][1];
                hi.x = acc[mi][nj][2]; hi.y = acc[mi][nj][3];
                *(float2*)(Cf + (size_t)row0 * N + col)       = lo;
                *(float2*)(Cf + (size_t)(row0 + 8) * N + col) = hi;
            }
        }
    }
}

__global__ __launch_bounds__(256, 2) void hgemm_f32(
    const __half* __restrict__ A, const __half* __restrict__ B,
    float* __restrict__ C, int M, int N, int K)
{
    hgemm_body<false>(A, B, C, M, N, K);
}

__global__ __launch_bounds__(256, 2) void hgemm_f16(
    const __half* __restrict__ A, const __half* __restrict__ B,
    __half* __restrict__ C, int M, int N, int K)
{
    hgemm_body<true>(A, B, C, M, N, K);
}

// ---------------------------------------------------------------------------
// Warp-per-head RMSNorm + RoPE, in place on fp16 fused QKV buffer.
// Block = 384 threads = 12 warps, one per head (8 Q + 4 K). 8 elems/lane
// (one uint4). Warp-shfl reductions only — no block barriers.
// ---------------------------------------------------------------------------
__global__ __launch_bounds__(384) void rmsnorm_rope_kernel(
    __half* __restrict__ qkv,
    const float* __restrict__ qw, const float* __restrict__ kw,
    const float* __restrict__ cs, const float* __restrict__ sn_t)
{
    const int t    = blockIdx.x;
    const int w    = threadIdx.x >> 5;     // head index 0..11
    const int lane = threadIdx.x & 31;
    const int d0   = lane * 8;

    __half* row;
    const float* wgt;
    if (w < NH) { row = qkv + (size_t)t * QKVS + w * HD;               wgt = qw; }
    else        { row = qkv + (size_t)t * QKVS + 2048 + (w - NH) * HD; wgt = kw; }

    uint4 wv = *(const uint4*)(row + d0);
    const uint32_t* wr = (const uint32_t*)&wv;
    float e[8];
#pragma unroll
    for (int j = 0; j < 4; j++) {
        __half2 h = *(const __half2*)&wr[j];
        float2 f = __half22float2(h);
        e[2 * j]     = f.x;
        e[2 * j + 1] = f.y;
    }

    float ss = 0.f;
#pragma unroll
    for (int j = 0; j < 8; j++) ss += e[j] * e[j];
#pragma unroll
    for (int o = 16; o; o >>= 1) ss += __shfl_xor_sync(0xffffffffu, ss, o);
    float scale = rsqrtf(ss * (1.0f / HD) + 1e-6f);

    const float* csr = cs  + t * 128;
    const float* snr = sn_t + t * 128;
    uint4 ov;
    uint32_t* orp = (uint32_t*)&ov;
#pragma unroll
    for (int j = 0; j < 4; j++) {
        int d  = d0 + 2 * j;
        float n0 = e[2 * j]     * scale * wgt[d];
        float n1 = e[2 * j + 1] * scale * wgt[d + 1];
        int   f0 = d & 127, f1 = (d + 1) & 127;
        float r0 = n0 * csr[f0] - n1 * snr[f0];   // rot[even] = -x[odd]
        float r1 = n1 * csr[f1] + n0 * snr[f1];   // rot[odd]  =  x[even]
        orp[j] = pack_f16x2(r0, r1);
    }
    *(uint4*)(row + d0) = ov;
}

// ---------------------------------------------------------------------------
// Flash attention, fp16 end-to-end data path, fp32 softmax, 2 CTAs/SM.
// qb is REVERSED vs blockIdx so the most expensive blocks (large windows)
// are scheduled first — better wave packing.
// ---------------------------------------------------------------------------
#define QK_PW 132
#define VT_PW 264
#define P_PW  36
#define ATTN_SMEM_WORDS (2*64*QK_PW + 32*VT_PW + 64*P_PW + 128 + 128 + 64 + 64)
#define ATTN_SMEM_BYTES (ATTN_SMEM_WORDS * 4)

__global__ __launch_bounds__(256, 2) void attn_f16(
    const __half* __restrict__ qkv, __half* __restrict__ yh)
{
    extern __shared__ uint32_t smw[];
    uint32_t* Qs = smw;                       // [64][132]
    uint32_t* Ks = Qs + 64 * QK_PW;           // [64][132]
    uint32_t* Vt = Ks + 64 * QK_PW;           // [32][264]
    uint32_t* Ps = Vt + 32 * VT_PW;           // [64][36]
    float* pmax = (float*)(Ps + 64 * P_PW);   // [64][2]
    float* psum = pmax + 128;                 // [64][2]
    float* m_s  = psum + 128;                 // [64]
    float* l_s  = m_s + 64;                   // [64]

    const int tid  = threadIdx.x;
    const int qb   = gridDim.x - 1 - blockIdx.x;   // longest-first scheduling
    const int h    = blockIdx.y;
    const int kvi  = h >> 1;
    const int warp = tid >> 5;
    const int lane = tid & 31;
    const int g    = lane >> 2;
    const int tig  = lane & 3;
    const int wn   = warp & 1;
    const int r0   = (warp >> 1) * 16 + g;

    const uint32_t q_lb = smem_u32(Qs) +
        4u * (((warp >> 1) * 16 + (lane & 15)) * QK_PW + ((lane >> 4) << 2));
    const uint32_t k_lb = smem_u32(Ks) +
        4u * ((wn * 32 + (lane & 7) + ((lane >> 4) << 3)) * QK_PW
              + (((lane >> 3) & 1) << 2));
    const uint32_t p_lb = smem_u32(Ps) +
        4u * (((warp >> 1) * 16 + (lane & 15)) * P_PW + ((lane >> 4) << 2));

    if (tid < 64) { m_s[tid] = -INFINITY; l_s[tid] = 0.f; }

    // Q tile: raw copy from fused buffer
    for (int idx = tid; idx < 64 * 32; idx += 256) {
        int r = idx >> 5, c = (idx & 31);
        uint4 o = *(const uint4*)(qkv + (size_t)(qb * 64 + r) * QKVS + h * HD + c * 8);
        *(uint4*)&Qs[r * QK_PW + c * 4] = o;
    }

    float acc[16][4];
#pragma unroll
    for (int nj = 0; nj < 16; nj++)
#pragma unroll
        for (int c = 0; c < 4; c++) acc[nj][c] = 0.f;

    int s0 = qb * 64 - (WIN - 1);
    if (s0 < 0) s0 = 0;
    const int kt0 = s0 >> 6;
    const int qi0 = qb * 64 + r0;
    const int qi1 = qi0 + 8;

    for (int kt = kt0; kt <= qb; kt++) {
        const bool edge = (kt == qb) || (kt == kt0);
        __syncthreads();

        // K tile: raw copy
        for (int idx = tid; idx < 64 * 32; idx += 256) {
            int r = idx >> 5, c = (idx & 31);
            uint4 o = *(const uint4*)(qkv + (size_t)(kt * 64 + r) * QKVS + 2048 + kvi * HD + c * 8);
            *(uint4*)&Ks[r * QK_PW + c * 4] = o;
        }
        // V tile: row-pair interleave via prmt
        for (int idx = tid; idx < 32 * 32; idx += 256) {
            int kp = idx >> 5, dg = (idx & 31) * 8;
            const __half* v0p = qkv + (size_t)(kt * 64 + 2 * kp) * QKVS + 3072 + kvi * HD + dg;
            uint4 A = *(const uint4*)v0p;
            uint4 B = *(const uint4*)(v0p + QKVS);
            uint32_t* dst = &Vt[kp * VT_PW + dg];
            dst[0] = __byte_perm(A.x, B.x, 0x5410);
            dst[1] = __byte_perm(A.x, B.x, 0x7632);
            dst[2] = __byte_perm(A.y, B.y, 0x5410);
            dst[3] = __byte_perm(A.y, B.y, 0x7632);
            dst[4] = __byte_perm(A.z, B.z, 0x5410);
            dst[5] = __byte_perm(A.z, B.z, 0x7632);
            dst[6] = __byte_perm(A.w, B.w, 0x5410);
            dst[7] = __byte_perm(A.w, B.w, 0x7632);
        }
        __syncthreads();

        // ---- S = Q @ K^T ----
        float sf[4][4];
#pragma unroll
        for (int nj = 0; nj < 4; nj++)
#pragma unroll
            for (int c = 0; c < 4; c++) sf[nj][c] = 0.f;
#pragma unroll
        for (int ks = 0; ks < 128; ks += 8) {
            uint32_t a0, a1, a2, a3;
            LDSM_X4(a0, a1, a2, a3, q_lb + 4u * ks);
#pragma unroll
            for (int njp = 0; njp < 2; njp++) {
                uint32_t b00, b01, b10, b11;
                LDSM_X4(b00, b01, b10, b11,
                        k_lb + (uint32_t)njp * (16 * QK_PW * 4) + 4u * ks);
                MMA_F16(sf[2*njp][0], sf[2*njp][1], sf[2*njp][2], sf[2*njp][3],
                        a0, a1, a2, a3, b00, b01);
                MMA_F16(sf[2*njp+1][0], sf[2*njp+1][1], sf[2*njp+1][2], sf[2*njp+1][3],
                        a0, a1, a2, a3, b10, b11);
            }
        }

        // ---- scale (+ mask on edge tiles) + partial row max ----
        float mx0 = -INFINITY, mx1 = -INFINITY;
        if (edge) {
#pragma unroll
            for (int nj = 0; nj < 4; nj++) {
#pragma unroll
                for (int c = 0; c < 2; c++) {
                    int col = kt * 64 + wn * 32 + nj * 8 + 2 * tig + c;
                    float v0 = sf[nj][c] * 0.0625f;
                    v0 = (col <= qi0 && col > qi0 - WIN) ? v0 : -INFINITY;
                    sf[nj][c] = v0;
                    mx0 = fmaxf(mx0, v0);
                    float v1 = sf[nj][2 + c] * 0.0625f;
                    v1 = (col <= qi1 && col > qi1 - WIN) ? v1 : -INFINITY;
                    sf[nj][2 + c] = v1;
                    mx1 = fmaxf(mx1, v1);
                }
            }
        } else {
#pragma unroll
            for (int nj = 0; nj < 4; nj++) {
#pragma unroll
                for (int c = 0; c < 2; c++) {
                    float v0 = sf[nj][c] * 0.0625f;
                    sf[nj][c] = v0;
                    mx0 = fmaxf(mx0, v0);
                    float v1 = sf[nj][2 + c] * 0.0625f;
                    sf[nj][2 + c] = v1;
                    mx1 = fmaxf(mx1, v1);
                }
            }
        }
#pragma unroll
        for (int o = 1; o <= 2; o <<= 1) {
            mx0 = fmaxf(mx0, __shfl_xor_sync(0xffffffffu, mx0, o));
            mx1 = fmaxf(mx1, __shfl_xor_sync(0xffffffffu, mx1, o));
        }
        if (tig == 0) {
            pmax[r0 * 2 + wn]       = mx0;
            pmax[(r0 + 8) * 2 + wn] = mx1;
        }
        __syncthreads();

        float mold0 = m_s[r0], mold1 = m_s[r0 + 8];
        float mn0 = fmaxf(mold0, fmaxf(pmax[r0 * 2], pmax[r0 * 2 + 1]));
        float mn1 = fmaxf(mold1, fmaxf(pmax[(r0 + 8) * 2], pmax[(r0 + 8) * 2 + 1]));

        // ---- exp, partial sums, store P packed fp16 ----
        float sum0 = 0.f, sum1 = 0.f;
#pragma unroll
        for (int nj = 0; nj < 4; nj++) {
            float p00, p01, p10, p11;
            if (edge) {
                p00 = (sf[nj][0] == -INFINITY) ? 0.f : __expf(sf[nj][0] - mn0);
                p01 = (sf[nj][1] == -INFINITY) ? 0.f : __expf(sf[nj][1] - mn0);
                p10 = (sf[nj][2] == -INFINITY) ? 0.f : __expf(sf[nj][2] - mn1);
                p11 = (sf[nj][3] == -INFINITY) ? 0.f : __expf(sf[nj][3] - mn1);
            } else {
                p00 = __expf(sf[nj][0] - mn0);
                p01 = __expf(sf[nj][1] - mn0);
                p10 = __expf(sf[nj][2] - mn1);
                p11 = __expf(sf[nj][3] - mn1);
            }
            sum0 += p00 + p01;
            sum1 += p10 + p11;
            int wd = wn * 16 + nj * 4 + tig;
            Ps[r0 * P_PW + wd]       = pack_f16x2(p00, p01);
            Ps[(r0 + 8) * P_PW + wd] = pack_f16x2(p10, p11);
        }
#pragma unroll
        for (int o = 1; o <= 2; o <<= 1) {
            sum0 += __shfl_xor_sync(0xffffffffu, sum0, o);
            sum1 += __shfl_xor_sync(0xffffffffu, sum1, o);
        }
        if (tig == 0) {
            psum[r0 * 2 + wn]       = sum0;
            psum[(r0 + 8) * 2 + wn] = sum1;
        }
        float corr0 = (mn0 == -INFINITY) ? 1.f
                    : ((mold0 == -INFINITY) ? 0.f : __expf(mold0 - mn0));
        float corr1 = (mn1 == -INFINITY) ? 1.f
                    : ((mold1 == -INFINITY) ? 0.f : __expf(mold1 - mn1));
        __syncthreads();

        if (wn == 0 && tig == 0) {
            l_s[r0]     = l_s[r0]     * corr0 + psum[r0 * 2]       + psum[r0 * 2 + 1];
            l_s[r0 + 8] = l_s[r0 + 8] * corr1 + psum[(r0 + 8) * 2] + psum[(r0 + 8) * 2 + 1];
            m_s[r0]     = mn0;
            m_s[r0 + 8] = mn1;
        }

        // ---- O = O*corr + P @ V ----
#pragma unroll
        for (int nj = 0; nj < 16; nj++) {
            acc[nj][0] *= corr0; acc[nj][1] *= corr0;
            acc[nj][2] *= corr1; acc[nj][3] *= corr1;
        }
#pragma unroll
        for (int ks = 0; ks < 32; ks += 8) {
            uint32_t a0, a1, a2, a3;
            LDSM_X4(a0, a1, a2, a3, p_lb + 4u * ks);
#pragma unroll
            for (int nj = 0; nj < 16; nj++) {
                int c = wn * 128 + nj * 8 + g;
                uint32_t b0 = Vt[(ks + tig) * VT_PW + c];
                uint32_t b1 = Vt[(ks + tig + 4) * VT_PW + c];
                MMA_F16(acc[nj][0], acc[nj][1], acc[nj][2], acc[nj][3],
                        a0, a1, a2, a3, b0, b1);
            }
        }
    }

    __syncthreads();
    float inv0 = 1.f / l_s[r0];
    float inv1 = 1.f / l_s[r0 + 8];
    __half* yr0 = yh + (size_t)(qb * 64 + r0) * DM + h * HD;
    __half* yr1 = yh + (size_t)(qb * 64 + r0 + 8) * DM + h * HD;
#pragma unroll
    for (int nj = 0; nj < 16; nj++) {
        int col = wn * 128 + nj * 8 + 2 * tig;
        *(uint32_t*)(yr0 + col) = pack_f16x2(acc[nj][0] * inv0, acc[nj][1] * inv0);
        *(uint32_t*)(yr1 + col) = pack_f16x2(acc[nj][2] * inv1, acc[nj][3] * inv1);
    }
}

// ---------------------------------------------------------------------------
extern "C" void kernel_launch(void* const* d_in, const int* in_sizes, int n_in,
                              void* d_out, int out_size)
{
    const float* x  = (const float*)d_in[0];
    const int*   pos= (const int*)  d_in[1];
    const float* Wq = (const float*)d_in[2];
    const float* Wk = (const float*)d_in[3];
    const float* Wv = (const float*)d_in[4];
    const float* Wo = (const float*)d_in[5];
    const float* qw = (const float*)d_in[6];
    const float* kw = (const float*)d_in[7];
    float* out = (float*)d_out;

    float  *cs_p, *sn_p;
    __half *qkvh_p, *xh_p, *wqkvh_p, *woh_p, *yh_p;
    cudaGetSymbolAddress((void**)&qkvh_p,  g_qkvh);
    cudaGetSymbolAddress((void**)&cs_p,    g_cs);
    cudaGetSymbolAddress((void**)&sn_p,    g_sn);
    cudaGetSymbolAddress((void**)&xh_p,    g_xh);
    cudaGetSymbolAddress((void**)&wqkvh_p, g_wqkvh);
    cudaGetSymbolAddress((void**)&woh_p,   g_woh);
    cudaGetSymbolAddress((void**)&yh_p,    g_yh);

    // One fused fp32->fp16 convert (x + all weights) + rope table
    convert_all_kernel<<<2048, 256>>>(x, Wq, Wk, Wv, Wo, xh_p, wqkvh_p, woh_p);
    rope_table_kernel<<<T_SEQ, 128>>>(pos, cs_p, sn_p);

    cudaFuncSetAttribute(hgemm_f32, cudaFuncAttributeMaxDynamicSharedMemorySize,
                         HG_SMEM_BYTES);
    cudaFuncSetAttribute(hgemm_f16, cudaFuncAttributeMaxDynamicSharedMemorySize,
                         HG_SMEM_BYTES);

    // Fused QKV projection: one launch, fp16 out
    hgemm_f16<<<dim3(QKVS / 128, T_SEQ / 128), 256, HG_SMEM_BYTES>>>(
        xh_p, wqkvh_p, qkvh_p, T_SEQ, QKVS, DM);

    // RMSNorm + RoPE: warp-per-head, in place on fp16 QKV
    rmsnorm_rope_kernel<<<T_SEQ, 384>>>(qkvh_p, qw, kw, cs_p, sn_p);

    // Flash attention (2 CTAs/SM, longest-first qb order)
    cudaFuncSetAttribute(attn_f16, cudaFuncAttributeMaxDynamicSharedMemorySize,
                         ATTN_SMEM_BYTES);
    attn_f16<<<dim3(T_SEQ / 64, NH), 256, ATTN_SMEM_BYTES>>>(qkvh_p, yh_p);

    // Output projection (fp32 out -> d_out)
    hgemm_f32<<<dim3(DM / 128, T_SEQ / 128), 256, HG_SMEM_BYTES>>>(
        yh_p, woh_p, out, T_SEQ, DM, DM);
}

// round 14
// speedup vs baseline: 6.2494x; 1.0417x over previous
#include <cuda_runtime.h>
#include <cuda_bf16.h>
#include <cuda_fp16.h>
#include <math.h>
#include <stdint.h>

#define T_SEQ 4096
#define DM    2048
#define NH    8
#define NKV   4
#define HD    256
#define WIN   1024
#define QKVS  4096     // fused row: Q[0,2048) | K[2048,3072) | V[3072,4096)
#define SMAX  8.0f     // fixed softmax max: |s| <= 16 provable, exp(16-8) < fp16 max

// Scratch (static __device__ arrays — allocation-free per harness rules)
__device__ __half g_qkvh[T_SEQ * QKVS];       // 32 MB fused QKV (fp16)
__device__ __half g_xh[T_SEQ * DM];           // 16 MB
__device__ __half g_wqkvh[QKVS * DM];         // 16 MB [Wq; Wk; Wv]
__device__ __half g_woh[DM * DM];             // 8 MB
__device__ __half g_yh[T_SEQ * DM];           // 16 MB (attention out, fp16)
__device__ float  g_cs[T_SEQ * 128];          // rope cos table
__device__ float  g_sn[T_SEQ * 128];          // rope sin table

__device__ __forceinline__ uint32_t pack_f16x2(float lo, float hi) {
    __half2 h = __floats2half2_rn(lo, hi);    // .x = lo (low 16 bits)
    return *reinterpret_cast<uint32_t*>(&h);
}

__device__ __forceinline__ uint32_t smem_u32(const void* p) {
    uint32_t a;
    asm("{ .reg .u64 t; cvta.to.shared.u64 t, %1; cvt.u32.u64 %0, t; }"
        : "=r"(a) : "l"(p));
    return a;
}
__device__ __forceinline__ void cp_async16(uint32_t dst, const void* src) {
    asm volatile("cp.async.cg.shared.global [%0], [%1], 16;" :: "r"(dst), "l"(src));
}
__device__ __forceinline__ void cp_commit() {
    asm volatile("cp.async.commit_group;" ::: "memory");
}
__device__ __forceinline__ void cp_wait1() {
    asm volatile("cp.async.wait_group 1;" ::: "memory");
}

#define MMA_F16(d0,d1,d2,d3,a0,a1,a2,a3,b0,b1)                               \
    asm volatile(                                                            \
        "mma.sync.aligned.m16n8k16.row.col.f32.f16.f16.f32 "                 \
        "{%0,%1,%2,%3}, {%4,%5,%6,%7}, {%8,%9}, {%0,%1,%2,%3};"              \
        : "+f"(d0), "+f"(d1), "+f"(d2), "+f"(d3)                             \
        : "r"(a0), "r"(a1), "r"(a2), "r"(a3), "r"(b0), "r"(b1))

#define LDSM_X4(r0,r1,r2,r3,addr)                                            \
    asm volatile("ldmatrix.sync.aligned.m8n8.x4.shared.b16 {%0,%1,%2,%3}, [%4];" \
        : "=r"(r0), "=r"(r1), "=r"(r2), "=r"(r3) : "r"(addr))

// ---------------------------------------------------------------------------
// ONE fused fp32->fp16 conversion pass over x, Wq, Wk, Wv, Wo.
// ---------------------------------------------------------------------------
#define NX   (T_SEQ * DM)
#define NWQ  (DM * DM)
#define NWK  (NKV * HD * DM)
#define NWV  (NKV * HD * DM)
#define NWO  (DM * DM)
#define NTOT (NX + NWQ + NWK + NWV + NWO)

__global__ __launch_bounds__(256) void convert_all_kernel(
    const float* __restrict__ x,  const float* __restrict__ Wq,
    const float* __restrict__ Wk, const float* __restrict__ Wv,
    const float* __restrict__ Wo,
    __half* __restrict__ xh, __half* __restrict__ wqkvh,
    __half* __restrict__ woh)
{
    for (size_t i = ((size_t)blockIdx.x * 256 + threadIdx.x) * 8; i < NTOT;
         i += (size_t)gridDim.x * 256 * 8) {
        const float* src;
        __half* dst;
        size_t o = i;
        if (o < NX)                        { src = x;  dst = xh; }
        else if ((o -= NX)  < NWQ)         { src = Wq; dst = wqkvh; }
        else if ((o -= NWQ) < NWK)         { src = Wk; dst = wqkvh + NWQ; }
        else if ((o -= NWK) < NWV)         { src = Wv; dst = wqkvh + NWQ + NWK; }
        else { o -= NWV;                     src = Wo; dst = woh; }
        float4 v0 = *(const float4*)(src + o);
        float4 v1 = *(const float4*)(src + o + 4);
        uint4 ov;
        ov.x = pack_f16x2(v0.x, v0.y);
        ov.y = pack_f16x2(v0.z, v0.w);
        ov.z = pack_f16x2(v1.x, v1.y);
        ov.w = pack_f16x2(v1.z, v1.w);
        *(uint4*)((char*)dst + o * 2) = ov;
    }
}

// ---------------------------------------------------------------------------
// RoPE table (bit-identical math to the original in-kernel version)
// ---------------------------------------------------------------------------
__global__ __launch_bounds__(128) void rope_table_kernel(
    const int* __restrict__ pos, float* __restrict__ cs, float* __restrict__ sn)
{
    int t = blockIdx.x, f = threadIdx.x;
    float inv_freq = expf(-(float)f * (logf(10000.0f) / 128.0f));
    float ang = (float)pos[t] * inv_freq;
    float sv, cv;
    sincosf(ang, &sv, &cv);
    cs[t * 128 + f] = cv;
    sn[t * 128 + f] = sv;
}

// ---------------------------------------------------------------------------
// FP16 tensor-core GEMM core (fp32 accum). 128x128 tile, BK=64 halves,
// cp.async double buffered, ldmatrix fragments, 8 warps (4m x 2n).
// ---------------------------------------------------------------------------
#define HG_STAGE_WORDS (128 * 36)
#define HG_SMEM_BYTES  (4 * HG_STAGE_WORDS * 4 * 2)   // 73728

template <bool HalfOut>
__device__ __forceinline__ void hgemm_body(
    const __half* __restrict__ A, const __half* __restrict__ B,
    void* __restrict__ C, int M, int N, int K)
{
    extern __shared__ uint32_t sm[];
    const int tid  = threadIdx.x;
    const int brow = blockIdx.y * 128;
    const int bcol = blockIdx.x * 128;
    const int warp = tid >> 5;
    const int lane = tid & 31;
    const int g    = lane >> 2;
    const int tig  = lane & 3;
    const int warpM = (warp >> 1) * 32;
    const int warpN = (warp & 1) * 64;
    const int nslab = K >> 6;

    const uint32_t sa = smem_u32(sm);
    const uint32_t aab = sa + 4u * ((warpM + (lane & 15)) * 36 + ((lane >> 4) << 2));
    const uint32_t bbb = sa + 4u * (HG_STAGE_WORDS
                       + (warpN + (lane & 7) + ((lane >> 4) << 3)) * 36
                       + (((lane >> 3) & 1) << 2));

    auto As_w = [&](int st, int r, int w) -> uint32_t& {
        return sm[st * 2 * HG_STAGE_WORDS + r * 36 + w];
    };
    auto Bs_w = [&](int st, int r, int w) -> uint32_t& {
        return sm[st * 2 * HG_STAGE_WORDS + HG_STAGE_WORDS + r * 36 + w];
    };

    auto load_slab = [&](int j, int st) {
        const int k0 = j << 6;
#pragma unroll
        for (int i = 0; i < 4; i++) {
            int id  = tid + i * 256;
            int row = id >> 3;
            int g8  = (id & 7) * 8;
            cp_async16(smem_u32(&As_w(st, row, g8 >> 1)),
                       A + (size_t)(brow + row) * K + k0 + g8);
            cp_async16(smem_u32(&Bs_w(st, row, g8 >> 1)),
                       B + (size_t)(bcol + row) * K + k0 + g8);
        }
    };

    float acc[2][8][4];
#pragma unroll
    for (int mi = 0; mi < 2; mi++)
#pragma unroll
        for (int nj = 0; nj < 8; nj++)
#pragma unroll
            for (int c = 0; c < 4; c++) acc[mi][nj][c] = 0.f;

    load_slab(0, 0);
    cp_commit();

    for (int j = 0; j < nslab; j++) {
        const int st = j & 1;
        if (j + 1 < nslab) load_slab(j + 1, st ^ 1);
        cp_commit();
        cp_wait1();
        __syncthreads();

        const uint32_t stoff = (uint32_t)st * (2 * HG_STAGE_WORDS * 4);
#pragma unroll
        for (int ks = 0; ks < 32; ks += 8) {
            uint32_t af[2][4];
            uint32_t bf[8][2];
            LDSM_X4(af[0][0], af[0][1], af[0][2], af[0][3],
                    aab + stoff + 4u * ks);
            LDSM_X4(af[1][0], af[1][1], af[1][2], af[1][3],
                    aab + stoff + 4u * (16 * 36) + 4u * ks);
#pragma unroll
            for (int njp = 0; njp < 4; njp++)
                LDSM_X4(bf[2 * njp][0], bf[2 * njp][1],
                        bf[2 * njp + 1][0], bf[2 * njp + 1][1],
                        bbb + stoff + (uint32_t)njp * (16 * 36 * 4) + 4u * ks);
#pragma unroll
            for (int mi = 0; mi < 2; mi++)
#pragma unroll
                for (int nj = 0; nj < 8; nj++)
                    MMA_F16(acc[mi][nj][0], acc[mi][nj][1],
                            acc[mi][nj][2], acc[mi][nj][3],
                            af[mi][0], af[mi][1], af[mi][2], af[mi][3],
                            bf[nj][0], bf[nj][1]);
        }
        __syncthreads();
    }

#pragma unroll
    for (int mi = 0; mi < 2; mi++) {
        int row0 = brow + warpM + mi * 16 + g;
#pragma unroll
        for (int nj = 0; nj < 8; nj++) {
            int col = bcol + warpN + nj * 8 + tig * 2;
            if (HalfOut) {
                __half* Ch = (__half*)C;
                *(uint32_t*)(Ch + (size_t)row0 * N + col) =
                    pack_f16x2(acc[mi][nj][0], acc[mi][nj][1]);
                *(uint32_t*)(Ch + (size_t)(row0 + 8) * N + col) =
                    pack_f16x2(acc[mi][nj][2], acc[mi][nj][3]);
            } else {
                float* Cf = (float*)C;
                float2 lo, hi;
                lo.x = acc[mi][nj][0]; lo.y = acc[mi][nj][1];
                hi.x = acc[mi][nj][2]; hi.y = acc[mi][nj][3];
                *(float2*)(Cf + (size_t)row0 * N + col)       = lo;
                *(float2*)(Cf + (size_t)(row0 + 8) * N + col) = hi;
            }
        }
    }
}

__global__ __launch_bounds__(256, 2) void hgemm_f32(
    const __half* __restrict__ A, const __half* __restrict__ B,
    float* __restrict__ C, int M, int N, int K)
{
    hgemm_body<false>(A, B, C, M, N, K);
}

__global__ __launch_bounds__(256, 2) void hgemm_f16(
    const __half* __restrict__ A, const __half* __restrict__ B,
    __half* __restrict__ C, int M, int N, int K)
{
    hgemm_body<true>(A, B, C, M, N, K);
}

// ---------------------------------------------------------------------------
// Warp-per-head RMSNorm + RoPE, in place on fp16 fused QKV buffer.
// Vectorized weight/table loads (the 8-elem lane chunk never crosses the
// 128-entry frequency boundary).
// ---------------------------------------------------------------------------
__global__ __launch_bounds__(384) void rmsnorm_rope_kernel(
    __half* __restrict__ qkv,
    const float* __restrict__ qw, const float* __restrict__ kw,
    const float* __restrict__ cs, const float* __restrict__ sn_t)
{
    const int t    = blockIdx.x;
    const int w    = threadIdx.x >> 5;     // head index 0..11
    const int lane = threadIdx.x & 31;
    const int d0   = lane * 8;

    __half* row;
    const float* wgt;
    if (w < NH) { row = qkv + (size_t)t * QKVS + w * HD;               wgt = qw; }
    else        { row = qkv + (size_t)t * QKVS + 2048 + (w - NH) * HD; wgt = kw; }

    uint4 wv = *(const uint4*)(row + d0);
    const uint32_t* wr = (const uint32_t*)&wv;
    float e[8];
#pragma unroll
    for (int j = 0; j < 4; j++) {
        __half2 h = *(const __half2*)&wr[j];
        float2 f = __half22float2(h);
        e[2 * j]     = f.x;
        e[2 * j + 1] = f.y;
    }

    float ss = 0.f;
#pragma unroll
    for (int j = 0; j < 8; j++) ss += e[j] * e[j];
#pragma unroll
    for (int o = 16; o; o >>= 1) ss += __shfl_xor_sync(0xffffffffu, ss, o);
    float scale = rsqrtf(ss * (1.0f / HD) + 1e-6f);

    const int fb = d0 & 127;
    float4 w4[2], c4[2], s4[2];
    w4[0] = *(const float4*)(wgt + d0);         w4[1] = *(const float4*)(wgt + d0 + 4);
    c4[0] = *(const float4*)(cs  + t * 128 + fb); c4[1] = *(const float4*)(cs  + t * 128 + fb + 4);
    s4[0] = *(const float4*)(sn_t + t * 128 + fb); s4[1] = *(const float4*)(sn_t + t * 128 + fb + 4);
    const float* wf = (const float*)w4;
    const float* cf = (const float*)c4;
    const float* sf = (const float*)s4;

    uint4 ov;
    uint32_t* orp = (uint32_t*)&ov;
#pragma unroll
    for (int j = 0; j < 4; j++) {
        float n0 = e[2 * j]     * scale * wf[2 * j];
        float n1 = e[2 * j + 1] * scale * wf[2 * j + 1];
        float r0 = n0 * cf[2 * j]     - n1 * sf[2 * j];
        float r1 = n1 * cf[2 * j + 1] + n0 * sf[2 * j + 1];
        orp[j] = pack_f16x2(r0, r1);
    }
    *(uint4*)(row + d0) = ov;
}

// ---------------------------------------------------------------------------
// Flash attention, fp16 data path, FIXED-MAX softmax (M=8): no online max/
// rescale machinery; row sums accumulate in registers; 3 syncs per tile.
// 2 CTAs/SM, longest-first qb order.
// ---------------------------------------------------------------------------
#define QK_PW 132
#define VT_PW 264
#define P_PW  36
#define ATTN_SMEM_WORDS (2*64*QK_PW + 32*VT_PW + 64*P_PW + 128)
#define ATTN_SMEM_BYTES (ATTN_SMEM_WORDS * 4)

__global__ __launch_bounds__(256, 2) void attn_f16(
    const __half* __restrict__ qkv, __half* __restrict__ yh)
{
    extern __shared__ uint32_t smw[];
    uint32_t* Qs = smw;                       // [64][132]
    uint32_t* Ks = Qs + 64 * QK_PW;           // [64][132]
    uint32_t* Vt = Ks + 64 * QK_PW;           // [32][264]
    uint32_t* Ps = Vt + 32 * VT_PW;           // [64][36]
    float* l2 = (float*)(Ps + 64 * P_PW);     // [64][2] final row sums

    const int tid  = threadIdx.x;
    const int qb   = gridDim.x - 1 - blockIdx.x;   // longest-first scheduling
    const int h    = blockIdx.y;
    const int kvi  = h >> 1;
    const int warp = tid >> 5;
    const int lane = tid & 31;
    const int g    = lane >> 2;
    const int tig  = lane & 3;
    const int wn   = warp & 1;
    const int r0   = (warp >> 1) * 16 + g;

    const uint32_t q_lb = smem_u32(Qs) +
        4u * (((warp >> 1) * 16 + (lane & 15)) * QK_PW + ((lane >> 4) << 2));
    const uint32_t k_lb = smem_u32(Ks) +
        4u * ((wn * 32 + (lane & 7) + ((lane >> 4) << 3)) * QK_PW
              + (((lane >> 3) & 1) << 2));
    const uint32_t p_lb = smem_u32(Ps) +
        4u * (((warp >> 1) * 16 + (lane & 15)) * P_PW + ((lane >> 4) << 2));

    // Q tile: raw copy from fused buffer
    for (int idx = tid; idx < 64 * 32; idx += 256) {
        int r = idx >> 5, c = (idx & 31);
        uint4 o = *(const uint4*)(qkv + (size_t)(qb * 64 + r) * QKVS + h * HD + c * 8);
        *(uint4*)&Qs[r * QK_PW + c * 4] = o;
    }

    float acc[16][4];
#pragma unroll
    for (int nj = 0; nj < 16; nj++)
#pragma unroll
        for (int c = 0; c < 4; c++) acc[nj][c] = 0.f;

    float rsum0 = 0.f, rsum1 = 0.f;   // unnormalized row sums (fixed max)

    int s0 = qb * 64 - (WIN - 1);
    if (s0 < 0) s0 = 0;
    const int kt0 = s0 >> 6;
    const int qi0 = qb * 64 + r0;
    const int qi1 = qi0 + 8;

    for (int kt = kt0; kt <= qb; kt++) {
        const bool edge = (kt == qb) || (kt == kt0);
        __syncthreads();   // previous tile's QK/PV smem reads done

        // K tile: raw copy
        for (int idx = tid; idx < 64 * 32; idx += 256) {
            int r = idx >> 5, c = (idx & 31);
            uint4 o = *(const uint4*)(qkv + (size_t)(kt * 64 + r) * QKVS + 2048 + kvi * HD + c * 8);
            *(uint4*)&Ks[r * QK_PW + c * 4] = o;
        }
        // V tile: row-pair interleave via prmt
        for (int idx = tid; idx < 32 * 32; idx += 256) {
            int kp = idx >> 5, dg = (idx & 31) * 8;
            const __half* v0p = qkv + (size_t)(kt * 64 + 2 * kp) * QKVS + 3072 + kvi * HD + dg;
            uint4 A = *(const uint4*)v0p;
            uint4 B = *(const uint4*)(v0p + QKVS);
            uint32_t* dst = &Vt[kp * VT_PW + dg];
            dst[0] = __byte_perm(A.x, B.x, 0x5410);
            dst[1] = __byte_perm(A.x, B.x, 0x7632);
            dst[2] = __byte_perm(A.y, B.y, 0x5410);
            dst[3] = __byte_perm(A.y, B.y, 0x7632);
            dst[4] = __byte_perm(A.z, B.z, 0x5410);
            dst[5] = __byte_perm(A.z, B.z, 0x7632);
            dst[6] = __byte_perm(A.w, B.w, 0x5410);
            dst[7] = __byte_perm(A.w, B.w, 0x7632);
        }
        __syncthreads();   // tiles resident

        // ---- S = Q @ K^T ----
        float sfr[4][4];
#pragma unroll
        for (int nj = 0; nj < 4; nj++)
#pragma unroll
            for (int c = 0; c < 4; c++) sfr[nj][c] = 0.f;
#pragma unroll
        for (int ks = 0; ks < 128; ks += 8) {
            uint32_t a0, a1, a2, a3;
            LDSM_X4(a0, a1, a2, a3, q_lb + 4u * ks);
#pragma unroll
            for (int njp = 0; njp < 2; njp++) {
                uint32_t b00, b01, b10, b11;
                LDSM_X4(b00, b01, b10, b11,
                        k_lb + (uint32_t)njp * (16 * QK_PW * 4) + 4u * ks);
                MMA_F16(sfr[2*njp][0], sfr[2*njp][1], sfr[2*njp][2], sfr[2*njp][3],
                        a0, a1, a2, a3, b00, b01);
                MMA_F16(sfr[2*njp+1][0], sfr[2*njp+1][1], sfr[2*njp+1][2], sfr[2*njp+1][3],
                        a0, a1, a2, a3, b10, b11);
            }
        }

        // ---- fixed-max softmax: p = exp(s/16 - 8); masked -> exp(-inf) = 0 ----
#pragma unroll
        for (int nj = 0; nj < 4; nj++) {
            float p00, p01, p10, p11;
            if (edge) {
                int colb = kt * 64 + wn * 32 + nj * 8 + 2 * tig;
                float v00 = sfr[nj][0] * 0.0625f;
                float v01 = sfr[nj][1] * 0.0625f;
                float v10 = sfr[nj][2] * 0.0625f;
                float v11 = sfr[nj][3] * 0.0625f;
                v00 = (colb     <= qi0 && colb     > qi0 - WIN) ? v00 : -INFINITY;
                v01 = (colb + 1 <= qi0 && colb + 1 > qi0 - WIN) ? v01 : -INFINITY;
                v10 = (colb     <= qi1 && colb     > qi1 - WIN) ? v10 : -INFINITY;
                v11 = (colb + 1 <= qi1 && colb + 1 > qi1 - WIN) ? v11 : -INFINITY;
                p00 = __expf(v00 - SMAX);
                p01 = __expf(v01 - SMAX);
                p10 = __expf(v10 - SMAX);
                p11 = __expf(v11 - SMAX);
            } else {
                p00 = __expf(fmaf(sfr[nj][0], 0.0625f, -SMAX));
                p01 = __expf(fmaf(sfr[nj][1], 0.0625f, -SMAX));
                p10 = __expf(fmaf(sfr[nj][2], 0.0625f, -SMAX));
                p11 = __expf(fmaf(sfr[nj][3], 0.0625f, -SMAX));
            }
            rsum0 += p00 + p01;
            rsum1 += p10 + p11;
            int wd = wn * 16 + nj * 4 + tig;
            Ps[r0 * P_PW + wd]       = pack_f16x2(p00, p01);
            Ps[(r0 + 8) * P_PW + wd] = pack_f16x2(p10, p11);
        }
        __syncthreads();   // P ready for cross-warp ldmatrix

        // ---- O += P @ V (no rescale needed) ----
#pragma unroll
        for (int ks = 0; ks < 32; ks += 8) {
            uint32_t a0, a1, a2, a3;
            LDSM_X4(a0, a1, a2, a3, p_lb + 4u * ks);
#pragma unroll
            for (int nj = 0; nj < 16; nj++) {
                int c = wn * 128 + nj * 8 + g;
                uint32_t b0 = Vt[(ks + tig) * VT_PW + c];
                uint32_t b1 = Vt[(ks + tig + 4) * VT_PW + c];
                MMA_F16(acc[nj][0], acc[nj][1], acc[nj][2], acc[nj][3],
                        a0, a1, a2, a3, b0, b1);
            }
        }
    }

    // Final row-sum reduction: shfl over tig group, combine the two n-warps.
#pragma unroll
    for (int o = 1; o <= 2; o <<= 1) {
        rsum0 += __shfl_xor_sync(0xffffffffu, rsum0, o);
        rsum1 += __shfl_xor_sync(0xffffffffu, rsum1, o);
    }
    if (tig == 0) {
        l2[r0 * 2 + wn]       = rsum0;
        l2[(r0 + 8) * 2 + wn] = rsum1;
    }
    __syncthreads();
    float inv0 = 1.f / (l2[r0 * 2]       + l2[r0 * 2 + 1]);
    float inv1 = 1.f / (l2[(r0 + 8) * 2] + l2[(r0 + 8) * 2 + 1]);

    __half* yr0 = yh + (size_t)(qb * 64 + r0) * DM + h * HD;
    __half* yr1 = yh + (size_t)(qb * 64 + r0 + 8) * DM + h * HD;
#pragma unroll
    for (int nj = 0; nj < 16; nj++) {
        int col = wn * 128 + nj * 8 + 2 * tig;
        *(uint32_t*)(yr0 + col) = pack_f16x2(acc[nj][0] * inv0, acc[nj][1] * inv0);
        *(uint32_t*)(yr1 + col) = pack_f16x2(acc[nj][2] * inv1, acc[nj][3] * inv1);
    }
}

// ---------------------------------------------------------------------------
extern "C" void kernel_launch(void* const* d_in, const int* in_sizes, int n_in,
                              void* d_out, int out_size)
{
    const float* x  = (const float*)d_in[0];
    const int*   pos= (const int*)  d_in[1];
    const float* Wq = (const float*)d_in[2];
    const float* Wk = (const float*)d_in[3];
    const float* Wv = (const float*)d_in[4];
    const float* Wo = (const float*)d_in[5];
    const float* qw = (const float*)d_in[6];
    const float* kw = (const float*)d_in[7];
    float* out = (float*)d_out;

    float  *cs_p, *sn_p;
    __half *qkvh_p, *xh_p, *wqkvh_p, *woh_p, *yh_p;
    cudaGetSymbolAddress((void**)&qkvh_p,  g_qkvh);
    cudaGetSymbolAddress((void**)&cs_p,    g_cs);
    cudaGetSymbolAddress((void**)&sn_p,    g_sn);
    cudaGetSymbolAddress((void**)&xh_p,    g_xh);
    cudaGetSymbolAddress((void**)&wqkvh_p, g_wqkvh);
    cudaGetSymbolAddress((void**)&woh_p,   g_woh);
    cudaGetSymbolAddress((void**)&yh_p,    g_yh);

    // One fused fp32->fp16 convert (x + all weights) + rope table
    convert_all_kernel<<<2048, 256>>>(x, Wq, Wk, Wv, Wo, xh_p, wqkvh_p, woh_p);
    rope_table_kernel<<<T_SEQ, 128>>>(pos, cs_p, sn_p);

    cudaFuncSetAttribute(hgemm_f32, cudaFuncAttributeMaxDynamicSharedMemorySize,
                         HG_SMEM_BYTES);
    cudaFuncSetAttribute(hgemm_f16, cudaFuncAttributeMaxDynamicSharedMemorySize,
                         HG_SMEM_BYTES);

    // Fused QKV projection: one launch, fp16 out
    hgemm_f16<<<dim3(QKVS / 128, T_SEQ / 128), 256, HG_SMEM_BYTES>>>(
        xh_p, wqkvh_p, qkvh_p, T_SEQ, QKVS, DM);

    // RMSNorm + RoPE: warp-per-head, in place on fp16 QKV
    rmsnorm_rope_kernel<<<T_SEQ, 384>>>(qkvh_p, qw, kw, cs_p, sn_p);

    // Flash attention (fixed-max softmax, 2 CTAs/SM, longest-first)
    cudaFuncSetAttribute(attn_f16, cudaFuncAttributeMaxDynamicSharedMemorySize,
                         ATTN_SMEM_BYTES);
    attn_f16<<<dim3(T_SEQ / 64, NH), 256, ATTN_SMEM_BYTES>>>(qkvh_p, yh_p);

    // Output projection (fp32 out -> d_out)
    hgemm_f32<<<dim3(DM / 128, T_SEQ / 128), 256, HG_SMEM_BYTES>>>(
        yh_p, woh_p, out, T_SEQ, DM, DM);
}

// round 15
// speedup vs baseline: 6.4394x; 1.0304x over previous
#include <cuda_runtime.h>
#include <cuda_bf16.h>
#include <cuda_fp16.h>
#include <math.h>
#include <stdint.h>

#define T_SEQ 4096
#define DM    2048
#define NH    8
#define NKV   4
#define HD    256
#define WIN   1024
#define QKVS  4096     // fused row: Q[0,2048) | K[2048,3072) | V[3072,4096)
#define SMAX  8.0f     // fixed softmax max: |s| <= 16 provable, exp(16-8) < fp16 max

// Scratch (static __device__ arrays — allocation-free per harness rules)
__device__ __half g_qkvh[T_SEQ * QKVS];       // 32 MB fused QKV (fp16)
__device__ __half g_xh[T_SEQ * DM];           // 16 MB
__device__ __half g_wqkvh[QKVS * DM];         // 16 MB [Wq; Wk; Wv]
__device__ __half g_woh[DM * DM];             // 8 MB
__device__ __half g_yh[T_SEQ * DM];           // 16 MB (attention out, fp16)
__device__ float  g_cs[T_SEQ * 128];          // rope cos table
__device__ float  g_sn[T_SEQ * 128];          // rope sin table

__device__ __forceinline__ uint32_t pack_f16x2(float lo, float hi) {
    __half2 h = __floats2half2_rn(lo, hi);    // .x = lo (low 16 bits)
    return *reinterpret_cast<uint32_t*>(&h);
}

__device__ __forceinline__ uint32_t smem_u32(const void* p) {
    uint32_t a;
    asm("{ .reg .u64 t; cvta.to.shared.u64 t, %1; cvt.u32.u64 %0, t; }"
        : "=r"(a) : "l"(p));
    return a;
}
__device__ __forceinline__ void cp_async16(uint32_t dst, const void* src) {
    asm volatile("cp.async.cg.shared.global [%0], [%1], 16;" :: "r"(dst), "l"(src));
}
__device__ __forceinline__ void cp_commit() {
    asm volatile("cp.async.commit_group;" ::: "memory");
}
__device__ __forceinline__ void cp_wait1() {
    asm volatile("cp.async.wait_group 1;" ::: "memory");
}

#define MMA_F16(d0,d1,d2,d3,a0,a1,a2,a3,b0,b1)                               \
    asm volatile(                                                            \
        "mma.sync.aligned.m16n8k16.row.col.f32.f16.f16.f32 "                 \
        "{%0,%1,%2,%3}, {%4,%5,%6,%7}, {%8,%9}, {%0,%1,%2,%3};"              \
        : "+f"(d0), "+f"(d1), "+f"(d2), "+f"(d3)                             \
        : "r"(a0), "r"(a1), "r"(a2), "r"(a3), "r"(b0), "r"(b1))

#define LDSM_X4(r0,r1,r2,r3,addr)                                            \
    asm volatile("ldmatrix.sync.aligned.m8n8.x4.shared.b16 {%0,%1,%2,%3}, [%4];" \
        : "=r"(r0), "=r"(r1), "=r"(r2), "=r"(r3) : "r"(addr))

// ---------------------------------------------------------------------------
// ONE fused fp32->fp16 conversion pass over x, Wq, Wk, Wv, Wo.
// ---------------------------------------------------------------------------
#define NX   (T_SEQ * DM)
#define NWQ  (DM * DM)
#define NWK  (NKV * HD * DM)
#define NWV  (NKV * HD * DM)
#define NWO  (DM * DM)
#define NTOT (NX + NWQ + NWK + NWV + NWO)

__global__ __launch_bounds__(256) void convert_all_kernel(
    const float* __restrict__ x,  const float* __restrict__ Wq,
    const float* __restrict__ Wk, const float* __restrict__ Wv,
    const float* __restrict__ Wo,
    __half* __restrict__ xh, __half* __restrict__ wqkvh,
    __half* __restrict__ woh)
{
    for (size_t i = ((size_t)blockIdx.x * 256 + threadIdx.x) * 8; i < NTOT;
         i += (size_t)gridDim.x * 256 * 8) {
        const float* src;
        __half* dst;
        size_t o = i;
        if (o < NX)                        { src = x;  dst = xh; }
        else if ((o -= NX)  < NWQ)         { src = Wq; dst = wqkvh; }
        else if ((o -= NWQ) < NWK)         { src = Wk; dst = wqkvh + NWQ; }
        else if ((o -= NWK) < NWV)         { src = Wv; dst = wqkvh + NWQ + NWK; }
        else { o -= NWV;                     src = Wo; dst = woh; }
        float4 v0 = *(const float4*)(src + o);
        float4 v1 = *(const float4*)(src + o + 4);
        uint4 ov;
        ov.x = pack_f16x2(v0.x, v0.y);
        ov.y = pack_f16x2(v0.z, v0.w);
        ov.z = pack_f16x2(v1.x, v1.y);
        ov.w = pack_f16x2(v1.z, v1.w);
        *(uint4*)((char*)dst + o * 2) = ov;
    }
}

// ---------------------------------------------------------------------------
// RoPE table (bit-identical math to the original in-kernel version)
// ---------------------------------------------------------------------------
__global__ __launch_bounds__(128) void rope_table_kernel(
    const int* __restrict__ pos, float* __restrict__ cs, float* __restrict__ sn)
{
    int t = blockIdx.x, f = threadIdx.x;
    float inv_freq = expf(-(float)f * (logf(10000.0f) / 128.0f));
    float ang = (float)pos[t] * inv_freq;
    float sv, cv;
    sincosf(ang, &sv, &cv);
    cs[t * 128 + f] = cv;
    sn[t * 128 + f] = sv;
}

// ---------------------------------------------------------------------------
// FP16 tensor-core GEMM core (fp32 accum). 128x128 tile, BK=64 halves,
// cp.async double buffered, ldmatrix fragments, 8 warps (4m x 2n).
// ---------------------------------------------------------------------------
#define HG_STAGE_WORDS (128 * 36)
#define HG_SMEM_BYTES  (4 * HG_STAGE_WORDS * 4 * 2)   // 73728

template <bool HalfOut>
__device__ __forceinline__ void hgemm_body(
    const __half* __restrict__ A, const __half* __restrict__ B,
    void* __restrict__ C, int M, int N, int K)
{
    extern __shared__ uint32_t sm[];
    const int tid  = threadIdx.x;
    const int brow = blockIdx.y * 128;
    const int bcol = blockIdx.x * 128;
    const int warp = tid >> 5;
    const int lane = tid & 31;
    const int g    = lane >> 2;
    const int tig  = lane & 3;
    const int warpM = (warp >> 1) * 32;
    const int warpN = (warp & 1) * 64;
    const int nslab = K >> 6;

    const uint32_t sa = smem_u32(sm);
    const uint32_t aab = sa + 4u * ((warpM + (lane & 15)) * 36 + ((lane >> 4) << 2));
    const uint32_t bbb = sa + 4u * (HG_STAGE_WORDS
                       + (warpN + (lane & 7) + ((lane >> 4) << 3)) * 36
                       + (((lane >> 3) & 1) << 2));

    auto As_w = [&](int st, int r, int w) -> uint32_t& {
        return sm[st * 2 * HG_STAGE_WORDS + r * 36 + w];
    };
    auto Bs_w = [&](int st, int r, int w) -> uint32_t& {
        return sm[st * 2 * HG_STAGE_WORDS + HG_STAGE_WORDS + r * 36 + w];
    };

    auto load_slab = [&](int j, int st) {
        const int k0 = j << 6;
#pragma unroll
        for (int i = 0; i < 4; i++) {
            int id  = tid + i * 256;
            int row = id >> 3;
            int g8  = (id & 7) * 8;
            cp_async16(smem_u32(&As_w(st, row, g8 >> 1)),
                       A + (size_t)(brow + row) * K + k0 + g8);
            cp_async16(smem_u32(&Bs_w(st, row, g8 >> 1)),
                       B + (size_t)(bcol + row) * K + k0 + g8);
        }
    };

    float acc[2][8][4];
#pragma unroll
    for (int mi = 0; mi < 2; mi++)
#pragma unroll
        for (int nj = 0; nj < 8; nj++)
#pragma unroll
            for (int c = 0; c < 4; c++) acc[mi][nj][c] = 0.f;

    load_slab(0, 0);
    cp_commit();

    for (int j = 0; j < nslab; j++) {
        const int st = j & 1;
        if (j + 1 < nslab) load_slab(j + 1, st ^ 1);
        cp_commit();
        cp_wait1();
        __syncthreads();

        const uint32_t stoff = (uint32_t)st * (2 * HG_STAGE_WORDS * 4);
#pragma unroll
        for (int ks = 0; ks < 32; ks += 8) {
            uint32_t af[2][4];
            uint32_t bf[8][2];
            LDSM_X4(af[0][0], af[0][1], af[0][2], af[0][3],
                    aab + stoff + 4u * ks);
            LDSM_X4(af[1][0], af[1][1], af[1][2], af[1][3],
                    aab + stoff + 4u * (16 * 36) + 4u * ks);
#pragma unroll
            for (int njp = 0; njp < 4; njp++)
                LDSM_X4(bf[2 * njp][0], bf[2 * njp][1],
                        bf[2 * njp + 1][0], bf[2 * njp + 1][1],
                        bbb + stoff + (uint32_t)njp * (16 * 36 * 4) + 4u * ks);
#pragma unroll
            for (int mi = 0; mi < 2; mi++)
#pragma unroll
                for (int nj = 0; nj < 8; nj++)
                    MMA_F16(acc[mi][nj][0], acc[mi][nj][1],
                            acc[mi][nj][2], acc[mi][nj][3],
                            af[mi][0], af[mi][1], af[mi][2], af[mi][3],
                            bf[nj][0], bf[nj][1]);
        }
        __syncthreads();
    }

#pragma unroll
    for (int mi = 0; mi < 2; mi++) {
        int row0 = brow + warpM + mi * 16 + g;
#pragma unroll
        for (int nj = 0; nj < 8; nj++) {
            int col = bcol + warpN + nj * 8 + tig * 2;
            if (HalfOut) {
                __half* Ch = (__half*)C;
                *(uint32_t*)(Ch + (size_t)row0 * N + col) =
                    pack_f16x2(acc[mi][nj][0], acc[mi][nj][1]);
                *(uint32_t*)(Ch + (size_t)(row0 + 8) * N + col) =
                    pack_f16x2(acc[mi][nj][2], acc[mi][nj][3]);
            } else {
                float* Cf = (float*)C;
                float2 lo, hi;
                lo.x = acc[mi][nj][0]; lo.y = acc[mi][nj][1];
                hi.x = acc[mi][nj][2]; hi.y = acc[mi][nj][3];
                *(float2*)(Cf + (size_t)row0 * N + col)       = lo;
                *(float2*)(Cf + (size_t)(row0 + 8) * N + col) = hi;
            }
        }
    }
}

__global__ __launch_bounds__(256, 2) void hgemm_f32(
    const __half* __restrict__ A, const __half* __restrict__ B,
    float* __restrict__ C, int M, int N, int K)
{
    hgemm_body<false>(A, B, C, M, N, K);
}

__global__ __launch_bounds__(256, 2) void hgemm_f16(
    const __half* __restrict__ A, const __half* __restrict__ B,
    __half* __restrict__ C, int M, int N, int K)
{
    hgemm_body<true>(A, B, C, M, N, K);
}

// ---------------------------------------------------------------------------
// Warp-per-head RMSNorm + RoPE, in place on fp16 fused QKV buffer.
// ---------------------------------------------------------------------------
__global__ __launch_bounds__(384) void rmsnorm_rope_kernel(
    __half* __restrict__ qkv,
    const float* __restrict__ qw, const float* __restrict__ kw,
    const float* __restrict__ cs, const float* __restrict__ sn_t)
{
    const int t    = blockIdx.x;
    const int w    = threadIdx.x >> 5;     // head index 0..11
    const int lane = threadIdx.x & 31;
    const int d0   = lane * 8;

    __half* row;
    const float* wgt;
    if (w < NH) { row = qkv + (size_t)t * QKVS + w * HD;               wgt = qw; }
    else        { row = qkv + (size_t)t * QKVS + 2048 + (w - NH) * HD; wgt = kw; }

    uint4 wv = *(const uint4*)(row + d0);
    const uint32_t* wr = (const uint32_t*)&wv;
    float e[8];
#pragma unroll
    for (int j = 0; j < 4; j++) {
        __half2 h = *(const __half2*)&wr[j];
        float2 f = __half22float2(h);
        e[2 * j]     = f.x;
        e[2 * j + 1] = f.y;
    }

    float ss = 0.f;
#pragma unroll
    for (int j = 0; j < 8; j++) ss += e[j] * e[j];
#pragma unroll
    for (int o = 16; o; o >>= 1) ss += __shfl_xor_sync(0xffffffffu, ss, o);
    float scale = rsqrtf(ss * (1.0f / HD) + 1e-6f);

    const int fb = d0 & 127;
    float4 w4[2], c4[2], s4[2];
    w4[0] = *(const float4*)(wgt + d0);          w4[1] = *(const float4*)(wgt + d0 + 4);
    c4[0] = *(const float4*)(cs  + t * 128 + fb); c4[1] = *(const float4*)(cs  + t * 128 + fb + 4);
    s4[0] = *(const float4*)(sn_t + t * 128 + fb); s4[1] = *(const float4*)(sn_t + t * 128 + fb + 4);
    const float* wf = (const float*)w4;
    const float* cf = (const float*)c4;
    const float* sf = (const float*)s4;

    uint4 ov;
    uint32_t* orp = (uint32_t*)&ov;
#pragma unroll
    for (int j = 0; j < 4; j++) {
        float n0 = e[2 * j]     * scale * wf[2 * j];
        float n1 = e[2 * j + 1] * scale * wf[2 * j + 1];
        float r0 = n0 * cf[2 * j]     - n1 * sf[2 * j];
        float r1 = n1 * cf[2 * j + 1] + n0 * sf[2 * j + 1];
        orp[j] = pack_f16x2(r0, r1);
    }
    *(uint4*)(row + d0) = ov;
}

// ---------------------------------------------------------------------------
// Flash attention, GQA K/V-sharing: one block = 64 queries x 1 KV group
// (= 2 q-heads). 512 threads = 2 warp-groups of 8 warps; each warp-group runs
// the proven 8-warp layout on its own Q/P while SHARING the K/V smem tiles.
// Fixed-max softmax, fp16 data path, 1 CTA/SM (same 16 warps/SM as before).
// ---------------------------------------------------------------------------
#define QK_PW 132
#define VT_PW 264
#define P_PW  36
#define ATTN_SMEM_WORDS (2*64*QK_PW + 64*QK_PW + 32*VT_PW + 2*64*P_PW + 2*128)
#define ATTN_SMEM_BYTES (ATTN_SMEM_WORDS * 4)   // 154112 B

__global__ __launch_bounds__(512, 1) void attn_f16(
    const __half* __restrict__ qkv, __half* __restrict__ yh)
{
    extern __shared__ uint32_t smw[];
    uint32_t* Qs = smw;                       // [2][64][132]
    uint32_t* Ks = Qs + 2 * 64 * QK_PW;       // [64][132]  (shared)
    uint32_t* Vt = Ks + 64 * QK_PW;           // [32][264]  (shared)
    uint32_t* Ps = Vt + 32 * VT_PW;           // [2][64][36]
    float* l2 = (float*)(Ps + 2 * 64 * P_PW); // [2][64][2] final row sums

    const int tid  = threadIdx.x;
    const int qb   = gridDim.x - 1 - blockIdx.x;   // longest-first scheduling
    const int kvi  = blockIdx.y;
    const int warp = tid >> 5;
    const int lane = tid & 31;
    const int g    = lane >> 2;
    const int tig  = lane & 3;
    const int wg   = warp >> 3;            // warp-group = q-head within pair
    const int w8   = warp & 7;
    const int wn   = w8 & 1;
    const int r0   = (w8 >> 1) * 16 + g;
    const int h    = kvi * 2 + wg;

    const uint32_t q_lb = smem_u32(Qs + wg * 64 * QK_PW) +
        4u * (((w8 >> 1) * 16 + (lane & 15)) * QK_PW + ((lane >> 4) << 2));
    const uint32_t k_lb = smem_u32(Ks) +
        4u * ((wn * 32 + (lane & 7) + ((lane >> 4) << 3)) * QK_PW
              + (((lane >> 3) & 1) << 2));
    const uint32_t p_lb = smem_u32(Ps + wg * 64 * P_PW) +
        4u * (((w8 >> 1) * 16 + (lane & 15)) * P_PW + ((lane >> 4) << 2));

    // Q tiles for both heads: raw copy (2 x 64 rows x 32 uint4 over 512 thr)
#pragma unroll
    for (int it = 0; it < 8; it++) {
        int idx = tid + it * 512;             // 0..4095
        int wq = idx >> 11;                   // head-in-pair
        int r  = (idx >> 5) & 63, c = idx & 31;
        uint4 o = *(const uint4*)(qkv + (size_t)(qb * 64 + r) * QKVS
                                  + (kvi * 2 + wq) * HD + c * 8);
        *(uint4*)&Qs[wq * 64 * QK_PW + r * QK_PW + c * 4] = o;
    }

    float acc[16][4];
#pragma unroll
    for (int nj = 0; nj < 16; nj++)
#pragma unroll
        for (int c = 0; c < 4; c++) acc[nj][c] = 0.f;

    float rsum0 = 0.f, rsum1 = 0.f;

    int s0 = qb * 64 - (WIN - 1);
    if (s0 < 0) s0 = 0;
    const int kt0 = s0 >> 6;
    const int qi0 = qb * 64 + r0;
    const int qi1 = qi0 + 8;

    for (int kt = kt0; kt <= qb; kt++) {
        const bool edge = (kt == qb) || (kt == kt0);
        __syncthreads();   // previous tile's smem reads done

        // K tile: raw copy (2048 uint4 over 512 threads)
#pragma unroll
        for (int it = 0; it < 4; it++) {
            int idx = tid + it * 512;
            int r = idx >> 5, c = idx & 31;
            uint4 o = *(const uint4*)(qkv + (size_t)(kt * 64 + r) * QKVS
                                      + 2048 + kvi * HD + c * 8);
            *(uint4*)&Ks[r * QK_PW + c * 4] = o;
        }
        // V tile: row-pair interleave via prmt (1024 chunks over 512 threads)
#pragma unroll
        for (int it = 0; it < 2; it++) {
            int idx = tid + it * 512;
            int kp = idx >> 5, dg = (idx & 31) * 8;
            const __half* v0p = qkv + (size_t)(kt * 64 + 2 * kp) * QKVS
                                + 3072 + kvi * HD + dg;
            uint4 A = *(const uint4*)v0p;
            uint4 B = *(const uint4*)(v0p + QKVS);
            uint32_t* dst = &Vt[kp * VT_PW + dg];
            dst[0] = __byte_perm(A.x, B.x, 0x5410);
            dst[1] = __byte_perm(A.x, B.x, 0x7632);
            dst[2] = __byte_perm(A.y, B.y, 0x5410);
            dst[3] = __byte_perm(A.y, B.y, 0x7632);
            dst[4] = __byte_perm(A.z, B.z, 0x5410);
            dst[5] = __byte_perm(A.z, B.z, 0x7632);
            dst[6] = __byte_perm(A.w, B.w, 0x5410);
            dst[7] = __byte_perm(A.w, B.w, 0x7632);
        }
        __syncthreads();   // tiles resident

        // ---- S = Q @ K^T (per warp-group on its own Q) ----
        float sfr[4][4];
#pragma unroll
        for (int nj = 0; nj < 4; nj++)
#pragma unroll
            for (int c = 0; c < 4; c++) sfr[nj][c] = 0.f;
#pragma unroll
        for (int ks = 0; ks < 128; ks += 8) {
            uint32_t a0, a1, a2, a3;
            LDSM_X4(a0, a1, a2, a3, q_lb + 4u * ks);
#pragma unroll
            for (int njp = 0; njp < 2; njp++) {
                uint32_t b00, b01, b10, b11;
                LDSM_X4(b00, b01, b10, b11,
                        k_lb + (uint32_t)njp * (16 * QK_PW * 4) + 4u * ks);
                MMA_F16(sfr[2*njp][0], sfr[2*njp][1], sfr[2*njp][2], sfr[2*njp][3],
                        a0, a1, a2, a3, b00, b01);
                MMA_F16(sfr[2*njp+1][0], sfr[2*njp+1][1], sfr[2*njp+1][2], sfr[2*njp+1][3],
                        a0, a1, a2, a3, b10, b11);
            }
        }

        // ---- fixed-max softmax: p = exp(s/16 - 8); masked -> 0 ----
        uint32_t* Pw = Ps + wg * 64 * P_PW;
#pragma unroll
        for (int nj = 0; nj < 4; nj++) {
            float p00, p01, p10, p11;
            if (edge) {
                int colb = kt * 64 + wn * 32 + nj * 8 + 2 * tig;
                float v00 = sfr[nj][0] * 0.0625f;
                float v01 = sfr[nj][1] * 0.0625f;
                float v10 = sfr[nj][2] * 0.0625f;
                float v11 = sfr[nj][3] * 0.0625f;
                v00 = (colb     <= qi0 && colb     > qi0 - WIN) ? v00 : -INFINITY;
                v01 = (colb + 1 <= qi0 && colb + 1 > qi0 - WIN) ? v01 : -INFINITY;
                v10 = (colb     <= qi1 && colb     > qi1 - WIN) ? v10 : -INFINITY;
                v11 = (colb + 1 <= qi1 && colb + 1 > qi1 - WIN) ? v11 : -INFINITY;
                p00 = __expf(v00 - SMAX);
                p01 = __expf(v01 - SMAX);
                p10 = __expf(v10 - SMAX);
                p11 = __expf(v11 - SMAX);
            } else {
                p00 = __expf(fmaf(sfr[nj][0], 0.0625f, -SMAX));
                p01 = __expf(fmaf(sfr[nj][1], 0.0625f, -SMAX));
                p10 = __expf(fmaf(sfr[nj][2], 0.0625f, -SMAX));
                p11 = __expf(fmaf(sfr[nj][3], 0.0625f, -SMAX));
            }
            rsum0 += p00 + p01;
            rsum1 += p10 + p11;
            int wd = wn * 16 + nj * 4 + tig;
            Pw[r0 * P_PW + wd]       = pack_f16x2(p00, p01);
            Pw[(r0 + 8) * P_PW + wd] = pack_f16x2(p10, p11);
        }
        __syncthreads();   // P ready for cross-warp ldmatrix

        // ---- O += P @ V ----
#pragma unroll
        for (int ks = 0; ks < 32; ks += 8) {
            uint32_t a0, a1, a2, a3;
            LDSM_X4(a0, a1, a2, a3, p_lb + 4u * ks);
#pragma unroll
            for (int nj = 0; nj < 16; nj++) {
                int c = wn * 128 + nj * 8 + g;
                uint32_t b0 = Vt[(ks + tig) * VT_PW + c];
                uint32_t b1 = Vt[(ks + tig + 4) * VT_PW + c];
                MMA_F16(acc[nj][0], acc[nj][1], acc[nj][2], acc[nj][3],
                        a0, a1, a2, a3, b0, b1);
            }
        }
    }

    // Final row-sum reduction per warp-group.
#pragma unroll
    for (int o = 1; o <= 2; o <<= 1) {
        rsum0 += __shfl_xor_sync(0xffffffffu, rsum0, o);
        rsum1 += __shfl_xor_sync(0xffffffffu, rsum1, o);
    }
    float* l2w = l2 + wg * 128;
    if (tig == 0) {
        l2w[r0 * 2 + wn]       = rsum0;
        l2w[(r0 + 8) * 2 + wn] = rsum1;
    }
    __syncthreads();
    float inv0 = 1.f / (l2w[r0 * 2]       + l2w[r0 * 2 + 1]);
    float inv1 = 1.f / (l2w[(r0 + 8) * 2] + l2w[(r0 + 8) * 2 + 1]);

    __half* yr0 = yh + (size_t)(qb * 64 + r0) * DM + h * HD;
    __half* yr1 = yh + (size_t)(qb * 64 + r0 + 8) * DM + h * HD;
#pragma unroll
    for (int nj = 0; nj < 16; nj++) {
        int col = wn * 128 + nj * 8 + 2 * tig;
        *(uint32_t*)(yr0 + col) = pack_f16x2(acc[nj][0] * inv0, acc[nj][1] * inv0);
        *(uint32_t*)(yr1 + col) = pack_f16x2(acc[nj][2] * inv1, acc[nj][3] * inv1);
    }
}

// ---------------------------------------------------------------------------
extern "C" void kernel_launch(void* const* d_in, const int* in_sizes, int n_in,
                              void* d_out, int out_size)
{
    const float* x  = (const float*)d_in[0];
    const int*   pos= (const int*)  d_in[1];
    const float* Wq = (const float*)d_in[2];
    const float* Wk = (const float*)d_in[3];
    const float* Wv = (const float*)d_in[4];
    const float* Wo = (const float*)d_in[5];
    const float* qw = (const float*)d_in[6];
    const float* kw = (const float*)d_in[7];
    float* out = (float*)d_out;

    float  *cs_p, *sn_p;
    __half *qkvh_p, *xh_p, *wqkvh_p, *woh_p, *yh_p;
    cudaGetSymbolAddress((void**)&qkvh_p,  g_qkvh);
    cudaGetSymbolAddress((void**)&cs_p,    g_cs);
    cudaGetSymbolAddress((void**)&sn_p,    g_sn);
    cudaGetSymbolAddress((void**)&xh_p,    g_xh);
    cudaGetSymbolAddress((void**)&wqkvh_p, g_wqkvh);
    cudaGetSymbolAddress((void**)&woh_p,   g_woh);
    cudaGetSymbolAddress((void**)&yh_p,    g_yh);

    // One fused fp32->fp16 convert (x + all weights) + rope table
    convert_all_kernel<<<2048, 256>>>(x, Wq, Wk, Wv, Wo, xh_p, wqkvh_p, woh_p);
    rope_table_kernel<<<T_SEQ, 128>>>(pos, cs_p, sn_p);

    cudaFuncSetAttribute(hgemm_f32, cudaFuncAttributeMaxDynamicSharedMemorySize,
                         HG_SMEM_BYTES);
    cudaFuncSetAttribute(hgemm_f16, cudaFuncAttributeMaxDynamicSharedMemorySize,
                         HG_SMEM_BYTES);

    // Fused QKV projection: one launch, fp16 out
    hgemm_f16<<<dim3(QKVS / 128, T_SEQ / 128), 256, HG_SMEM_BYTES>>>(
        xh_p, wqkvh_p, qkvh_p, T_SEQ, QKVS, DM);

    // RMSNorm + RoPE: warp-per-head, in place on fp16 QKV
    rmsnorm_rope_kernel<<<T_SEQ, 384>>>(qkvh_p, qw, kw, cs_p, sn_p);

    // Flash attention (GQA K/V sharing: 64 queries x 1 KV group per block)
    cudaFuncSetAttribute(attn_f16, cudaFuncAttributeMaxDynamicSharedMemorySize,
                         ATTN_SMEM_BYTES);
    attn_f16<<<dim3(T_SEQ / 64, NKV), 512, ATTN_SMEM_BYTES>>>(qkvh_p, yh_p);

    // Output projection (fp32 out -> d_out)
    hgemm_f32<<<dim3(DM / 128, T_SEQ / 128), 256, HG_SMEM_BYTES>>>(
        yh_p, woh_p, out, T_SEQ, DM, DM);
}